// round 3
// baseline (speedup 1.0000x reference)
#include <cuda_runtime.h>

// Problem constants (fixed shapes)
#define S_LEN  4096
#define NHEAD  16
#define NBATCH 2
#define DHEAD  64
#define NPROJ  8
#define BLK    128
#define NBLK   32      // S_LEN / BLK
#define NSAMP  128
#define LOG2E  1.4426950408889634f

// ---------------- scratch (no cudaMalloc allowed) ----------------
__device__ __align__(16) unsigned char g_qh[NBATCH*NHEAD*S_LEN];
__device__ __align__(16) unsigned char g_kh[NBATCH*NHEAD*S_LEN];
__device__ int g_qidx[NBATCH*NHEAD*S_LEN];
__device__ int g_kidx[NBATCH*NHEAD*S_LEN];

// ---------------------------------------------------------------------------
// Kernel 1: LSH hash. One CTA per (b,s). Loads the q and k rows for all 16
// heads (contiguous 8KB), projects onto 8 directions, emits Gray-coded
// bucket id = code ^ (code>>1)  (== PERM[code] of the reference).
// ---------------------------------------------------------------------------
__global__ void hyper_hash_kernel(const float* __restrict__ qkv,
                                  const float* __restrict__ proj)
{
    __shared__ float sp[DHEAD*NPROJ];        // 512 floats: proj_dir [d][r]
    __shared__ float row[2*NHEAD*DHEAD];     // q rows then k rows, all heads
    __shared__ unsigned int sbits[128];

    int t  = threadIdx.x;                    // 0..127
    int bs = blockIdx.x;                     // b*4096 + s
    int b  = bs >> 12;
    int s  = bs & (S_LEN - 1);

    ((float4*)sp)[t] = ((const float4*)proj)[t];           // 128 float4 = 512 f
    const float4* src = (const float4*)(qkv + (size_t)bs * 3072);  // q(1024)+k(1024)
    float4* dst = (float4*)row;
    dst[t]       = src[t];
    dst[t + 128] = src[t + 128];
    dst[t + 256] = src[t + 256];
    dst[t + 384] = src[t + 384];
    __syncthreads();

    int h = t >> 3, r = t & 7;               // thread = (head, projection)
    const float* xq = row + h * DHEAD;
    const float* xk = row + NHEAD * DHEAD + h * DHEAD;
    float dq = 0.f, dk = 0.f;
#pragma unroll
    for (int d = 0; d < DHEAD; d++) {
        float p = sp[d * NPROJ + r];
        dq += xq[d] * p;
        dk += xk[d] * p;
    }
    unsigned bq = (dq > 0.f) ? (1u << r) : 0u;
    unsigned bk = (dk > 0.f) ? (1u << r) : 0u;
    sbits[t] = bq | (bk << 8);
    __syncthreads();

    if (r == 0) {
        unsigned c = 0;
#pragma unroll
        for (int i = 0; i < 8; i++) c |= sbits[t + i];
        unsigned cq = c & 0xFFu, ck = (c >> 8) & 0xFFu;
        cq ^= cq >> 1;                        // Gray permutation
        ck ^= ck >> 1;
        size_t o = (size_t)(b * NHEAD + h) * S_LEN + s;
        g_qh[o] = (unsigned char)cq;
        g_kh[o] = (unsigned char)ck;
    }
}

// ---------------------------------------------------------------------------
// Kernel 2: stable counting sort of 4096 8-bit keys per (b,h).
// grid (32, 2): y=0 sorts q hashes -> g_qidx, y=1 sorts k hashes -> g_kidx.
// Thread k owns bucket k; placement scans elements in ascending original
// index => stable, matching jnp.argsort(stable=True).
// ---------------------------------------------------------------------------
__global__ void hyper_sort_kernel()
{
    int bh    = blockIdx.x;                  // 0..31
    int which = blockIdx.y;                  // 0=q, 1=k
    const unsigned int* hw =
        (const unsigned int*)((which ? g_kh : g_qh) + (size_t)bh * S_LEN);
    int* idx = (which ? g_kidx : g_qidx) + (size_t)bh * S_LEN;

    __shared__ unsigned int w[1024];
    __shared__ int scan[256];
    int t = threadIdx.x;                     // 0..255 = bucket id
#pragma unroll
    for (int i = 0; i < 4; i++) w[t + i * 256] = hw[t + i * 256];
    __syncthreads();

    unsigned k4 = t * 0x01010101u;
    int cnt = 0;
#pragma unroll 4
    for (int i = 0; i < 1024; i++) cnt += __popc(__vcmpeq4(w[i], k4));
    cnt >>= 3;                               // 8 bits set per matching byte

    scan[t] = cnt;
    __syncthreads();
    for (int off = 1; off < 256; off <<= 1) {
        int v = (t >= off) ? scan[t - off] : 0;
        __syncthreads();
        scan[t] += v;
        __syncthreads();
    }
    int pos = scan[t] - cnt;                 // exclusive prefix = bucket start

    for (int i = 0; i < 1024; i++) {
        unsigned m = __vcmpeq4(w[i], k4);
        if (m) {
            int base = i * 4;
            if (m & 0x000000FFu) idx[pos++] = base;
            if (m & 0x0000FF00u) idx[pos++] = base + 1;
            if (m & 0x00FF0000u) idx[pos++] = base + 2;
            if (m & 0xFF000000u) idx[pos++] = base + 3;
        }
    }
}

// ---------------------------------------------------------------------------
// Kernel 3: fused block + residual attention, one CTA per (b,h,g).
// Joint online softmax over 256 keys:
//   keys 0..127   = sorted block keys (bias 0)
//   keys 128..255 = sampled keys (bias +log2(32)=5, or -inf when the sample's
//                   sorted block == g, reproducing the reference mask)
// Everything gathered directly from qkv via g_qidx/g_kidx. Output scattered
// back to original query order (inverse permutation == scatter via q_idx).
// ---------------------------------------------------------------------------
__global__ void __launch_bounds__(128)
hyper_attn_kernel(const float* __restrict__ qkv,
                  const int*   __restrict__ sampled,
                  float*       __restrict__ out)
{
    __shared__ float sk[64 * 64];            // 64-key K chunk
    __shared__ float sv[64 * 64];            // 64-key V chunk
    __shared__ float sbias[64];
    __shared__ int   ssrc[64];

    int g = blockIdx.x, h = blockIdx.y, b = blockIdx.z;
    int bh = b * NHEAD + h;
    int t  = threadIdx.x;                    // query row within block

    int qsrc = g_qidx[(size_t)bh * S_LEN + g * BLK + t];
    const float4* qp =
        (const float4*)(qkv + (size_t)(b * S_LEN + qsrc) * 3072 + h * 64);

    float q[64], acc[64];
    const float qs = 0.125f * LOG2E;         // D^-1/2 * log2(e) folded into q
#pragma unroll
    for (int i = 0; i < 16; i++) {
        float4 v = qp[i];
        q[4*i+0] = v.x * qs; q[4*i+1] = v.y * qs;
        q[4*i+2] = v.z * qs; q[4*i+3] = v.w * qs;
    }
#pragma unroll
    for (int d = 0; d < 64; d++) acc[d] = 0.f;
    float mr = -1e30f, lr = 0.f;

    for (int c = 0; c < 4; c++) {            // 4 chunks of 64 keys
        if (t < 64) {
            int pos; float bias;
            if (c < 2) { pos = g * BLK + c * 64 + t; bias = 0.f; }
            else {
                pos  = sampled[bh * NSAMP + (c - 2) * 64 + t];
                bias = ((pos >> 7) == g) ? -1e30f : 5.0f;   // log2(n/m)=5
            }
            ssrc[t]  = g_kidx[(size_t)bh * S_LEN + pos];
            sbias[t] = bias;
        }
        __syncthreads();
        // cooperative gather: 64 rows x 16 float4, 16 consecutive threads/row
#pragma unroll
        for (int i = 0; i < 8; i++) {
            int f = t + i * 128;             // 0..1023
            int j = f >> 4, d4 = f & 15;
            const float4* kb =
                (const float4*)(qkv + (size_t)(b * S_LEN + ssrc[j]) * 3072
                                + 1024 + h * 64);
            ((float4*)sk)[f] = kb[d4];        // K component (c=1)
            ((float4*)sv)[f] = kb[d4 + 256];  // V component (c=2, +1024 floats)
        }
        __syncthreads();

#pragma unroll 1                              // keep body inside I$
        for (int kb8 = 0; kb8 < 8; kb8++) {  // 8 batches of 8 keys
            float sc[8];
            const float4* krb = (const float4*)(sk + kb8 * 8 * 64);
#pragma unroll
            for (int jj = 0; jj < 8; jj++) {
                float s0 = 0.f, s1 = 0.f, s2 = 0.f, s3 = 0.f;
                const float4* kr = krb + jj * 16;
#pragma unroll
                for (int d4 = 0; d4 < 16; d4++) {
                    float4 kk = kr[d4];      // broadcast LDS.128
                    s0 += q[4*d4+0] * kk.x; s1 += q[4*d4+1] * kk.y;
                    s2 += q[4*d4+2] * kk.z; s3 += q[4*d4+3] * kk.w;
                }
                sc[jj] = (s0 + s1) + (s2 + s3) + sbias[kb8 * 8 + jj];
            }
            float cm = sc[0];
#pragma unroll
            for (int jj = 1; jj < 8; jj++) cm = fmaxf(cm, sc[jj]);
            float nm  = fmaxf(mr, cm);
            float fsc = exp2f(mr - nm);
            lr *= fsc;
#pragma unroll
            for (int d = 0; d < 64; d++) acc[d] *= fsc;
            const float4* vrb = (const float4*)(sv + kb8 * 8 * 64);
#pragma unroll
            for (int jj = 0; jj < 8; jj++) {
                float p = exp2f(sc[jj] - nm);
                lr += p;
                const float4* vr = vrb + jj * 16;
#pragma unroll
                for (int d4 = 0; d4 < 16; d4++) {
                    float4 vv = vr[d4];
                    acc[4*d4+0] += p * vv.x; acc[4*d4+1] += p * vv.y;
                    acc[4*d4+2] += p * vv.z; acc[4*d4+3] += p * vv.w;
                }
            }
            mr = nm;
        }
        __syncthreads();
    }

    float inv = 1.0f / lr;
    // scatter back to original order: out[b, qsrc, h, :]
    float4* op = (float4*)(out + ((size_t)(b * S_LEN + qsrc) * NHEAD + h) * 64);
#pragma unroll
    for (int i = 0; i < 16; i++) {
        float4 v;
        v.x = acc[4*i+0] * inv; v.y = acc[4*i+1] * inv;
        v.z = acc[4*i+2] * inv; v.w = acc[4*i+3] * inv;
        op[i] = v;
    }
}

// ---------------------------------------------------------------------------
extern "C" void kernel_launch(void* const* d_in, const int* in_sizes, int n_in,
                              void* d_out, int out_size)
{
    const float* qkv     = (const float*)d_in[0];   // [2,4096,3,16,64] f32
    const float* proj    = (const float*)d_in[1];   // [64,8] f32
    const int*   sampled = (const int*)d_in[2];     // [2,16,128] i32
    float*       out     = (float*)d_out;           // [2,4096,16,64] f32

    hyper_hash_kernel<<<NBATCH * S_LEN, 128>>>(qkv, proj);
    hyper_sort_kernel<<<dim3(NBATCH * NHEAD, 2), 256>>>();
    hyper_attn_kernel<<<dim3(NBLK, NHEAD, NBATCH), 128>>>(qkv, sampled, out);
}

// round 5
// speedup vs baseline: 1.7652x; 1.7652x over previous
#include <cuda_runtime.h>
#include <cuda_bf16.h>

// Problem constants (fixed shapes)
#define S_LEN  4096
#define NHEAD  16
#define NBATCH 2
#define BLK    128
#define NBLK   32      // S_LEN / BLK
#define NSAMP  128
#define LOG2E  1.4426950408889634f
#define PITCH  72      // bf16 elements per smem tile row (conflict-free padding)

// ---------------- scratch (no cudaMalloc allowed) ----------------
__device__ __align__(16) unsigned char g_qh[NBATCH*NHEAD*S_LEN];
__device__ __align__(16) unsigned char g_kh[NBATCH*NHEAD*S_LEN];
__device__ int g_qidx[NBATCH*NHEAD*S_LEN];
__device__ int g_kidx[NBATCH*NHEAD*S_LEN];

// Fast exp2 via MUFU.EX2 (one SFU op, ~2^-22 rel error)
__device__ __forceinline__ float fast_exp2(float x)
{
    float r;
    asm("ex2.approx.f32 %0, %1;" : "=f"(r) : "f"(x));
    return r;
}

// Split fp32 pair into hi/lo bf16 pairs packed as b32 (x in low half).
__device__ __forceinline__ void split2(float x, float y,
                                       unsigned& hi, unsigned& lo)
{
    __nv_bfloat16 hx = __float2bfloat16(x);
    __nv_bfloat16 hy = __float2bfloat16(y);
    __nv_bfloat16 lx = __float2bfloat16(x - __bfloat162float(hx));
    __nv_bfloat16 ly = __float2bfloat16(y - __bfloat162float(hy));
    hi = (unsigned)__bfloat16_as_ushort(hx) |
         ((unsigned)__bfloat16_as_ushort(hy) << 16);
    lo = (unsigned)__bfloat16_as_ushort(lx) |
         ((unsigned)__bfloat16_as_ushort(ly) << 16);
}

#define MMA(c, a0,a1,a2,a3, b0,b1) \
  asm volatile("mma.sync.aligned.m16n8k16.row.col.f32.bf16.bf16.f32 " \
    "{%0,%1,%2,%3}, {%4,%5,%6,%7}, {%8,%9}, {%0,%1,%2,%3};" \
    : "+f"((c)[0]), "+f"((c)[1]), "+f"((c)[2]), "+f"((c)[3]) \
    : "r"(a0), "r"(a1), "r"(a2), "r"(a3), "r"(b0), "r"(b1))

// ---------------------------------------------------------------------------
// Kernel 1: LSH hash. One CTA per (b,s). Padded smem rows (68 floats) kill
// bank conflicts; dot loop is float4.
// ---------------------------------------------------------------------------
__global__ void hyper_hash_kernel(const float* __restrict__ qkv,
                                  const float* __restrict__ proj)
{
    __shared__ float spT[8 * 68];        // proj transposed [r][d], padded
    __shared__ float row[32 * 68];       // 16 q rows then 16 k rows, padded
    __shared__ unsigned int sbits[128];

    int t  = threadIdx.x;                // 0..127
    int bs = blockIdx.x;                 // b*4096 + s
    int b  = bs >> 12;
    int s  = bs & (S_LEN - 1);

    if (t < 64) {                        // dim t, all 8 projections
        const float* pr = proj + t * 8;
#pragma unroll
        for (int r = 0; r < 8; r++) spT[r * 68 + t] = pr[r];
    }
    const float4* src = (const float4*)(qkv + (size_t)bs * 3072); // q+k = 512 f4
    float4* dst = (float4*)row;
#pragma unroll
    for (int i = 0; i < 4; i++) {
        int f = t + i * 128;             // 0..511
        dst[(f >> 4) * 17 + (f & 15)] = src[f];
    }
    __syncthreads();

    int h = t >> 3, r = t & 7;
    const float4* xq = (const float4*)(row + h * 68);
    const float4* xk = (const float4*)(row + (16 + h) * 68);
    const float4* pp = (const float4*)(spT + r * 68);
    float dq = 0.f, dk = 0.f;
#pragma unroll
    for (int i = 0; i < 16; i++) {
        float4 p4 = pp[i];
        float4 a  = xq[i];
        float4 c  = xk[i];
        dq += a.x*p4.x + a.y*p4.y + a.z*p4.z + a.w*p4.w;
        dk += c.x*p4.x + c.y*p4.y + c.z*p4.z + c.w*p4.w;
    }
    unsigned bq = (dq > 0.f) ? (1u << r) : 0u;
    unsigned bk = (dk > 0.f) ? (1u << r) : 0u;
    sbits[t] = bq | (bk << 8);
    __syncthreads();

    if (r == 0) {
        unsigned c = 0;
#pragma unroll
        for (int i = 0; i < 8; i++) c |= sbits[t + i];
        unsigned cq = c & 0xFFu, ck = (c >> 8) & 0xFFu;
        cq ^= cq >> 1;                   // Gray permutation
        ck ^= ck >> 1;
        size_t o = (size_t)(b * NHEAD + h) * S_LEN + s;
        g_qh[o] = (unsigned char)cq;
        g_kh[o] = (unsigned char)ck;
    }
}

// ---------------------------------------------------------------------------
// Kernel 2: stable counting sort of 4096 8-bit keys per (b,h). Unchanged.
// ---------------------------------------------------------------------------
__global__ void hyper_sort_kernel()
{
    int bh    = blockIdx.x;
    int which = blockIdx.y;
    const unsigned int* hw =
        (const unsigned int*)((which ? g_kh : g_qh) + (size_t)bh * S_LEN);
    int* idx = (which ? g_kidx : g_qidx) + (size_t)bh * S_LEN;

    __shared__ unsigned int w[1024];
    __shared__ int scan[256];
    int t = threadIdx.x;
#pragma unroll
    for (int i = 0; i < 4; i++) w[t + i * 256] = hw[t + i * 256];
    __syncthreads();

    unsigned k4 = t * 0x01010101u;
    int cnt = 0;
#pragma unroll 4
    for (int i = 0; i < 1024; i++) cnt += __popc(__vcmpeq4(w[i], k4));
    cnt >>= 3;

    scan[t] = cnt;
    __syncthreads();
    for (int off = 1; off < 256; off <<= 1) {
        int v = (t >= off) ? scan[t - off] : 0;
        __syncthreads();
        scan[t] += v;
        __syncthreads();
    }
    int pos = scan[t] - cnt;

    for (int i = 0; i < 1024; i++) {
        unsigned m = __vcmpeq4(w[i], k4);
        if (m) {
            int base = i * 4;
            if (m & 0x000000FFu) idx[pos++] = base;
            if (m & 0x0000FF00u) idx[pos++] = base + 1;
            if (m & 0x00FF0000u) idx[pos++] = base + 2;
            if (m & 0xFF000000u) idx[pos++] = base + 3;
        }
    }
}

// ---------------------------------------------------------------------------
// Kernel 3: fused attention on tensor cores (bf16 hi/lo split, fp32 accum).
// CTA = (g,h,b), 4 warps, warp w owns query rows [32w, 32w+32).
// Joint online softmax over 256 keys in 4 chunks of 64
// (chunks 0-1: block keys, bias 0; chunks 2-3: sampled keys, bias +5/-inf).
// ---------------------------------------------------------------------------
__global__ void __launch_bounds__(128, 2)
hyper_attn_kernel(const float* __restrict__ qkv,
                  const int*   __restrict__ sampled,
                  float*       __restrict__ out)
{
    __shared__ __align__(16) __nv_bfloat16 skh[64 * PITCH];
    __shared__ __align__(16) __nv_bfloat16 skl[64 * PITCH];
    __shared__ __align__(16) __nv_bfloat16 svh[64 * PITCH];
    __shared__ __align__(16) __nv_bfloat16 svl[64 * PITCH];
    __shared__ float sbias[64];
    __shared__ int   ssrc[64];
    __shared__ int   ssq[128];

    int g = blockIdx.x, h = blockIdx.y, b = blockIdx.z;
    int bh = b * NHEAD + h;
    int t  = threadIdx.x;
    int w  = t >> 5, l = t & 31;
    int lg = l >> 2;                     // row-group within mma tile
    int lq = l & 3;                      // quad lane (column pair selector)

    ssq[t] = g_qidx[(size_t)bh * S_LEN + g * BLK + t];
    __syncthreads();

    // ---- Q fragments, register resident, scale folded, hi/lo split ----
    const float qs = 0.125f * LOG2E;
    unsigned qhi[2][4][4], qlo[2][4][4];
#pragma unroll
    for (int mt = 0; mt < 2; mt++) {
        int rA = w * 32 + mt * 16 + lg;
        const float* qa = qkv + (size_t)(b * S_LEN + ssq[rA])     * 3072 + h * 64;
        const float* qb = qkv + (size_t)(b * S_LEN + ssq[rA + 8]) * 3072 + h * 64;
#pragma unroll
        for (int ks = 0; ks < 4; ks++) {
            int c0 = ks * 16 + lq * 2;
            float2 xa0 = *(const float2*)(qa + c0);
            float2 xb0 = *(const float2*)(qb + c0);
            float2 xa1 = *(const float2*)(qa + c0 + 8);
            float2 xb1 = *(const float2*)(qb + c0 + 8);
            split2(xa0.x * qs, xa0.y * qs, qhi[mt][ks][0], qlo[mt][ks][0]);
            split2(xb0.x * qs, xb0.y * qs, qhi[mt][ks][1], qlo[mt][ks][1]);
            split2(xa1.x * qs, xa1.y * qs, qhi[mt][ks][2], qlo[mt][ks][2]);
            split2(xb1.x * qs, xb1.y * qs, qhi[mt][ks][3], qlo[mt][ks][3]);
        }
    }

    float o[2][8][4];
#pragma unroll
    for (int mt = 0; mt < 2; mt++)
#pragma unroll
        for (int nt = 0; nt < 8; nt++)
#pragma unroll
            for (int q4 = 0; q4 < 4; q4++) o[mt][nt][q4] = 0.f;
    float mrow[4] = {-1e30f, -1e30f, -1e30f, -1e30f};
    float lrow[4] = {0.f, 0.f, 0.f, 0.f};

    for (int c = 0; c < 4; c++) {
        // ---- key list + bias for this chunk ----
        if (t < 64) {
            int pos; float bias;
            if (c < 2) { pos = g * BLK + c * 64 + t; bias = 0.f; }
            else {
                pos  = sampled[bh * NSAMP + (c - 2) * 64 + t];
                bias = ((pos >> 7) == g) ? -1e30f : 5.0f;   // log2(n/m) = 5
            }
            ssrc[t]  = g_kidx[(size_t)bh * S_LEN + pos];
            sbias[t] = bias;
        }
        __syncthreads();

        // ---- gather K/V, convert fp32 -> bf16 hi/lo into smem ----
#pragma unroll
        for (int i = 0; i < 8; i++) {
            int f = t + i * 128;
            int j = f >> 4, d4 = f & 15;
            const float4* kb =
                (const float4*)(qkv + (size_t)(b * S_LEN + ssrc[j]) * 3072
                                + 1024 + h * 64);
            float4 kk = kb[d4];
            float4 vv = kb[d4 + 256];
            unsigned h0, l0, h1, l1;
            int u = j * (PITCH / 2) + d4 * 2;    // u32 index
            split2(kk.x, kk.y, h0, l0); split2(kk.z, kk.w, h1, l1);
            ((unsigned*)skh)[u] = h0; ((unsigned*)skh)[u + 1] = h1;
            ((unsigned*)skl)[u] = l0; ((unsigned*)skl)[u + 1] = l1;
            split2(vv.x, vv.y, h0, l0); split2(vv.z, vv.w, h1, l1);
            ((unsigned*)svh)[u] = h0; ((unsigned*)svh)[u + 1] = h1;
            ((unsigned*)svl)[u] = l0; ((unsigned*)svl)[u + 1] = l1;
        }
        __syncthreads();

        // ---- S = Q K^T + bias (init accumulators with bias) ----
        float s[2][8][4];
#pragma unroll
        for (int nt = 0; nt < 8; nt++) {
            float2 bv = *(const float2*)(sbias + nt * 8 + lq * 2);
            s[0][nt][0] = bv.x; s[0][nt][1] = bv.y;
            s[0][nt][2] = bv.x; s[0][nt][3] = bv.y;
            s[1][nt][0] = bv.x; s[1][nt][1] = bv.y;
            s[1][nt][2] = bv.x; s[1][nt][3] = bv.y;
        }
#pragma unroll
        for (int ks = 0; ks < 4; ks++) {
#pragma unroll
            for (int nt = 0; nt < 8; nt++) {
                int u = (nt * 8 + lg) * (PITCH / 2) + ks * 8 + lq;
                unsigned bh0 = ((const unsigned*)skh)[u];
                unsigned bh1 = ((const unsigned*)skh)[u + 4];
                unsigned bl0 = ((const unsigned*)skl)[u];
                unsigned bl1 = ((const unsigned*)skl)[u + 4];
#pragma unroll
                for (int mt = 0; mt < 2; mt++) {
                    MMA(s[mt][nt], qhi[mt][ks][0], qhi[mt][ks][1],
                                   qhi[mt][ks][2], qhi[mt][ks][3], bh0, bh1);
                    MMA(s[mt][nt], qlo[mt][ks][0], qlo[mt][ks][1],
                                   qlo[mt][ks][2], qlo[mt][ks][3], bh0, bh1);
                    MMA(s[mt][nt], qhi[mt][ks][0], qhi[mt][ks][1],
                                   qhi[mt][ks][2], qhi[mt][ks][3], bl0, bl1);
                }
            }
        }

        // ---- online softmax (base-2), s becomes P ----
#pragma unroll
        for (int mt = 0; mt < 2; mt++) {
#pragma unroll
            for (int hh = 0; hh < 2; hh++) {
                float cm = -1e30f;
#pragma unroll
                for (int nt = 0; nt < 8; nt++)
                    cm = fmaxf(cm, fmaxf(s[mt][nt][2*hh], s[mt][nt][2*hh+1]));
                cm = fmaxf(cm, __shfl_xor_sync(0xFFFFFFFFu, cm, 1));
                cm = fmaxf(cm, __shfl_xor_sync(0xFFFFFFFFu, cm, 2));
                int ri = mt * 2 + hh;
                float nm  = fmaxf(mrow[ri], cm);
                float fsc = fast_exp2(mrow[ri] - nm);
                mrow[ri]  = nm;
                float ls = 0.f;
#pragma unroll
                for (int nt = 0; nt < 8; nt++) {
                    float p0 = fast_exp2(s[mt][nt][2*hh]     - nm);
                    float p1 = fast_exp2(s[mt][nt][2*hh + 1] - nm);
                    s[mt][nt][2*hh] = p0; s[mt][nt][2*hh+1] = p1;
                    ls += p0 + p1;
                }
                ls += __shfl_xor_sync(0xFFFFFFFFu, ls, 1);
                ls += __shfl_xor_sync(0xFFFFFFFFu, ls, 2);
                lrow[ri] = lrow[ri] * fsc + ls;
#pragma unroll
                for (int nt = 0; nt < 8; nt++) {
                    o[mt][nt][2*hh]     *= fsc;
                    o[mt][nt][2*hh + 1] *= fsc;
                }
            }
        }

        // ---- P -> bf16 hi/lo fragments ----
        unsigned phi[2][8][2], plo[2][8][2];
#pragma unroll
        for (int mt = 0; mt < 2; mt++)
#pragma unroll
            for (int nt = 0; nt < 8; nt++) {
                split2(s[mt][nt][0], s[mt][nt][1], phi[mt][nt][0], plo[mt][nt][0]);
                split2(s[mt][nt][2], s[mt][nt][3], phi[mt][nt][1], plo[mt][nt][1]);
            }

        // ---- O += P V ----
#pragma unroll
        for (int kap = 0; kap < 4; kap++) {
#pragma unroll
            for (int ntd = 0; ntd < 8; ntd++) {
                int n = ntd * 8 + lg;
                int k = kap * 16 + lq * 2;
                unsigned v00 = __bfloat16_as_ushort(svh[(k)     * PITCH + n]);
                unsigned v01 = __bfloat16_as_ushort(svh[(k + 1) * PITCH + n]);
                unsigned v08 = __bfloat16_as_ushort(svh[(k + 8) * PITCH + n]);
                unsigned v09 = __bfloat16_as_ushort(svh[(k + 9) * PITCH + n]);
                unsigned u00 = __bfloat16_as_ushort(svl[(k)     * PITCH + n]);
                unsigned u01 = __bfloat16_as_ushort(svl[(k + 1) * PITCH + n]);
                unsigned u08 = __bfloat16_as_ushort(svl[(k + 8) * PITCH + n]);
                unsigned u09 = __bfloat16_as_ushort(svl[(k + 9) * PITCH + n]);
                unsigned vh0 = v00 | (v01 << 16), vh1 = v08 | (v09 << 16);
                unsigned vl0 = u00 | (u01 << 16), vl1 = u08 | (u09 << 16);
#pragma unroll
                for (int mt = 0; mt < 2; mt++) {
                    MMA(o[mt][ntd], phi[mt][2*kap][0], phi[mt][2*kap][1],
                                    phi[mt][2*kap+1][0], phi[mt][2*kap+1][1],
                        vh0, vh1);
                    MMA(o[mt][ntd], plo[mt][2*kap][0], plo[mt][2*kap][1],
                                    plo[mt][2*kap+1][0], plo[mt][2*kap+1][1],
                        vh0, vh1);
                    MMA(o[mt][ntd], phi[mt][2*kap][0], phi[mt][2*kap][1],
                                    phi[mt][2*kap+1][0], phi[mt][2*kap+1][1],
                        vl0, vl1);
                }
            }
        }
        __syncthreads();   // smem reused next chunk
    }

    // ---- normalize + scatter back to original query order ----
#pragma unroll
    for (int mt = 0; mt < 2; mt++) {
#pragma unroll
        for (int hh = 0; hh < 2; hh++) {
            int ri = mt * 2 + hh;
            float inv = 1.0f / lrow[ri];
            int row = w * 32 + mt * 16 + hh * 8 + lg;
            float* op = out + ((size_t)(b * S_LEN + ssq[row]) * NHEAD + h) * 64;
#pragma unroll
            for (int nt = 0; nt < 8; nt++) {
                float2 v;
                v.x = o[mt][nt][2*hh]     * inv;
                v.y = o[mt][nt][2*hh + 1] * inv;
                *(float2*)(op + nt * 8 + lq * 2) = v;
            }
        }
    }
}

// ---------------------------------------------------------------------------
extern "C" void kernel_launch(void* const* d_in, const int* in_sizes, int n_in,
                              void* d_out, int out_size)
{
    const float* qkv     = (const float*)d_in[0];   // [2,4096,3,16,64] f32
    const float* proj    = (const float*)d_in[1];   // [64,8] f32
    const int*   sampled = (const int*)d_in[2];     // [2,16,128] i32
    float*       out     = (float*)d_out;           // [2,4096,16,64] f32

    hyper_hash_kernel<<<NBATCH * S_LEN, 128>>>(qkv, proj);
    hyper_sort_kernel<<<dim3(NBATCH * NHEAD, 2), 256>>>();
    hyper_attn_kernel<<<dim3(NBLK, NHEAD, NBATCH), 128>>>(qkv, sampled, out);
}

// round 6
// speedup vs baseline: 2.1862x; 1.2385x over previous
#include <cuda_runtime.h>
#include <cuda_bf16.h>

// Problem constants (fixed shapes)
#define S_LEN  4096
#define NHEAD  16
#define NBATCH 2
#define BLK    128
#define NBLK   32      // S_LEN / BLK
#define NSAMP  128
#define LOG2E  1.4426950408889634f
#define PITCH  72      // bf16 per smem row: 144B = 9*16B -> ldmatrix-aligned,
                       // row stride = 4 banks -> conflict-free 8-row phases

// ---------------- scratch (no cudaMalloc allowed) ----------------
__device__ __align__(16) unsigned char g_qh[NBATCH*NHEAD*S_LEN];
__device__ __align__(16) unsigned char g_kh[NBATCH*NHEAD*S_LEN];
__device__ int g_qidx[NBATCH*NHEAD*S_LEN];
__device__ int g_kidx[NBATCH*NHEAD*S_LEN];

__device__ __forceinline__ float fast_exp2(float x)
{
    float r;
    asm("ex2.approx.f32 %0, %1;" : "=f"(r) : "f"(x));
    return r;
}

// Split fp32 pair into hi/lo bf16 pairs packed as b32 (x in low half).
__device__ __forceinline__ void split2(float x, float y,
                                       unsigned& hi, unsigned& lo)
{
    __nv_bfloat16 hx = __float2bfloat16(x);
    __nv_bfloat16 hy = __float2bfloat16(y);
    __nv_bfloat16 lx = __float2bfloat16(x - __bfloat162float(hx));
    __nv_bfloat16 ly = __float2bfloat16(y - __bfloat162float(hy));
    hi = (unsigned)__bfloat16_as_ushort(hx) |
         ((unsigned)__bfloat16_as_ushort(hy) << 16);
    lo = (unsigned)__bfloat16_as_ushort(lx) |
         ((unsigned)__bfloat16_as_ushort(ly) << 16);
}

#define MMA(c, a0,a1,a2,a3, b0,b1) \
  asm volatile("mma.sync.aligned.m16n8k16.row.col.f32.bf16.bf16.f32 " \
    "{%0,%1,%2,%3}, {%4,%5,%6,%7}, {%8,%9}, {%0,%1,%2,%3};" \
    : "+f"((c)[0]), "+f"((c)[1]), "+f"((c)[2]), "+f"((c)[3]) \
    : "r"(a0), "r"(a1), "r"(a2), "r"(a3), "r"(b0), "r"(b1))

__device__ __forceinline__ void ldsm_x4(unsigned& r0, unsigned& r1,
                                        unsigned& r2, unsigned& r3,
                                        unsigned addr)
{
    asm volatile("ldmatrix.sync.aligned.m8n8.x4.shared.b16 {%0,%1,%2,%3}, [%4];"
                 : "=r"(r0), "=r"(r1), "=r"(r2), "=r"(r3) : "r"(addr));
}
__device__ __forceinline__ void ldsm_x4_t(unsigned& r0, unsigned& r1,
                                          unsigned& r2, unsigned& r3,
                                          unsigned addr)
{
    asm volatile("ldmatrix.sync.aligned.m8n8.x4.trans.shared.b16 {%0,%1,%2,%3}, [%4];"
                 : "=r"(r0), "=r"(r1), "=r"(r2), "=r"(r3) : "r"(addr));
}

// ---------------------------------------------------------------------------
// Kernel 1: LSH hash (unchanged from R5).
// ---------------------------------------------------------------------------
__global__ void hyper_hash_kernel(const float* __restrict__ qkv,
                                  const float* __restrict__ proj)
{
    __shared__ float spT[8 * 68];
    __shared__ float row[32 * 68];
    __shared__ unsigned int sbits[128];

    int t  = threadIdx.x;
    int bs = blockIdx.x;
    int b  = bs >> 12;
    int s  = bs & (S_LEN - 1);

    if (t < 64) {
        const float* pr = proj + t * 8;
#pragma unroll
        for (int r = 0; r < 8; r++) spT[r * 68 + t] = pr[r];
    }
    const float4* src = (const float4*)(qkv + (size_t)bs * 3072);
    float4* dst = (float4*)row;
#pragma unroll
    for (int i = 0; i < 4; i++) {
        int f = t + i * 128;
        dst[(f >> 4) * 17 + (f & 15)] = src[f];
    }
    __syncthreads();

    int h = t >> 3, r = t & 7;
    const float4* xq = (const float4*)(row + h * 68);
    const float4* xk = (const float4*)(row + (16 + h) * 68);
    const float4* pp = (const float4*)(spT + r * 68);
    float dq = 0.f, dk = 0.f;
#pragma unroll
    for (int i = 0; i < 16; i++) {
        float4 p4 = pp[i];
        float4 a  = xq[i];
        float4 c  = xk[i];
        dq += a.x*p4.x + a.y*p4.y + a.z*p4.z + a.w*p4.w;
        dk += c.x*p4.x + c.y*p4.y + c.z*p4.z + c.w*p4.w;
    }
    unsigned bq = (dq > 0.f) ? (1u << r) : 0u;
    unsigned bk = (dk > 0.f) ? (1u << r) : 0u;
    sbits[t] = bq | (bk << 8);
    __syncthreads();

    if (r == 0) {
        unsigned c = 0;
#pragma unroll
        for (int i = 0; i < 8; i++) c |= sbits[t + i];
        unsigned cq = c & 0xFFu, ck = (c >> 8) & 0xFFu;
        cq ^= cq >> 1;
        ck ^= ck >> 1;
        size_t o = (size_t)(b * NHEAD + h) * S_LEN + s;
        g_qh[o] = (unsigned char)cq;
        g_kh[o] = (unsigned char)ck;
    }
}

// ---------------------------------------------------------------------------
// Kernel 2: stable counting sort (unchanged).
// ---------------------------------------------------------------------------
__global__ void hyper_sort_kernel()
{
    int bh    = blockIdx.x;
    int which = blockIdx.y;
    const unsigned int* hw =
        (const unsigned int*)((which ? g_kh : g_qh) + (size_t)bh * S_LEN);
    int* idx = (which ? g_kidx : g_qidx) + (size_t)bh * S_LEN;

    __shared__ unsigned int w[1024];
    __shared__ int scan[256];
    int t = threadIdx.x;
#pragma unroll
    for (int i = 0; i < 4; i++) w[t + i * 256] = hw[t + i * 256];
    __syncthreads();

    unsigned k4 = t * 0x01010101u;
    int cnt = 0;
#pragma unroll 4
    for (int i = 0; i < 1024; i++) cnt += __popc(__vcmpeq4(w[i], k4));
    cnt >>= 3;

    scan[t] = cnt;
    __syncthreads();
    for (int off = 1; off < 256; off <<= 1) {
        int v = (t >= off) ? scan[t - off] : 0;
        __syncthreads();
        scan[t] += v;
        __syncthreads();
    }
    int pos = scan[t] - cnt;

    for (int i = 0; i < 1024; i++) {
        unsigned m = __vcmpeq4(w[i], k4);
        if (m) {
            int base = i * 4;
            if (m & 0x000000FFu) idx[pos++] = base;
            if (m & 0x0000FF00u) idx[pos++] = base + 1;
            if (m & 0x00FF0000u) idx[pos++] = base + 2;
            if (m & 0xFF000000u) idx[pos++] = base + 3;
        }
    }
}

// ---------------------------------------------------------------------------
// Kernel 3: fused attention, 256 threads, 8 warps (warp w = query rows
// [16w,16w+16)). ldmatrix K/V fragment loads, in-loop P split.
// ---------------------------------------------------------------------------
__global__ void __launch_bounds__(256, 2)
hyper_attn_kernel(const float* __restrict__ qkv,
                  const int*   __restrict__ sampled,
                  float*       __restrict__ out)
{
    __shared__ __align__(16) __nv_bfloat16 skh[64 * PITCH];
    __shared__ __align__(16) __nv_bfloat16 skl[64 * PITCH];
    __shared__ __align__(16) __nv_bfloat16 svh[64 * PITCH];
    __shared__ __align__(16) __nv_bfloat16 svl[64 * PITCH];
    __shared__ float sbias[64];
    __shared__ int   ssrc[64];
    __shared__ int   ssq[128];

    int g = blockIdx.x, h = blockIdx.y, b = blockIdx.z;
    int bh = b * NHEAD + h;
    int t  = threadIdx.x;
    int w  = t >> 5, l = t & 31;
    int lg = l >> 2;                     // 0..7
    int lq = l & 3;                      // 0..3
    int m8 = l >> 3, r8 = l & 7;         // ldmatrix lane split

    unsigned skh_b = (unsigned)__cvta_generic_to_shared(skh);
    unsigned skl_b = (unsigned)__cvta_generic_to_shared(skl);
    unsigned svh_b = (unsigned)__cvta_generic_to_shared(svh);
    unsigned svl_b = (unsigned)__cvta_generic_to_shared(svl);

    if (t < 128) ssq[t] = g_qidx[(size_t)bh * S_LEN + g * BLK + t];
    __syncthreads();

    // ---- Q fragments (16 rows per warp), scale folded, hi/lo split ----
    const float qs = 0.125f * LOG2E;
    unsigned qhi[4][4], qlo[4][4];
    {
        int rA = w * 16 + lg;
        const float* qa = qkv + (size_t)(b * S_LEN + ssq[rA])     * 3072 + h * 64;
        const float* qb = qkv + (size_t)(b * S_LEN + ssq[rA + 8]) * 3072 + h * 64;
#pragma unroll
        for (int ks = 0; ks < 4; ks++) {
            int c0 = ks * 16 + lq * 2;
            float2 xa0 = *(const float2*)(qa + c0);
            float2 xb0 = *(const float2*)(qb + c0);
            float2 xa1 = *(const float2*)(qa + c0 + 8);
            float2 xb1 = *(const float2*)(qb + c0 + 8);
            split2(xa0.x * qs, xa0.y * qs, qhi[ks][0], qlo[ks][0]);
            split2(xb0.x * qs, xb0.y * qs, qhi[ks][1], qlo[ks][1]);
            split2(xa1.x * qs, xa1.y * qs, qhi[ks][2], qlo[ks][2]);
            split2(xb1.x * qs, xb1.y * qs, qhi[ks][3], qlo[ks][3]);
        }
    }

    float o[8][4];
#pragma unroll
    for (int nt = 0; nt < 8; nt++)
#pragma unroll
        for (int q4 = 0; q4 < 4; q4++) o[nt][q4] = 0.f;
    float mrow[2] = {-1e30f, -1e30f};
    float lrow[2] = {0.f, 0.f};

    for (int c = 0; c < 4; c++) {
        // ---- key list + bias for this chunk ----
        if (t < 64) {
            int pos; float bias;
            if (c < 2) { pos = g * BLK + c * 64 + t; bias = 0.f; }
            else {
                pos  = sampled[bh * NSAMP + (c - 2) * 64 + t];
                bias = ((pos >> 7) == g) ? -1e30f : 5.0f;   // log2(n/m) = 5
            }
            ssrc[t]  = g_kidx[(size_t)bh * S_LEN + pos];
            sbias[t] = bias;
        }
        __syncthreads();

        // ---- gather K/V, convert fp32 -> bf16 hi/lo into smem ----
#pragma unroll
        for (int i = 0; i < 4; i++) {
            int f = t + i * 256;             // 0..1023
            int j = f >> 4, d4 = f & 15;
            const float4* kb =
                (const float4*)(qkv + (size_t)(b * S_LEN + ssrc[j]) * 3072
                                + 1024 + h * 64);
            float4 kk = kb[d4];
            float4 vv = kb[d4 + 256];
            unsigned h0, l0, h1, l1;
            int u = j * (PITCH / 2) + d4 * 2;
            split2(kk.x, kk.y, h0, l0); split2(kk.z, kk.w, h1, l1);
            ((unsigned*)skh)[u] = h0; ((unsigned*)skh)[u + 1] = h1;
            ((unsigned*)skl)[u] = l0; ((unsigned*)skl)[u + 1] = l1;
            split2(vv.x, vv.y, h0, l0); split2(vv.z, vv.w, h1, l1);
            ((unsigned*)svh)[u] = h0; ((unsigned*)svh)[u + 1] = h1;
            ((unsigned*)svl)[u] = l0; ((unsigned*)svl)[u + 1] = l1;
        }
        __syncthreads();

        // ---- S = Q K^T + bias ----
        float s[8][4];
#pragma unroll
        for (int nt = 0; nt < 8; nt++) {
            float2 bv = *(const float2*)(sbias + nt * 8 + lq * 2);
            s[nt][0] = bv.x; s[nt][1] = bv.y;
            s[nt][2] = bv.x; s[nt][3] = bv.y;
        }
#pragma unroll
        for (int ks = 0; ks < 4; ks++) {
#pragma unroll
            for (int ntp = 0; ntp < 4; ntp++) {
                // m0: keys nt0, d+0 -> b0(nt0); m1: nt0, d+8 -> b1(nt0);
                // m2: nt1, d+0 -> b0(nt1); m3: nt1, d+8 -> b1(nt1)
                int key   = (2 * ntp + (m8 >> 1)) * 8 + r8;
                int dbase = ks * 16 + (m8 & 1) * 8;
                unsigned off = (unsigned)(key * PITCH + dbase) * 2u;
                unsigned kh0, kh1, kh2, kh3, kl0, kl1, kl2, kl3;
                ldsm_x4(kh0, kh1, kh2, kh3, skh_b + off);
                ldsm_x4(kl0, kl1, kl2, kl3, skl_b + off);
                MMA(s[2*ntp],   qhi[ks][0],qhi[ks][1],qhi[ks][2],qhi[ks][3], kh0,kh1);
                MMA(s[2*ntp],   qlo[ks][0],qlo[ks][1],qlo[ks][2],qlo[ks][3], kh0,kh1);
                MMA(s[2*ntp],   qhi[ks][0],qhi[ks][1],qhi[ks][2],qhi[ks][3], kl0,kl1);
                MMA(s[2*ntp+1], qhi[ks][0],qhi[ks][1],qhi[ks][2],qhi[ks][3], kh2,kh3);
                MMA(s[2*ntp+1], qlo[ks][0],qlo[ks][1],qlo[ks][2],qlo[ks][3], kh2,kh3);
                MMA(s[2*ntp+1], qhi[ks][0],qhi[ks][1],qhi[ks][2],qhi[ks][3], kl2,kl3);
            }
        }

        // ---- online softmax (base-2), s becomes P ----
#pragma unroll
        for (int hh = 0; hh < 2; hh++) {
            float cm = -1e30f;
#pragma unroll
            for (int nt = 0; nt < 8; nt++)
                cm = fmaxf(cm, fmaxf(s[nt][2*hh], s[nt][2*hh+1]));
            cm = fmaxf(cm, __shfl_xor_sync(0xFFFFFFFFu, cm, 1));
            cm = fmaxf(cm, __shfl_xor_sync(0xFFFFFFFFu, cm, 2));
            float nm  = fmaxf(mrow[hh], cm);
            float fsc = fast_exp2(mrow[hh] - nm);
            mrow[hh]  = nm;
            float ls = 0.f;
#pragma unroll
            for (int nt = 0; nt < 8; nt++) {
                float p0 = fast_exp2(s[nt][2*hh]     - nm);
                float p1 = fast_exp2(s[nt][2*hh + 1] - nm);
                s[nt][2*hh] = p0; s[nt][2*hh+1] = p1;
                ls += p0 + p1;
            }
            ls += __shfl_xor_sync(0xFFFFFFFFu, ls, 1);
            ls += __shfl_xor_sync(0xFFFFFFFFu, ls, 2);
            lrow[hh] = lrow[hh] * fsc + ls;
#pragma unroll
            for (int nt = 0; nt < 8; nt++) {
                o[nt][2*hh]     *= fsc;
                o[nt][2*hh + 1] *= fsc;
            }
        }

        // ---- O += P V (P split in-loop; V via ldmatrix.trans) ----
#pragma unroll
        for (int kap = 0; kap < 4; kap++) {
            unsigned ph[4], pl[4];
            split2(s[2*kap][0],   s[2*kap][1],   ph[0], pl[0]);
            split2(s[2*kap][2],   s[2*kap][3],   ph[1], pl[1]);
            split2(s[2*kap+1][0], s[2*kap+1][1], ph[2], pl[2]);
            split2(s[2*kap+1][2], s[2*kap+1][3], ph[3], pl[3]);
#pragma unroll
            for (int ntdp = 0; ntdp < 4; ntdp++) {
                // m0: keys+0, d+0 -> b0(ntd0); m1: keys+8, d+0 -> b1(ntd0);
                // m2: keys+0, d+8 -> b0(ntd1); m3: keys+8, d+8 -> b1(ntd1)
                int key   = kap * 16 + (m8 & 1) * 8 + r8;
                int dbase = ntdp * 16 + (m8 >> 1) * 8;
                unsigned off = (unsigned)(key * PITCH + dbase) * 2u;
                unsigned vh0, vh1, vh2, vh3, vl0, vl1, vl2, vl3;
                ldsm_x4_t(vh0, vh1, vh2, vh3, svh_b + off);
                ldsm_x4_t(vl0, vl1, vl2, vl3, svl_b + off);
                MMA(o[2*ntdp],   ph[0],ph[1],ph[2],ph[3], vh0,vh1);
                MMA(o[2*ntdp],   pl[0],pl[1],pl[2],pl[3], vh0,vh1);
                MMA(o[2*ntdp],   ph[0],ph[1],ph[2],ph[3], vl0,vl1);
                MMA(o[2*ntdp+1], ph[0],ph[1],ph[2],ph[3], vh2,vh3);
                MMA(o[2*ntdp+1], pl[0],pl[1],pl[2],pl[3], vh2,vh3);
                MMA(o[2*ntdp+1], ph[0],ph[1],ph[2],ph[3], vl2,vl3);
            }
        }
        __syncthreads();   // smem reused next chunk
    }

    // ---- normalize + scatter back to original query order ----
#pragma unroll
    for (int hh = 0; hh < 2; hh++) {
        float inv = 1.0f / lrow[hh];
        int row = w * 16 + hh * 8 + lg;
        float* op = out + ((size_t)(b * S_LEN + ssq[row]) * NHEAD + h) * 64;
#pragma unroll
        for (int nt = 0; nt < 8; nt++) {
            float2 v;
            v.x = o[nt][2*hh]     * inv;
            v.y = o[nt][2*hh + 1] * inv;
            *(float2*)(op + nt * 8 + lq * 2) = v;
        }
    }
}

// ---------------------------------------------------------------------------
extern "C" void kernel_launch(void* const* d_in, const int* in_sizes, int n_in,
                              void* d_out, int out_size)
{
    const float* qkv     = (const float*)d_in[0];   // [2,4096,3,16,64] f32
    const float* proj    = (const float*)d_in[1];   // [64,8] f32
    const int*   sampled = (const int*)d_in[2];     // [2,16,128] i32
    float*       out     = (float*)d_out;           // [2,4096,16,64] f32

    hyper_hash_kernel<<<NBATCH * S_LEN, 128>>>(qkv, proj);
    hyper_sort_kernel<<<dim3(NBATCH * NHEAD, 2), 256>>>();
    hyper_attn_kernel<<<dim3(NBLK, NHEAD, NBATCH), 256>>>(qkv, sampled, out);
}

// round 7
// speedup vs baseline: 2.4074x; 1.1012x over previous
#include <cuda_runtime.h>
#include <cuda_bf16.h>

// Problem constants (fixed shapes)
#define S_LEN  4096
#define NHEAD  16
#define NBATCH 2
#define NBH    (NBATCH*NHEAD)
#define BLK    128
#define NBLK   32
#define NSAMP  128
#define LOG2E  1.4426950408889634f
#define COMP_BYTES ((size_t)NBH * S_LEN * 128)   // one packed component

// ---------------- scratch (no cudaMalloc allowed) ----------------
__device__ __align__(16) unsigned char g_qh[NBH*S_LEN];
__device__ __align__(16) unsigned char g_kh[NBH*S_LEN];
__device__ int g_qidx[NBH*S_LEN];
__device__ int g_kidx[NBH*S_LEN];
// packed K/V rows: [comp(khi,klo,vhi,vlo)][bh][token][128B]
__device__ __align__(128) unsigned char g_pack[4 * NBH * S_LEN * 128];

__device__ __forceinline__ float fast_exp2(float x)
{
    float r;
    asm("ex2.approx.f32 %0, %1;" : "=f"(r) : "f"(x));
    return r;
}

// Split fp32 pair into hi/lo bf16 pairs packed as b32 (x in low half).
__device__ __forceinline__ void split2(float x, float y,
                                       unsigned& hi, unsigned& lo)
{
    __nv_bfloat16 hx = __float2bfloat16(x);
    __nv_bfloat16 hy = __float2bfloat16(y);
    __nv_bfloat16 lx = __float2bfloat16(x - __bfloat162float(hx));
    __nv_bfloat16 ly = __float2bfloat16(y - __bfloat162float(hy));
    hi = (unsigned)__bfloat16_as_ushort(hx) |
         ((unsigned)__bfloat16_as_ushort(hy) << 16);
    lo = (unsigned)__bfloat16_as_ushort(lx) |
         ((unsigned)__bfloat16_as_ushort(ly) << 16);
}

#define MMA(c, a0,a1,a2,a3, b0,b1) \
  asm volatile("mma.sync.aligned.m16n8k16.row.col.f32.bf16.bf16.f32 " \
    "{%0,%1,%2,%3}, {%4,%5,%6,%7}, {%8,%9}, {%0,%1,%2,%3};" \
    : "+f"((c)[0]), "+f"((c)[1]), "+f"((c)[2]), "+f"((c)[3]) \
    : "r"(a0), "r"(a1), "r"(a2), "r"(a3), "r"(b0), "r"(b1))

__device__ __forceinline__ void ldsm_x4(unsigned& r0, unsigned& r1,
                                        unsigned& r2, unsigned& r3,
                                        unsigned addr)
{
    asm volatile("ldmatrix.sync.aligned.m8n8.x4.shared.b16 {%0,%1,%2,%3}, [%4];"
                 : "=r"(r0), "=r"(r1), "=r"(r2), "=r"(r3) : "r"(addr));
}
__device__ __forceinline__ void ldsm_x4_t(unsigned& r0, unsigned& r1,
                                          unsigned& r2, unsigned& r3,
                                          unsigned addr)
{
    asm volatile("ldmatrix.sync.aligned.m8n8.x4.trans.shared.b16 {%0,%1,%2,%3}, [%4];"
                 : "=r"(r0), "=r"(r1), "=r"(r2), "=r"(r3) : "r"(addr));
}

__device__ __forceinline__ void cp16(unsigned dst, const void* src)
{
    asm volatile("cp.async.cg.shared.global [%0], [%1], 16;"
                 :: "r"(dst), "l"(src) : "memory");
}
__device__ __forceinline__ void cp_commit()
{
    asm volatile("cp.async.commit_group;" ::: "memory");
}
template<int N> __device__ __forceinline__ void cp_wait()
{
    asm volatile("cp.async.wait_group %0;" :: "n"(N) : "memory");
}

// ---------------------------------------------------------------------------
// Kernel 1: LSH hash + K/V bf16 hi/lo pre-pack. One CTA per (b,s), 256 thr.
// ---------------------------------------------------------------------------
__global__ void __launch_bounds__(256)
hyper_hash_pack_kernel(const float* __restrict__ qkv,
                       const float* __restrict__ proj)
{
    __shared__ float spT[8 * 68];
    __shared__ float row[32 * 68];       // 16 q rows then 16 k rows, padded
    __shared__ unsigned int sbits[128];

    int t  = threadIdx.x;                // 0..255
    int bs = blockIdx.x;                 // b*4096 + s
    int b  = bs >> 12;
    int s  = bs & (S_LEN - 1);
    int hh = t >> 4, dg = t & 15;        // pack assignment: head, 4-float group

    // V row piece for pack (independent of smem)
    float4 vvec = *(const float4*)(qkv + (size_t)bs * 3072 + 2048
                                   + hh * 64 + dg * 4);

    if (t < 64) {
        const float* pr = proj + t * 8;
#pragma unroll
        for (int r = 0; r < 8; r++) spT[r * 68 + t] = pr[r];
    }
    const float4* src = (const float4*)(qkv + (size_t)bs * 3072); // q+k = 512 f4
    float4* dst = (float4*)row;
#pragma unroll
    for (int i = 0; i < 2; i++) {
        int f = t + i * 256;
        dst[(f >> 4) * 17 + (f & 15)] = src[f];
    }
    __syncthreads();

    // ---- pack K (from smem) and V (from reg) into g_pack ----
    {
        float4 kvec = *(const float4*)(row + (16 + hh) * 68 + dg * 4);
        int bh = b * NHEAD + hh;
        size_t rb = (((size_t)bh) * S_LEN + s) * 128 + dg * 8;
        unsigned h0, l0, h1, l1;
        split2(kvec.x, kvec.y, h0, l0); split2(kvec.z, kvec.w, h1, l1);
        *(uint2*)(g_pack + 0 * COMP_BYTES + rb) = make_uint2(h0, h1);
        *(uint2*)(g_pack + 1 * COMP_BYTES + rb) = make_uint2(l0, l1);
        split2(vvec.x, vvec.y, h0, l0); split2(vvec.z, vvec.w, h1, l1);
        *(uint2*)(g_pack + 2 * COMP_BYTES + rb) = make_uint2(h0, h1);
        *(uint2*)(g_pack + 3 * COMP_BYTES + rb) = make_uint2(l0, l1);
    }

    // ---- hash: threads 0..127 = (head, projection) ----
    if (t < 128) {
        int h = t >> 3, r = t & 7;
        const float4* xq = (const float4*)(row + h * 68);
        const float4* xk = (const float4*)(row + (16 + h) * 68);
        const float4* pp = (const float4*)(spT + r * 68);
        float dq = 0.f, dk = 0.f;
#pragma unroll
        for (int i = 0; i < 16; i++) {
            float4 p4 = pp[i];
            float4 a  = xq[i];
            float4 c  = xk[i];
            dq += a.x*p4.x + a.y*p4.y + a.z*p4.z + a.w*p4.w;
            dk += c.x*p4.x + c.y*p4.y + c.z*p4.z + c.w*p4.w;
        }
        unsigned bq = (dq > 0.f) ? (1u << r) : 0u;
        unsigned bk = (dk > 0.f) ? (1u << r) : 0u;
        sbits[t] = bq | (bk << 8);
    }
    __syncthreads();
    if (t < 128 && (t & 7) == 0) {
        unsigned c = 0;
#pragma unroll
        for (int i = 0; i < 8; i++) c |= sbits[t + i];
        unsigned cq = c & 0xFFu, ck = (c >> 8) & 0xFFu;
        cq ^= cq >> 1;                   // Gray permutation
        ck ^= ck >> 1;
        size_t o = (size_t)(b * NHEAD + (t >> 3)) * S_LEN + s;
        g_qh[o] = (unsigned char)cq;
        g_kh[o] = (unsigned char)ck;
    }
}

// ---------------------------------------------------------------------------
// Kernel 2: stable counting sort of 4096 8-bit keys per (b,h). Unchanged.
// ---------------------------------------------------------------------------
__global__ void hyper_sort_kernel()
{
    int bh    = blockIdx.x;
    int which = blockIdx.y;
    const unsigned int* hw =
        (const unsigned int*)((which ? g_kh : g_qh) + (size_t)bh * S_LEN);
    int* idx = (which ? g_kidx : g_qidx) + (size_t)bh * S_LEN;

    __shared__ unsigned int w[1024];
    __shared__ int scan[256];
    int t = threadIdx.x;
#pragma unroll
    for (int i = 0; i < 4; i++) w[t + i * 256] = hw[t + i * 256];
    __syncthreads();

    unsigned k4 = t * 0x01010101u;
    int cnt = 0;
#pragma unroll 4
    for (int i = 0; i < 1024; i++) cnt += __popc(__vcmpeq4(w[i], k4));
    cnt >>= 3;

    scan[t] = cnt;
    __syncthreads();
    for (int off = 1; off < 256; off <<= 1) {
        int v = (t >= off) ? scan[t - off] : 0;
        __syncthreads();
        scan[t] += v;
        __syncthreads();
    }
    int pos = scan[t] - cnt;

    for (int i = 0; i < 1024; i++) {
        unsigned m = __vcmpeq4(w[i], k4);
        if (m) {
            int base = i * 4;
            if (m & 0x000000FFu) idx[pos++] = base;
            if (m & 0x0000FF00u) idx[pos++] = base + 1;
            if (m & 0x00FF0000u) idx[pos++] = base + 2;
            if (m & 0xFF000000u) idx[pos++] = base + 3;
        }
    }
}

// ---------------------------------------------------------------------------
// Kernel 3: fused attention, 256 threads, cp.async double-buffered tile
// loads from g_pack (no conversion in-kernel), XOR-swizzled 128B smem rows.
// Dynamic smem: 2 buffers x 4 comps x 64 rows x 128 B = 64 KB.
// ---------------------------------------------------------------------------
extern __shared__ __align__(16) unsigned char dyn_smem[];

__global__ void __launch_bounds__(256, 2)
hyper_attn_kernel(const float* __restrict__ qkv,
                  const int*   __restrict__ sampled,
                  float*       __restrict__ out)
{
    __shared__ int   ssq[128];
    __shared__ int   ssrc_all[256];
    __shared__ float sbias_all[256];

    unsigned sbase = (unsigned)__cvta_generic_to_shared(dyn_smem);

    int g = blockIdx.x, h = blockIdx.y, b = blockIdx.z;
    int bh = b * NHEAD + h;
    int t  = threadIdx.x;
    int w  = t >> 5, l = t & 31;
    int lg = l >> 2, lq = l & 3;
    int m8 = l >> 3, r8 = l & 7;

    if (t < 128) ssq[t] = g_qidx[(size_t)bh * S_LEN + g * BLK + t];
    {   // all 4 chunks' key lists + biases in one pass
        int c = t >> 6, j = t & 63;
        int pos; float bias;
        if (c < 2) { pos = g * BLK + c * 64 + j; bias = 0.f; }
        else {
            pos  = sampled[bh * NSAMP + (c - 2) * 64 + j];
            bias = ((pos >> 7) == g) ? -1e30f : 5.0f;   // log2(n/m) = 5
        }
        ssrc_all[t]  = g_kidx[(size_t)bh * S_LEN + pos];
        sbias_all[t] = bias;
    }
    __syncthreads();

    // ---- prefetch chunk 0 ----
#define FILL_CHUNK(cc, bb)                                                    \
    {                                                                         \
        _Pragma("unroll")                                                     \
        for (int i = 0; i < 8; i++) {                                         \
            int lin = t + i * 256;                                            \
            int comp = lin >> 9, rowg = lin & 511;                            \
            int rr = rowg >> 3, gg = rowg & 7;                                \
            int srow = ssrc_all[(cc) * 64 + rr];                              \
            const void* sp = g_pack + (size_t)comp * COMP_BYTES               \
                             + (((size_t)bh) * S_LEN + srow) * 128 + gg * 16; \
            unsigned dp = sbase + (bb) * 32768 + comp * 8192 + rr * 128       \
                          + ((gg ^ (rr & 7)) << 4);                           \
            cp16(dp, sp);                                                     \
        }                                                                     \
        cp_commit();                                                          \
    }
    FILL_CHUNK(0, 0);

    // ---- Q fragments (16 rows per warp), scale folded, hi/lo split ----
    const float qs = 0.125f * LOG2E;
    unsigned qhi[4][4], qlo[4][4];
    {
        int rA = w * 16 + lg;
        const float* qa = qkv + (size_t)(b * S_LEN + ssq[rA])     * 3072 + h * 64;
        const float* qb = qkv + (size_t)(b * S_LEN + ssq[rA + 8]) * 3072 + h * 64;
#pragma unroll
        for (int ks = 0; ks < 4; ks++) {
            int c0 = ks * 16 + lq * 2;
            float2 xa0 = *(const float2*)(qa + c0);
            float2 xb0 = *(const float2*)(qb + c0);
            float2 xa1 = *(const float2*)(qa + c0 + 8);
            float2 xb1 = *(const float2*)(qb + c0 + 8);
            split2(xa0.x * qs, xa0.y * qs, qhi[ks][0], qlo[ks][0]);
            split2(xb0.x * qs, xb0.y * qs, qhi[ks][1], qlo[ks][1]);
            split2(xa1.x * qs, xa1.y * qs, qhi[ks][2], qlo[ks][2]);
            split2(xb1.x * qs, xb1.y * qs, qhi[ks][3], qlo[ks][3]);
        }
    }

    float o[8][4];
#pragma unroll
    for (int nt = 0; nt < 8; nt++)
#pragma unroll
        for (int q4 = 0; q4 < 4; q4++) o[nt][q4] = 0.f;
    float mrow[2] = {-1e30f, -1e30f};
    float lrow[2] = {0.f, 0.f};

#pragma unroll
    for (int c = 0; c < 4; c++) {
        if (c < 3) { FILL_CHUNK(c + 1, (c + 1) & 1); cp_wait<1>(); }
        else       { cp_wait<0>(); }
        __syncthreads();

        unsigned tb  = sbase + (c & 1) * 32768;
        unsigned khb = tb, klb = tb + 8192, vhb = tb + 16384, vlb = tb + 24576;

        // ---- S = Q K^T + bias ----
        float s[8][4];
#pragma unroll
        for (int nt = 0; nt < 8; nt++) {
            float2 bv = *(const float2*)(sbias_all + c * 64 + nt * 8 + lq * 2);
            s[nt][0] = bv.x; s[nt][1] = bv.y;
            s[nt][2] = bv.x; s[nt][3] = bv.y;
        }
#pragma unroll
        for (int ks = 0; ks < 4; ks++) {
#pragma unroll
            for (int ntp = 0; ntp < 4; ntp++) {
                int key  = (2 * ntp + (m8 >> 1)) * 8 + r8;
                int gidx = ks * 2 + (m8 & 1);
                unsigned off = (unsigned)(key * 128 + ((gidx ^ (key & 7)) << 4));
                unsigned kh0, kh1, kh2, kh3, kl0, kl1, kl2, kl3;
                ldsm_x4(kh0, kh1, kh2, kh3, khb + off);
                ldsm_x4(kl0, kl1, kl2, kl3, klb + off);
                MMA(s[2*ntp],   qhi[ks][0],qhi[ks][1],qhi[ks][2],qhi[ks][3], kh0,kh1);
                MMA(s[2*ntp],   qlo[ks][0],qlo[ks][1],qlo[ks][2],qlo[ks][3], kh0,kh1);
                MMA(s[2*ntp],   qhi[ks][0],qhi[ks][1],qhi[ks][2],qhi[ks][3], kl0,kl1);
                MMA(s[2*ntp+1], qhi[ks][0],qhi[ks][1],qhi[ks][2],qhi[ks][3], kh2,kh3);
                MMA(s[2*ntp+1], qlo[ks][0],qlo[ks][1],qlo[ks][2],qlo[ks][3], kh2,kh3);
                MMA(s[2*ntp+1], qhi[ks][0],qhi[ks][1],qhi[ks][2],qhi[ks][3], kl2,kl3);
            }
        }

        // ---- online softmax (base-2), s becomes P ----
#pragma unroll
        for (int hh = 0; hh < 2; hh++) {
            float cm = -1e30f;
#pragma unroll
            for (int nt = 0; nt < 8; nt++)
                cm = fmaxf(cm, fmaxf(s[nt][2*hh], s[nt][2*hh+1]));
            cm = fmaxf(cm, __shfl_xor_sync(0xFFFFFFFFu, cm, 1));
            cm = fmaxf(cm, __shfl_xor_sync(0xFFFFFFFFu, cm, 2));
            float nm  = fmaxf(mrow[hh], cm);
            float fsc = fast_exp2(mrow[hh] - nm);
            mrow[hh]  = nm;
            float ls = 0.f;
#pragma unroll
            for (int nt = 0; nt < 8; nt++) {
                float p0 = fast_exp2(s[nt][2*hh]     - nm);
                float p1 = fast_exp2(s[nt][2*hh + 1] - nm);
                s[nt][2*hh] = p0; s[nt][2*hh+1] = p1;
                ls += p0 + p1;
            }
            ls += __shfl_xor_sync(0xFFFFFFFFu, ls, 1);
            ls += __shfl_xor_sync(0xFFFFFFFFu, ls, 2);
            lrow[hh] = lrow[hh] * fsc + ls;
#pragma unroll
            for (int nt = 0; nt < 8; nt++) {
                o[nt][2*hh]     *= fsc;
                o[nt][2*hh + 1] *= fsc;
            }
        }

        // ---- O += P V (P split in-loop; V via ldmatrix.trans) ----
#pragma unroll
        for (int kap = 0; kap < 4; kap++) {
            unsigned ph[4], pl[4];
            split2(s[2*kap][0],   s[2*kap][1],   ph[0], pl[0]);
            split2(s[2*kap][2],   s[2*kap][3],   ph[1], pl[1]);
            split2(s[2*kap+1][0], s[2*kap+1][1], ph[2], pl[2]);
            split2(s[2*kap+1][2], s[2*kap+1][3], ph[3], pl[3]);
#pragma unroll
            for (int ntdp = 0; ntdp < 4; ntdp++) {
                int key  = kap * 16 + (m8 & 1) * 8 + r8;
                int gidx = ntdp * 2 + (m8 >> 1);
                unsigned off = (unsigned)(key * 128 + ((gidx ^ (key & 7)) << 4));
                unsigned vh0, vh1, vh2, vh3, vl0, vl1, vl2, vl3;
                ldsm_x4_t(vh0, vh1, vh2, vh3, vhb + off);
                ldsm_x4_t(vl0, vl1, vl2, vl3, vlb + off);
                MMA(o[2*ntdp],   ph[0],ph[1],ph[2],ph[3], vh0,vh1);
                MMA(o[2*ntdp],   pl[0],pl[1],pl[2],pl[3], vh0,vh1);
                MMA(o[2*ntdp],   ph[0],ph[1],ph[2],ph[3], vl0,vl1);
                MMA(o[2*ntdp+1], ph[0],ph[1],ph[2],ph[3], vh2,vh3);
                MMA(o[2*ntdp+1], pl[0],pl[1],pl[2],pl[3], vh2,vh3);
                MMA(o[2*ntdp+1], ph[0],ph[1],ph[2],ph[3], vl2,vl3);
            }
        }
        __syncthreads();   // buffer (c&1) reused by fill at next iteration
    }

    // ---- normalize + scatter back to original query order ----
#pragma unroll
    for (int hh = 0; hh < 2; hh++) {
        float inv = 1.0f / lrow[hh];
        int row = w * 16 + hh * 8 + lg;
        float* op = out + ((size_t)(b * S_LEN + ssq[row]) * NHEAD + h) * 64;
#pragma unroll
        for (int nt = 0; nt < 8; nt++) {
            float2 v;
            v.x = o[nt][2*hh]     * inv;
            v.y = o[nt][2*hh + 1] * inv;
            *(float2*)(op + nt * 8 + lq * 2) = v;
        }
    }
}

// ---------------------------------------------------------------------------
extern "C" void kernel_launch(void* const* d_in, const int* in_sizes, int n_in,
                              void* d_out, int out_size)
{
    const float* qkv     = (const float*)d_in[0];   // [2,4096,3,16,64] f32
    const float* proj    = (const float*)d_in[1];   // [64,8] f32
    const int*   sampled = (const int*)d_in[2];     // [2,16,128] i32
    float*       out     = (float*)d_out;           // [2,4096,16,64] f32

    cudaFuncSetAttribute(hyper_attn_kernel,
                         cudaFuncAttributeMaxDynamicSharedMemorySize, 65536);

    hyper_hash_pack_kernel<<<NBATCH * S_LEN, 256>>>(qkv, proj);
    hyper_sort_kernel<<<dim3(NBH, 2), 256>>>();
    hyper_attn_kernel<<<dim3(NBLK, NHEAD, NBATCH), 256, 65536>>>(qkv, sampled, out);
}

// round 9
// speedup vs baseline: 2.6775x; 1.1122x over previous
#include <cuda_runtime.h>
#include <cuda_fp16.h>

// Problem constants (fixed shapes)
#define S_LEN  4096
#define NHEAD  16
#define NBATCH 2
#define NBH    (NBATCH*NHEAD)
#define BLK    128
#define NBLK   32
#define NSAMP  128
#define LOG2E  1.4426950408889634f
#define COMP_BYTES ((size_t)NBH * S_LEN * 128)   // one packed component

// ---------------- scratch (no cudaMalloc allowed) ----------------
__device__ __align__(16) unsigned char g_qh[NBH*S_LEN];
__device__ __align__(16) unsigned char g_kh[NBH*S_LEN];
__device__ int g_qidx[NBH*S_LEN];
__device__ int g_kidx[NBH*S_LEN];
// packed K/V rows (fp16): [comp(khi,klo,vhi,vlo)][bh][token][128B]
__device__ __align__(128) unsigned char g_pack[4 * NBH * S_LEN * 128];

__device__ __forceinline__ float fast_exp2(float x)
{
    float r;
    asm("ex2.approx.f32 %0, %1;" : "=f"(r) : "f"(x));
    return r;
}

// fp16 hi/lo split of an fp32 pair, packed as b32 (x in low half).
__device__ __forceinline__ void split2f(float x, float y,
                                        unsigned& hi, unsigned& lo)
{
    __half hx = __float2half_rn(x), hy = __float2half_rn(y);
    float  fx = __half2float(hx),  fy = __half2float(hy);
    __half lx = __float2half_rn(x - fx), ly = __float2half_rn(y - fy);
    hi = (unsigned)__half_as_ushort(hx) | ((unsigned)__half_as_ushort(hy) << 16);
    lo = (unsigned)__half_as_ushort(lx) | ((unsigned)__half_as_ushort(ly) << 16);
}

// fp32 pair -> packed fp16x2
__device__ __forceinline__ unsigned pack_h2(float x, float y)
{
    __half2 h = __floats2half2_rn(x, y);
    return *reinterpret_cast<unsigned*>(&h);
}

#define MMAH(c, a0,a1,a2,a3, b0,b1) \
  asm volatile("mma.sync.aligned.m16n8k16.row.col.f32.f16.f16.f32 " \
    "{%0,%1,%2,%3}, {%4,%5,%6,%7}, {%8,%9}, {%0,%1,%2,%3};" \
    : "+f"((c)[0]), "+f"((c)[1]), "+f"((c)[2]), "+f"((c)[3]) \
    : "r"(a0), "r"(a1), "r"(a2), "r"(a3), "r"(b0), "r"(b1))

__device__ __forceinline__ void ldsm_x4(unsigned& r0, unsigned& r1,
                                        unsigned& r2, unsigned& r3,
                                        unsigned addr)
{
    asm volatile("ldmatrix.sync.aligned.m8n8.x4.shared.b16 {%0,%1,%2,%3}, [%4];"
                 : "=r"(r0), "=r"(r1), "=r"(r2), "=r"(r3) : "r"(addr));
}
__device__ __forceinline__ void ldsm_x4_t(unsigned& r0, unsigned& r1,
                                          unsigned& r2, unsigned& r3,
                                          unsigned addr)
{
    asm volatile("ldmatrix.sync.aligned.m8n8.x4.trans.shared.b16 {%0,%1,%2,%3}, [%4];"
                 : "=r"(r0), "=r"(r1), "=r"(r2), "=r"(r3) : "r"(addr));
}

__device__ __forceinline__ void cp16(unsigned dst, const void* src)
{
    asm volatile("cp.async.cg.shared.global [%0], [%1], 16;"
                 :: "r"(dst), "l"(src) : "memory");
}
__device__ __forceinline__ void cp_commit()
{ asm volatile("cp.async.commit_group;" ::: "memory"); }
template<int N> __device__ __forceinline__ void cp_wait()
{ asm volatile("cp.async.wait_group %0;" :: "n"(N) : "memory"); }

// ---------------------------------------------------------------------------
// Kernel 1: LSH hash + K/V fp16 hi/lo pre-pack. One CTA per (b,s), 256 thr.
// ---------------------------------------------------------------------------
__global__ void __launch_bounds__(256)
hyper_hash_pack_kernel(const float* __restrict__ qkv,
                       const float* __restrict__ proj)
{
    __shared__ float spT[8 * 68];
    __shared__ float row[32 * 68];       // 16 q rows then 16 k rows, padded
    __shared__ unsigned int sbits[128];

    int t  = threadIdx.x;                // 0..255
    int bs = blockIdx.x;                 // b*4096 + s
    int b  = bs >> 12;
    int s  = bs & (S_LEN - 1);
    int hh = t >> 4, dg = t & 15;        // pack assignment: head, 4-float group

    float4 vvec = *(const float4*)(qkv + (size_t)bs * 3072 + 2048
                                   + hh * 64 + dg * 4);

    if (t < 64) {
        const float* pr = proj + t * 8;
#pragma unroll
        for (int r = 0; r < 8; r++) spT[r * 68 + t] = pr[r];
    }
    const float4* src = (const float4*)(qkv + (size_t)bs * 3072); // q+k = 512 f4
    float4* dst = (float4*)row;
#pragma unroll
    for (int i = 0; i < 2; i++) {
        int f = t + i * 256;
        dst[(f >> 4) * 17 + (f & 15)] = src[f];
    }
    __syncthreads();

    // ---- pack K (from smem) and V (from reg) into g_pack (fp16 hi/lo) ----
    {
        float4 kvec = *(const float4*)(row + (16 + hh) * 68 + dg * 4);
        int bh = b * NHEAD + hh;
        size_t rb = (((size_t)bh) * S_LEN + s) * 128 + dg * 8;
        unsigned h0, l0, h1, l1;
        split2f(kvec.x, kvec.y, h0, l0); split2f(kvec.z, kvec.w, h1, l1);
        *(uint2*)(g_pack + 0 * COMP_BYTES + rb) = make_uint2(h0, h1);
        *(uint2*)(g_pack + 1 * COMP_BYTES + rb) = make_uint2(l0, l1);
        split2f(vvec.x, vvec.y, h0, l0); split2f(vvec.z, vvec.w, h1, l1);
        *(uint2*)(g_pack + 2 * COMP_BYTES + rb) = make_uint2(h0, h1);
        *(uint2*)(g_pack + 3 * COMP_BYTES + rb) = make_uint2(l0, l1);
    }

    // ---- hash: threads 0..127 = (head, projection) ----
    if (t < 128) {
        int h = t >> 3, r = t & 7;
        const float4* xq = (const float4*)(row + h * 68);
        const float4* xk = (const float4*)(row + (16 + h) * 68);
        const float4* pp = (const float4*)(spT + r * 68);
        float dq = 0.f, dk = 0.f;
#pragma unroll
        for (int i = 0; i < 16; i++) {
            float4 p4 = pp[i];
            float4 a  = xq[i];
            float4 c  = xk[i];
            dq += a.x*p4.x + a.y*p4.y + a.z*p4.z + a.w*p4.w;
            dk += c.x*p4.x + c.y*p4.y + c.z*p4.z + c.w*p4.w;
        }
        unsigned bq = (dq > 0.f) ? (1u << r) : 0u;
        unsigned bk = (dk > 0.f) ? (1u << r) : 0u;
        sbits[t] = bq | (bk << 8);
    }
    __syncthreads();
    if (t < 128 && (t & 7) == 0) {
        unsigned c = 0;
#pragma unroll
        for (int i = 0; i < 8; i++) c |= sbits[t + i];
        unsigned cq = c & 0xFFu, ck = (c >> 8) & 0xFFu;
        cq ^= cq >> 1;                   // Gray permutation
        ck ^= ck >> 1;
        size_t o = (size_t)(b * NHEAD + (t >> 3)) * S_LEN + s;
        g_qh[o] = (unsigned char)cq;
        g_kh[o] = (unsigned char)ck;
    }
}

// ---------------------------------------------------------------------------
// Kernel 2: stable counting sort of 4096 8-bit keys per (b,h). Unchanged.
// ---------------------------------------------------------------------------
__global__ void hyper_sort_kernel()
{
    int bh    = blockIdx.x;
    int which = blockIdx.y;
    const unsigned int* hw =
        (const unsigned int*)((which ? g_kh : g_qh) + (size_t)bh * S_LEN);
    int* idx = (which ? g_kidx : g_qidx) + (size_t)bh * S_LEN;

    __shared__ unsigned int w[1024];
    __shared__ int scan[256];
    int t = threadIdx.x;
#pragma unroll
    for (int i = 0; i < 4; i++) w[t + i * 256] = hw[t + i * 256];
    __syncthreads();

    unsigned k4 = t * 0x01010101u;
    int cnt = 0;
#pragma unroll 4
    for (int i = 0; i < 1024; i++) cnt += __popc(__vcmpeq4(w[i], k4));
    cnt >>= 3;

    scan[t] = cnt;
    __syncthreads();
    for (int off = 1; off < 256; off <<= 1) {
        int v = (t >= off) ? scan[t - off] : 0;
        __syncthreads();
        scan[t] += v;
        __syncthreads();
    }
    int pos = scan[t] - cnt;

    for (int i = 0; i < 1024; i++) {
        unsigned m = __vcmpeq4(w[i], k4);
        if (m) {
            int base = i * 4;
            if (m & 0x000000FFu) idx[pos++] = base;
            if (m & 0x0000FF00u) idx[pos++] = base + 1;
            if (m & 0x00FF0000u) idx[pos++] = base + 2;
            if (m & 0xFF000000u) idx[pos++] = base + 3;
        }
    }
}

// ---------------------------------------------------------------------------
// Kernel 3: fused attention, 256 threads, cp.async double-buffered tiles,
// fp16 MMAs: S = qh * (Khi + Klo);  O += ph * (Vhi + Vlo).
// Dynamic smem: 2 buffers x 4 comps x 64 rows x 128 B = 64 KB.
// ---------------------------------------------------------------------------
extern __shared__ __align__(16) unsigned char dyn_smem[];

__global__ void __launch_bounds__(256, 2)
hyper_attn_kernel(const float* __restrict__ qkv,
                  const int*   __restrict__ sampled,
                  float*       __restrict__ out)
{
    __shared__ int   ssq[128];
    __shared__ int   ssrc_all[256];
    __shared__ float sbias_all[256];

    unsigned sbase = (unsigned)__cvta_generic_to_shared(dyn_smem);

    int g = blockIdx.x, h = blockIdx.y, b = blockIdx.z;
    int bh = b * NHEAD + h;
    int t  = threadIdx.x;
    int w  = t >> 5, l = t & 31;
    int lg = l >> 2, lq = l & 3;
    int m8 = l >> 3, r8 = l & 7;

    if (t < 128) ssq[t] = g_qidx[(size_t)bh * S_LEN + g * BLK + t];
    {   // all 4 chunks' key lists + biases in one pass
        int c = t >> 6, j = t & 63;
        int pos; float bias;
        if (c < 2) { pos = g * BLK + c * 64 + j; bias = 0.f; }
        else {
            pos  = sampled[bh * NSAMP + (c - 2) * 64 + j];
            bias = ((pos >> 7) == g) ? -1e30f : 5.0f;   // log2(n/m) = 5
        }
        ssrc_all[t]  = g_kidx[(size_t)bh * S_LEN + pos];
        sbias_all[t] = bias;
    }
    __syncthreads();

#define FILL_CHUNK(cc, bb)                                                    \
    {                                                                         \
        _Pragma("unroll")                                                     \
        for (int i = 0; i < 8; i++) {                                         \
            int lin = t + i * 256;                                            \
            int comp = lin >> 9, rowg = lin & 511;                            \
            int rr = rowg >> 3, gg = rowg & 7;                                \
            int srow = ssrc_all[(cc) * 64 + rr];                              \
            const void* sp = g_pack + (size_t)comp * COMP_BYTES               \
                             + (((size_t)bh) * S_LEN + srow) * 128 + gg * 16; \
            unsigned dp = sbase + (bb) * 32768 + comp * 8192 + rr * 128       \
                          + ((gg ^ (rr & 7)) << 4);                           \
            cp16(dp, sp);                                                     \
        }                                                                     \
        cp_commit();                                                          \
    }
    FILL_CHUNK(0, 0);

    // ---- Q fragments (single fp16, 16 rows per warp), scale folded ----
    const float qs = 0.125f * LOG2E;
    unsigned qf[4][4];
    {
        int rA = w * 16 + lg;
        const float* qa = qkv + (size_t)(b * S_LEN + ssq[rA])     * 3072 + h * 64;
        const float* qb = qkv + (size_t)(b * S_LEN + ssq[rA + 8]) * 3072 + h * 64;
#pragma unroll
        for (int ks = 0; ks < 4; ks++) {
            int c0 = ks * 16 + lq * 2;
            float2 xa0 = *(const float2*)(qa + c0);
            float2 xb0 = *(const float2*)(qb + c0);
            float2 xa1 = *(const float2*)(qa + c0 + 8);
            float2 xb1 = *(const float2*)(qb + c0 + 8);
            qf[ks][0] = pack_h2(xa0.x * qs, xa0.y * qs);
            qf[ks][1] = pack_h2(xb0.x * qs, xb0.y * qs);
            qf[ks][2] = pack_h2(xa1.x * qs, xa1.y * qs);
            qf[ks][3] = pack_h2(xb1.x * qs, xb1.y * qs);
        }
    }

    float o[8][4];
#pragma unroll
    for (int nt = 0; nt < 8; nt++)
#pragma unroll
        for (int q4 = 0; q4 < 4; q4++) o[nt][q4] = 0.f;
    float mrow[2] = {-1e30f, -1e30f};
    float lrow[2] = {0.f, 0.f};

#pragma unroll
    for (int c = 0; c < 4; c++) {
        if (c < 3) { FILL_CHUNK(c + 1, (c + 1) & 1); cp_wait<1>(); }
        else       { cp_wait<0>(); }
        __syncthreads();

        unsigned tb  = sbase + (c & 1) * 32768;
        unsigned khb = tb, klb = tb + 8192, vhb = tb + 16384, vlb = tb + 24576;

        // ---- S = qh*(Khi+Klo) + bias ----
        float s[8][4];
#pragma unroll
        for (int nt = 0; nt < 8; nt++) {
            float2 bv = *(const float2*)(sbias_all + c * 64 + nt * 8 + lq * 2);
            s[nt][0] = bv.x; s[nt][1] = bv.y;
            s[nt][2] = bv.x; s[nt][3] = bv.y;
        }
#pragma unroll
        for (int ks = 0; ks < 4; ks++) {
#pragma unroll
            for (int ntp = 0; ntp < 4; ntp++) {
                int key  = (2 * ntp + (m8 >> 1)) * 8 + r8;
                int gidx = ks * 2 + (m8 & 1);
                unsigned off = (unsigned)(key * 128 + ((gidx ^ (key & 7)) << 4));
                unsigned kh0, kh1, kh2, kh3, kl0, kl1, kl2, kl3;
                ldsm_x4(kh0, kh1, kh2, kh3, khb + off);
                ldsm_x4(kl0, kl1, kl2, kl3, klb + off);
                MMAH(s[2*ntp],   qf[ks][0],qf[ks][1],qf[ks][2],qf[ks][3], kh0,kh1);
                MMAH(s[2*ntp],   qf[ks][0],qf[ks][1],qf[ks][2],qf[ks][3], kl0,kl1);
                MMAH(s[2*ntp+1], qf[ks][0],qf[ks][1],qf[ks][2],qf[ks][3], kh2,kh3);
                MMAH(s[2*ntp+1], qf[ks][0],qf[ks][1],qf[ks][2],qf[ks][3], kl2,kl3);
            }
        }

        // ---- online softmax (base-2), s becomes P ----
#pragma unroll
        for (int hh = 0; hh < 2; hh++) {
            float cm = -1e30f;
#pragma unroll
            for (int nt = 0; nt < 8; nt++)
                cm = fmaxf(cm, fmaxf(s[nt][2*hh], s[nt][2*hh+1]));
            cm = fmaxf(cm, __shfl_xor_sync(0xFFFFFFFFu, cm, 1));
            cm = fmaxf(cm, __shfl_xor_sync(0xFFFFFFFFu, cm, 2));
            float nm  = fmaxf(mrow[hh], cm);
            float fsc = fast_exp2(mrow[hh] - nm);
            mrow[hh]  = nm;
            float ls = 0.f;
#pragma unroll
            for (int nt = 0; nt < 8; nt++) {
                float p0 = fast_exp2(s[nt][2*hh]     - nm);
                float p1 = fast_exp2(s[nt][2*hh + 1] - nm);
                s[nt][2*hh] = p0; s[nt][2*hh+1] = p1;
                ls += p0 + p1;
            }
            ls += __shfl_xor_sync(0xFFFFFFFFu, ls, 1);
            ls += __shfl_xor_sync(0xFFFFFFFFu, ls, 2);
            lrow[hh] = lrow[hh] * fsc + ls;
#pragma unroll
            for (int nt = 0; nt < 8; nt++) {
                o[nt][2*hh]     *= fsc;
                o[nt][2*hh + 1] *= fsc;
            }
        }

        // ---- O += ph*(Vhi+Vlo) ----
#pragma unroll
        for (int kap = 0; kap < 4; kap++) {
            unsigned ph[4];
            ph[0] = pack_h2(s[2*kap][0],   s[2*kap][1]);
            ph[1] = pack_h2(s[2*kap][2],   s[2*kap][3]);
            ph[2] = pack_h2(s[2*kap+1][0], s[2*kap+1][1]);
            ph[3] = pack_h2(s[2*kap+1][2], s[2*kap+1][3]);
#pragma unroll
            for (int ntdp = 0; ntdp < 4; ntdp++) {
                int key  = kap * 16 + (m8 & 1) * 8 + r8;
                int gidx = ntdp * 2 + (m8 >> 1);
                unsigned off = (unsigned)(key * 128 + ((gidx ^ (key & 7)) << 4));
                unsigned vh0, vh1, vh2, vh3, vl0, vl1, vl2, vl3;
                ldsm_x4_t(vh0, vh1, vh2, vh3, vhb + off);
                ldsm_x4_t(vl0, vl1, vl2, vl3, vlb + off);
                MMAH(o[2*ntdp],   ph[0],ph[1],ph[2],ph[3], vh0,vh1);
                MMAH(o[2*ntdp],   ph[0],ph[1],ph[2],ph[3], vl0,vl1);
                MMAH(o[2*ntdp+1], ph[0],ph[1],ph[2],ph[3], vh2,vh3);
                MMAH(o[2*ntdp+1], ph[0],ph[1],ph[2],ph[3], vl2,vl3);
            }
        }
        __syncthreads();   // buffer (c&1) reused by fill at next iteration
    }

    // ---- normalize + scatter back to original query order ----
#pragma unroll
    for (int hh = 0; hh < 2; hh++) {
        float inv = 1.0f / lrow[hh];
        int row = w * 16 + hh * 8 + lg;
        float* op = out + ((size_t)(b * S_LEN + ssq[row]) * NHEAD + h) * 64;
#pragma unroll
        for (int nt = 0; nt < 8; nt++) {
            float2 v;
            v.x = o[nt][2*hh]     * inv;
            v.y = o[nt][2*hh + 1] * inv;
            *(float2*)(op + nt * 8 + lq * 2) = v;
        }
    }
}

// ---------------------------------------------------------------------------
extern "C" void kernel_launch(void* const* d_in, const int* in_sizes, int n_in,
                              void* d_out, int out_size)
{
    const float* qkv     = (const float*)d_in[0];   // [2,4096,3,16,64] f32
    const float* proj    = (const float*)d_in[1];   // [64,8] f32
    const int*   sampled = (const int*)d_in[2];     // [2,16,128] i32
    float*       out     = (float*)d_out;           // [2,4096,16,64] f32

    cudaFuncSetAttribute(hyper_attn_kernel,
                         cudaFuncAttributeMaxDynamicSharedMemorySize, 65536);

    hyper_hash_pack_kernel<<<NBATCH * S_LEN, 256>>>(qkv, proj);
    hyper_sort_kernel<<<dim3(NBH, 2), 256>>>();
    hyper_attn_kernel<<<dim3(NBLK, NHEAD, NBATCH), 256, 65536>>>(qkv, sampled, out);
}

// round 12
// speedup vs baseline: 2.8533x; 1.0657x over previous
#include <cuda_runtime.h>
#include <cuda_fp16.h>

// Problem constants (fixed shapes)
#define S_LEN  4096
#define NHEAD  16
#define NBATCH 2
#define NBH    (NBATCH*NHEAD)
#define BLK    128
#define NBLK   32
#define NSAMP  128
#define LOG2E  1.4426950408889634f
#define COMP_BYTES ((size_t)NBH * S_LEN * 128)   // one packed component
#define BUFB   24576                             // smem bytes per chunk buffer

// ---------------- scratch (no cudaMalloc allowed) ----------------
__device__ __align__(16) unsigned char g_qh[NBH*S_LEN];
__device__ __align__(16) unsigned char g_kh[NBH*S_LEN];
__device__ int g_qidx[NBH*S_LEN];
__device__ int g_kidx[NBH*S_LEN];
// packed K/V rows (fp16): [comp(k, vhi, vlo)][bh][token][128B]
__device__ __align__(128) unsigned char g_pack[3 * NBH * S_LEN * 128];

__device__ __forceinline__ float fast_exp2(float x)
{
    float r;
    asm("ex2.approx.f32 %0, %1;" : "=f"(r) : "f"(x));
    return r;
}

// fp16 hi/lo split of an fp32 pair, packed as b32 (x in low half).
__device__ __forceinline__ void split2f(float x, float y,
                                        unsigned& hi, unsigned& lo)
{
    __half hx = __float2half_rn(x), hy = __float2half_rn(y);
    float  fx = __half2float(hx),  fy = __half2float(hy);
    __half lx = __float2half_rn(x - fx), ly = __float2half_rn(y - fy);
    hi = (unsigned)__half_as_ushort(hx) | ((unsigned)__half_as_ushort(hy) << 16);
    lo = (unsigned)__half_as_ushort(lx) | ((unsigned)__half_as_ushort(ly) << 16);
}

// fp32 pair -> packed fp16x2
__device__ __forceinline__ unsigned pack_h2(float x, float y)
{
    __half2 h = __floats2half2_rn(x, y);
    return *reinterpret_cast<unsigned*>(&h);
}

#define MMAH(c, a0,a1,a2,a3, b0,b1) \
  asm volatile("mma.sync.aligned.m16n8k16.row.col.f32.f16.f16.f32 " \
    "{%0,%1,%2,%3}, {%4,%5,%6,%7}, {%8,%9}, {%0,%1,%2,%3};" \
    : "+f"((c)[0]), "+f"((c)[1]), "+f"((c)[2]), "+f"((c)[3]) \
    : "r"(a0), "r"(a1), "r"(a2), "r"(a3), "r"(b0), "r"(b1))

__device__ __forceinline__ void ldsm_x4(unsigned& r0, unsigned& r1,
                                        unsigned& r2, unsigned& r3,
                                        unsigned addr)
{
    asm volatile("ldmatrix.sync.aligned.m8n8.x4.shared.b16 {%0,%1,%2,%3}, [%4];"
                 : "=r"(r0), "=r"(r1), "=r"(r2), "=r"(r3) : "r"(addr));
}
__device__ __forceinline__ void ldsm_x4_t(unsigned& r0, unsigned& r1,
                                          unsigned& r2, unsigned& r3,
                                          unsigned addr)
{
    asm volatile("ldmatrix.sync.aligned.m8n8.x4.trans.shared.b16 {%0,%1,%2,%3}, [%4];"
                 : "=r"(r0), "=r"(r1), "=r"(r2), "=r"(r3) : "r"(addr));
}

__device__ __forceinline__ void cp16(unsigned dst, const void* src)
{
    asm volatile("cp.async.cg.shared.global [%0], [%1], 16;"
                 :: "r"(dst), "l"(src) : "memory");
}
__device__ __forceinline__ void cp_commit()
{ asm volatile("cp.async.commit_group;" ::: "memory"); }
template<int N> __device__ __forceinline__ void cp_wait()
{ asm volatile("cp.async.wait_group %0;" :: "n"(N) : "memory"); }

// ---------------------------------------------------------------------------
// Kernel 1: LSH hash + K(fp16)/V(fp16 hi/lo) pre-pack. One CTA per (b,s).
// ---------------------------------------------------------------------------
__global__ void __launch_bounds__(256)
hyper_hash_pack_kernel(const float* __restrict__ qkv,
                       const float* __restrict__ proj)
{
    __shared__ float spT[8 * 68];
    __shared__ float row[32 * 68];       // 16 q rows then 16 k rows, padded
    __shared__ unsigned int sbits[128];

    int t  = threadIdx.x;                // 0..255
    int bs = blockIdx.x;                 // b*4096 + s
    int b  = bs >> 12;
    int s  = bs & (S_LEN - 1);
    int hh = t >> 4, dg = t & 15;        // pack assignment: head, 4-float group

    float4 vvec = *(const float4*)(qkv + (size_t)bs * 3072 + 2048
                                   + hh * 64 + dg * 4);

    if (t < 64) {
        const float* pr = proj + t * 8;
#pragma unroll
        for (int r = 0; r < 8; r++) spT[r * 68 + t] = pr[r];
    }
    const float4* src = (const float4*)(qkv + (size_t)bs * 3072); // q+k = 512 f4
    float4* dst = (float4*)row;
#pragma unroll
    for (int i = 0; i < 2; i++) {
        int f = t + i * 256;
        dst[(f >> 4) * 17 + (f & 15)] = src[f];
    }
    __syncthreads();

    // ---- pack K (single fp16) and V (fp16 hi/lo) into g_pack ----
    {
        float4 kvec = *(const float4*)(row + (16 + hh) * 68 + dg * 4);
        int bh = b * NHEAD + hh;
        size_t rb = (((size_t)bh) * S_LEN + s) * 128 + dg * 8;
        unsigned k0 = pack_h2(kvec.x, kvec.y);
        unsigned k1 = pack_h2(kvec.z, kvec.w);
        *(uint2*)(g_pack + 0 * COMP_BYTES + rb) = make_uint2(k0, k1);
        unsigned h0, l0, h1, l1;
        split2f(vvec.x, vvec.y, h0, l0); split2f(vvec.z, vvec.w, h1, l1);
        *(uint2*)(g_pack + 1 * COMP_BYTES + rb) = make_uint2(h0, h1);
        *(uint2*)(g_pack + 2 * COMP_BYTES + rb) = make_uint2(l0, l1);
    }

    // ---- hash: threads 0..127 = (head, projection) ----
    if (t < 128) {
        int h = t >> 3, r = t & 7;
        const float4* xq = (const float4*)(row + h * 68);
        const float4* xk = (const float4*)(row + (16 + h) * 68);
        const float4* pp = (const float4*)(spT + r * 68);
        float dq = 0.f, dk = 0.f;
#pragma unroll
        for (int i = 0; i < 16; i++) {
            float4 p4 = pp[i];
            float4 a  = xq[i];
            float4 c  = xk[i];
            dq += a.x*p4.x + a.y*p4.y + a.z*p4.z + a.w*p4.w;
            dk += c.x*p4.x + c.y*p4.y + c.z*p4.z + c.w*p4.w;
        }
        unsigned bq = (dq > 0.f) ? (1u << r) : 0u;
        unsigned bk = (dk > 0.f) ? (1u << r) : 0u;
        sbits[t] = bq | (bk << 8);
    }
    __syncthreads();
    if (t < 128 && (t & 7) == 0) {
        unsigned c = 0;
#pragma unroll
        for (int i = 0; i < 8; i++) c |= sbits[t + i];
        unsigned cq = c & 0xFFu, ck = (c >> 8) & 0xFFu;
        cq ^= cq >> 1;                   // Gray permutation
        ck ^= ck >> 1;
        size_t o = (size_t)(b * NHEAD + (t >> 3)) * S_LEN + s;
        g_qh[o] = (unsigned char)cq;
        g_kh[o] = (unsigned char)ck;
    }
}

// ---------------------------------------------------------------------------
// Kernel 2: stable counting sort of 4096 8-bit keys per (b,h). Unchanged.
// ---------------------------------------------------------------------------
__global__ void hyper_sort_kernel()
{
    int bh    = blockIdx.x;
    int which = blockIdx.y;
    const unsigned int* hw =
        (const unsigned int*)((which ? g_kh : g_qh) + (size_t)bh * S_LEN);
    int* idx = (which ? g_kidx : g_qidx) + (size_t)bh * S_LEN;

    __shared__ unsigned int w[1024];
    __shared__ int scan[256];
    int t = threadIdx.x;
#pragma unroll
    for (int i = 0; i < 4; i++) w[t + i * 256] = hw[t + i * 256];
    __syncthreads();

    unsigned k4 = t * 0x01010101u;
    int cnt = 0;
#pragma unroll 4
    for (int i = 0; i < 1024; i++) cnt += __popc(__vcmpeq4(w[i], k4));
    cnt >>= 3;

    scan[t] = cnt;
    __syncthreads();
    for (int off = 1; off < 256; off <<= 1) {
        int v = (t >= off) ? scan[t - off] : 0;
        __syncthreads();
        scan[t] += v;
        __syncthreads();
    }
    int pos = scan[t] - cnt;

    for (int i = 0; i < 1024; i++) {
        unsigned m = __vcmpeq4(w[i], k4);
        if (m) {
            int base = i * 4;
            if (m & 0x000000FFu) idx[pos++] = base;
            if (m & 0x0000FF00u) idx[pos++] = base + 1;
            if (m & 0x00FF0000u) idx[pos++] = base + 2;
            if (m & 0xFF000000u) idx[pos++] = base + 3;
        }
    }
}

// ---------------------------------------------------------------------------
// Kernel 3: fused attention, 256 threads, cp.async double-buffered tiles,
// fp16 MMAs: S = qh * K;  O += ph * (Vhi + Vlo).
// Dynamic smem: 2 buffers x 3 comps x 64 rows x 128 B = 48 KB.
// ---------------------------------------------------------------------------
extern __shared__ __align__(16) unsigned char dyn_smem[];

__global__ void __launch_bounds__(256, 2)
hyper_attn_kernel(const float* __restrict__ qkv,
                  const int*   __restrict__ sampled,
                  float*       __restrict__ out)
{
    __shared__ int   ssq[128];
    __shared__ int   ssrc_all[256];
    __shared__ float sbias_all[256];

    unsigned sbase = (unsigned)__cvta_generic_to_shared(dyn_smem);

    int g = blockIdx.x, h = blockIdx.y, b = blockIdx.z;
    int bh = b * NHEAD + h;
    int t  = threadIdx.x;
    int w  = t >> 5, l = t & 31;
    int lg = l >> 2, lq = l & 3;
    int m8 = l >> 3, r8 = l & 7;

    if (t < 128) ssq[t] = g_qidx[(size_t)bh * S_LEN + g * BLK + t];
    {   // all 4 chunks' key lists + biases in one pass
        int c = t >> 6, j = t & 63;
        int pos; float bias;
        if (c < 2) { pos = g * BLK + c * 64 + j; bias = 0.f; }
        else {
            pos  = sampled[bh * NSAMP + (c - 2) * 64 + j];
            bias = ((pos >> 7) == g) ? -1e30f : 5.0f;   // log2(n/m) = 5
        }
        ssrc_all[t]  = g_kidx[(size_t)bh * S_LEN + pos];
        sbias_all[t] = bias;
    }
    __syncthreads();

// 3 comps x 64 rows x 8 groups = 1536 cp16 per chunk = 6 per thread
#define FILL_CHUNK(cc, bb)                                                    \
    {                                                                         \
        _Pragma("unroll")                                                     \
        for (int i = 0; i < 6; i++) {                                         \
            int lin = t + i * 256;                                            \
            int comp = lin >> 9, rowg = lin & 511;                            \
            int rr = rowg >> 3, gg = rowg & 7;                                \
            int srow = ssrc_all[(cc) * 64 + rr];                              \
            const void* sp = g_pack + (size_t)comp * COMP_BYTES               \
                             + (((size_t)bh) * S_LEN + srow) * 128 + gg * 16; \
            unsigned dp = sbase + (bb) * BUFB + comp * 8192 + rr * 128        \
                          + ((gg ^ (rr & 7)) << 4);                           \
            cp16(dp, sp);                                                     \
        }                                                                     \
        cp_commit();                                                          \
    }
    FILL_CHUNK(0, 0);

    // ---- Q fragments (single fp16, 16 rows per warp), scale folded ----
    const float qs = 0.125f * LOG2E;
    unsigned qf[4][4];
    {
        int rA = w * 16 + lg;
        const float* qa = qkv + (size_t)(b * S_LEN + ssq[rA])     * 3072 + h * 64;
        const float* qb = qkv + (size_t)(b * S_LEN + ssq[rA + 8]) * 3072 + h * 64;
#pragma unroll
        for (int ks = 0; ks < 4; ks++) {
            int c0 = ks * 16 + lq * 2;
            float2 xa0 = *(const float2*)(qa + c0);
            float2 xb0 = *(const float2*)(qb + c0);
            float2 xa1 = *(const float2*)(qa + c0 + 8);
            float2 xb1 = *(const float2*)(qb + c0 + 8);
            qf[ks][0] = pack_h2(xa0.x * qs, xa0.y * qs);
            qf[ks][1] = pack_h2(xb0.x * qs, xb0.y * qs);
            qf[ks][2] = pack_h2(xa1.x * qs, xa1.y * qs);
            qf[ks][3] = pack_h2(xb1.x * qs, xb1.y * qs);
        }
    }

    float o[8][4];
#pragma unroll
    for (int nt = 0; nt < 8; nt++)
#pragma unroll
        for (int q4 = 0; q4 < 4; q4++) o[nt][q4] = 0.f;
    float mrow[2] = {-1e30f, -1e30f};
    float lrow[2] = {0.f, 0.f};

#pragma unroll
    for (int c = 0; c < 4; c++) {
        if (c < 3) { FILL_CHUNK(c + 1, (c + 1) & 1); cp_wait<1>(); }
        else       { cp_wait<0>(); }
        __syncthreads();

        unsigned tb  = sbase + (c & 1) * BUFB;
        unsigned kb  = tb, vhb = tb + 8192, vlb = tb + 16384;

        // ---- S = qh*K + bias ----
        float s[8][4];
#pragma unroll
        for (int nt = 0; nt < 8; nt++) {
            float2 bv = *(const float2*)(sbias_all + c * 64 + nt * 8 + lq * 2);
            s[nt][0] = bv.x; s[nt][1] = bv.y;
            s[nt][2] = bv.x; s[nt][3] = bv.y;
        }
#pragma unroll
        for (int ks = 0; ks < 4; ks++) {
#pragma unroll
            for (int ntp = 0; ntp < 4; ntp++) {
                int key  = (2 * ntp + (m8 >> 1)) * 8 + r8;
                int gidx = ks * 2 + (m8 & 1);
                unsigned off = (unsigned)(key * 128 + ((gidx ^ (key & 7)) << 4));
                unsigned kh0, kh1, kh2, kh3;
                ldsm_x4(kh0, kh1, kh2, kh3, kb + off);
                MMAH(s[2*ntp],   qf[ks][0],qf[ks][1],qf[ks][2],qf[ks][3], kh0,kh1);
                MMAH(s[2*ntp+1], qf[ks][0],qf[ks][1],qf[ks][2],qf[ks][3], kh2,kh3);
            }
        }

        // ---- online softmax (base-2), s becomes P ----
#pragma unroll
        for (int hh = 0; hh < 2; hh++) {
            float cm = -1e30f;
#pragma unroll
            for (int nt = 0; nt < 8; nt++)
                cm = fmaxf(cm, fmaxf(s[nt][2*hh], s[nt][2*hh+1]));
            cm = fmaxf(cm, __shfl_xor_sync(0xFFFFFFFFu, cm, 1));
            cm = fmaxf(cm, __shfl_xor_sync(0xFFFFFFFFu, cm, 2));
            float nm  = fmaxf(mrow[hh], cm);
            float fsc = fast_exp2(mrow[hh] - nm);
            mrow[hh]  = nm;
            float ls = 0.f;
#pragma unroll
            for (int nt = 0; nt < 8; nt++) {
                float p0 = fast_exp2(s[nt][2*hh]     - nm);
                float p1 = fast_exp2(s[nt][2*hh + 1] - nm);
                s[nt][2*hh] = p0; s[nt][2*hh+1] = p1;
                ls += p0 + p1;
            }
            ls += __shfl_xor_sync(0xFFFFFFFFu, ls, 1);
            ls += __shfl_xor_sync(0xFFFFFFFFu, ls, 2);
            lrow[hh] = lrow[hh] * fsc + ls;
#pragma unroll
            for (int nt = 0; nt < 8; nt++) {
                o[nt][2*hh]     *= fsc;
                o[nt][2*hh + 1] *= fsc;
            }
        }

        // ---- O += ph*(Vhi+Vlo) ----
#pragma unroll
        for (int kap = 0; kap < 4; kap++) {
            unsigned ph[4];
            ph[0] = pack_h2(s[2*kap][0],   s[2*kap][1]);
            ph[1] = pack_h2(s[2*kap][2],   s[2*kap][3]);
            ph[2] = pack_h2(s[2*kap+1][0], s[2*kap+1][1]);
            ph[3] = pack_h2(s[2*kap+1][2], s[2*kap+1][3]);
#pragma unroll
            for (int ntdp = 0; ntdp < 4; ntdp++) {
                int key  = kap * 16 + (m8 & 1) * 8 + r8;
                int gidx = ntdp * 2 + (m8 >> 1);
                unsigned off = (unsigned)(key * 128 + ((gidx ^ (key & 7)) << 4));
                unsigned vh0, vh1, vh2, vh3, vl0, vl1, vl2, vl3;
                ldsm_x4_t(vh0, vh1, vh2, vh3, vhb + off);
                ldsm_x4_t(vl0, vl1, vl2, vl3, vlb + off);
                MMAH(o[2*ntdp],   ph[0],ph[1],ph[2],ph[3], vh0,vh1);
                MMAH(o[2*ntdp],   ph[0],ph[1],ph[2],ph[3], vl0,vl1);
                MMAH(o[2*ntdp+1], ph[0],ph[1],ph[2],ph[3], vh2,vh3);
                MMAH(o[2*ntdp+1], ph[0],ph[1],ph[2],ph[3], vl2,vl3);
            }
        }
        __syncthreads();   // buffer (c&1) reused by fill at next iteration
    }

    // ---- normalize + scatter back to original query order ----
#pragma unroll
    for (int hh = 0; hh < 2; hh++) {
        float inv = 1.0f / lrow[hh];
        int row = w * 16 + hh * 8 + lg;
        float* op = out + ((size_t)(b * S_LEN + ssq[row]) * NHEAD + h) * 64;
#pragma unroll
        for (int nt = 0; nt < 8; nt++) {
            float2 v;
            v.x = o[nt][2*hh]     * inv;
            v.y = o[nt][2*hh + 1] * inv;
            *(float2*)(op + nt * 8 + lq * 2) = v;
        }
    }
}

// ---------------------------------------------------------------------------
extern "C" void kernel_launch(void* const* d_in, const int* in_sizes, int n_in,
                              void* d_out, int out_size)
{
    const float* qkv     = (const float*)d_in[0];   // [2,4096,3,16,64] f32
    const float* proj    = (const float*)d_in[1];   // [64,8] f32
    const int*   sampled = (const int*)d_in[2];     // [2,16,128] i32
    float*       out     = (float*)d_out;           // [2,4096,16,64] f32

    cudaFuncSetAttribute(hyper_attn_kernel,
                         cudaFuncAttributeMaxDynamicSharedMemorySize, 49152);

    hyper_hash_pack_kernel<<<NBATCH * S_LEN, 256>>>(qkv, proj);
    hyper_sort_kernel<<<dim3(NBH, 2), 256>>>();
    hyper_attn_kernel<<<dim3(NBLK, NHEAD, NBATCH), 256, 49152>>>(qkv, sampled, out);
}

// round 13
// speedup vs baseline: 3.0923x; 1.0837x over previous
#include <cuda_runtime.h>
#include <cuda_fp16.h>

// Problem constants (fixed shapes)
#define S_LEN  4096
#define NHEAD  16
#define NBATCH 2
#define NBH    (NBATCH*NHEAD)
#define BLK    128
#define NBLK   32
#define NSAMP  128
#define LOG2E  1.4426950408889634f
#define COMP_BYTES ((size_t)NBH * S_LEN * 128)   // one packed component
#define BUFB   16384                             // smem bytes per chunk buffer

// ---------------- scratch (no cudaMalloc allowed) ----------------
__device__ __align__(16) unsigned char g_qh[NBH*S_LEN];
__device__ __align__(16) unsigned char g_kh[NBH*S_LEN];
__device__ int g_qidx[NBH*S_LEN];
__device__ int g_kidx[NBH*S_LEN];
// packed K/V rows (fp16): [comp(k, v)][bh][token][128B]
__device__ __align__(128) unsigned char g_pack[2 * NBH * S_LEN * 128];

__device__ __forceinline__ float fast_exp2(float x)
{
    float r;
    asm("ex2.approx.f32 %0, %1;" : "=f"(r) : "f"(x));
    return r;
}

// fp32 pair -> packed fp16x2
__device__ __forceinline__ unsigned pack_h2(float x, float y)
{
    __half2 h = __floats2half2_rn(x, y);
    return *reinterpret_cast<unsigned*>(&h);
}

#define MMAH(c, a0,a1,a2,a3, b0,b1) \
  asm volatile("mma.sync.aligned.m16n8k16.row.col.f32.f16.f16.f32 " \
    "{%0,%1,%2,%3}, {%4,%5,%6,%7}, {%8,%9}, {%0,%1,%2,%3};" \
    : "+f"((c)[0]), "+f"((c)[1]), "+f"((c)[2]), "+f"((c)[3]) \
    : "r"(a0), "r"(a1), "r"(a2), "r"(a3), "r"(b0), "r"(b1))

__device__ __forceinline__ void ldsm_x4(unsigned& r0, unsigned& r1,
                                        unsigned& r2, unsigned& r3,
                                        unsigned addr)
{
    asm volatile("ldmatrix.sync.aligned.m8n8.x4.shared.b16 {%0,%1,%2,%3}, [%4];"
                 : "=r"(r0), "=r"(r1), "=r"(r2), "=r"(r3) : "r"(addr));
}
__device__ __forceinline__ void ldsm_x4_t(unsigned& r0, unsigned& r1,
                                          unsigned& r2, unsigned& r3,
                                          unsigned addr)
{
    asm volatile("ldmatrix.sync.aligned.m8n8.x4.trans.shared.b16 {%0,%1,%2,%3}, [%4];"
                 : "=r"(r0), "=r"(r1), "=r"(r2), "=r"(r3) : "r"(addr));
}

__device__ __forceinline__ void cp16(unsigned dst, const void* src)
{
    asm volatile("cp.async.cg.shared.global [%0], [%1], 16;"
                 :: "r"(dst), "l"(src) : "memory");
}
__device__ __forceinline__ void cp_commit()
{ asm volatile("cp.async.commit_group;" ::: "memory"); }
template<int N> __device__ __forceinline__ void cp_wait()
{ asm volatile("cp.async.wait_group %0;" :: "n"(N) : "memory"); }

// ---------------------------------------------------------------------------
// Kernel 1: LSH hash + K/V fp16 pre-pack. One CTA per (b,s), 256 threads.
// ---------------------------------------------------------------------------
__global__ void __launch_bounds__(256)
hyper_hash_pack_kernel(const float* __restrict__ qkv,
                       const float* __restrict__ proj)
{
    __shared__ float spT[8 * 68];
    __shared__ float row[32 * 68];       // 16 q rows then 16 k rows, padded
    __shared__ unsigned int sbits[128];

    int t  = threadIdx.x;                // 0..255
    int bs = blockIdx.x;                 // b*4096 + s
    int b  = bs >> 12;
    int s  = bs & (S_LEN - 1);
    int hh = t >> 4, dg = t & 15;        // pack assignment: head, 4-float group

    float4 vvec = *(const float4*)(qkv + (size_t)bs * 3072 + 2048
                                   + hh * 64 + dg * 4);

    if (t < 64) {
        const float* pr = proj + t * 8;
#pragma unroll
        for (int r = 0; r < 8; r++) spT[r * 68 + t] = pr[r];
    }
    const float4* src = (const float4*)(qkv + (size_t)bs * 3072); // q+k = 512 f4
    float4* dst = (float4*)row;
#pragma unroll
    for (int i = 0; i < 2; i++) {
        int f = t + i * 256;
        dst[(f >> 4) * 17 + (f & 15)] = src[f];
    }
    __syncthreads();

    // ---- pack K and V (single fp16 each) into g_pack ----
    {
        float4 kvec = *(const float4*)(row + (16 + hh) * 68 + dg * 4);
        int bh = b * NHEAD + hh;
        size_t rb = (((size_t)bh) * S_LEN + s) * 128 + dg * 8;
        unsigned k0 = pack_h2(kvec.x, kvec.y);
        unsigned k1 = pack_h2(kvec.z, kvec.w);
        *(uint2*)(g_pack + 0 * COMP_BYTES + rb) = make_uint2(k0, k1);
        unsigned v0 = pack_h2(vvec.x, vvec.y);
        unsigned v1 = pack_h2(vvec.z, vvec.w);
        *(uint2*)(g_pack + 1 * COMP_BYTES + rb) = make_uint2(v0, v1);
    }

    // ---- hash: threads 0..127 = (head, projection) ----
    if (t < 128) {
        int h = t >> 3, r = t & 7;
        const float4* xq = (const float4*)(row + h * 68);
        const float4* xk = (const float4*)(row + (16 + h) * 68);
        const float4* pp = (const float4*)(spT + r * 68);
        float dq = 0.f, dk = 0.f;
#pragma unroll
        for (int i = 0; i < 16; i++) {
            float4 p4 = pp[i];
            float4 a  = xq[i];
            float4 c  = xk[i];
            dq += a.x*p4.x + a.y*p4.y + a.z*p4.z + a.w*p4.w;
            dk += c.x*p4.x + c.y*p4.y + c.z*p4.z + c.w*p4.w;
        }
        unsigned bq = (dq > 0.f) ? (1u << r) : 0u;
        unsigned bk = (dk > 0.f) ? (1u << r) : 0u;
        sbits[t] = bq | (bk << 8);
    }
    __syncthreads();
    if (t < 128 && (t & 7) == 0) {
        unsigned c = 0;
#pragma unroll
        for (int i = 0; i < 8; i++) c |= sbits[t + i];
        unsigned cq = c & 0xFFu, ck = (c >> 8) & 0xFFu;
        cq ^= cq >> 1;                   // Gray permutation
        ck ^= ck >> 1;
        size_t o = (size_t)(b * NHEAD + (t >> 3)) * S_LEN + s;
        g_qh[o] = (unsigned char)cq;
        g_kh[o] = (unsigned char)ck;
    }
}

// ---------------------------------------------------------------------------
// Kernel 2: stable counting sort of 4096 8-bit keys per (b,h). Unchanged.
// ---------------------------------------------------------------------------
__global__ void hyper_sort_kernel()
{
    int bh    = blockIdx.x;
    int which = blockIdx.y;
    const unsigned int* hw =
        (const unsigned int*)((which ? g_kh : g_qh) + (size_t)bh * S_LEN);
    int* idx = (which ? g_kidx : g_qidx) + (size_t)bh * S_LEN;

    __shared__ unsigned int w[1024];
    __shared__ int scan[256];
    int t = threadIdx.x;
#pragma unroll
    for (int i = 0; i < 4; i++) w[t + i * 256] = hw[t + i * 256];
    __syncthreads();

    unsigned k4 = t * 0x01010101u;
    int cnt = 0;
#pragma unroll 4
    for (int i = 0; i < 1024; i++) cnt += __popc(__vcmpeq4(w[i], k4));
    cnt >>= 3;

    scan[t] = cnt;
    __syncthreads();
    for (int off = 1; off < 256; off <<= 1) {
        int v = (t >= off) ? scan[t - off] : 0;
        __syncthreads();
        scan[t] += v;
        __syncthreads();
    }
    int pos = scan[t] - cnt;

    for (int i = 0; i < 1024; i++) {
        unsigned m = __vcmpeq4(w[i], k4);
        if (m) {
            int base = i * 4;
            if (m & 0x000000FFu) idx[pos++] = base;
            if (m & 0x0000FF00u) idx[pos++] = base + 1;
            if (m & 0x00FF0000u) idx[pos++] = base + 2;
            if (m & 0xFF000000u) idx[pos++] = base + 3;
        }
    }
}

// ---------------------------------------------------------------------------
// Kernel 3: fused attention, 256 threads, cp.async double-buffered tiles,
// plain fp16 MMAs with fp32 softmax/accumulation: S = q*K;  O += p*V.
// Dynamic smem: 2 buffers x 2 comps x 64 rows x 128 B = 32 KB.
// ---------------------------------------------------------------------------
extern __shared__ __align__(16) unsigned char dyn_smem[];

__global__ void __launch_bounds__(256, 2)
hyper_attn_kernel(const float* __restrict__ qkv,
                  const int*   __restrict__ sampled,
                  float*       __restrict__ out)
{
    __shared__ int   ssq[128];
    __shared__ int   ssrc_all[256];
    __shared__ float sbias_all[256];

    unsigned sbase = (unsigned)__cvta_generic_to_shared(dyn_smem);

    int g = blockIdx.x, h = blockIdx.y, b = blockIdx.z;
    int bh = b * NHEAD + h;
    int t  = threadIdx.x;
    int w  = t >> 5, l = t & 31;
    int lg = l >> 2, lq = l & 3;
    int m8 = l >> 3, r8 = l & 7;

    if (t < 128) ssq[t] = g_qidx[(size_t)bh * S_LEN + g * BLK + t];
    {   // all 4 chunks' key lists + biases in one pass
        int c = t >> 6, j = t & 63;
        int pos; float bias;
        if (c < 2) { pos = g * BLK + c * 64 + j; bias = 0.f; }
        else {
            pos  = sampled[bh * NSAMP + (c - 2) * 64 + j];
            bias = ((pos >> 7) == g) ? -1e30f : 5.0f;   // log2(n/m) = 5
        }
        ssrc_all[t]  = g_kidx[(size_t)bh * S_LEN + pos];
        sbias_all[t] = bias;
    }
    __syncthreads();

// 2 comps x 64 rows x 8 groups = 1024 cp16 per chunk = 4 per thread
#define FILL_CHUNK(cc, bb)                                                    \
    {                                                                         \
        _Pragma("unroll")                                                     \
        for (int i = 0; i < 4; i++) {                                         \
            int lin = t + i * 256;                                            \
            int comp = lin >> 9, rowg = lin & 511;                            \
            int rr = rowg >> 3, gg = rowg & 7;                                \
            int srow = ssrc_all[(cc) * 64 + rr];                              \
            const void* sp = g_pack + (size_t)comp * COMP_BYTES               \
                             + (((size_t)bh) * S_LEN + srow) * 128 + gg * 16; \
            unsigned dp = sbase + (bb) * BUFB + comp * 8192 + rr * 128        \
                          + ((gg ^ (rr & 7)) << 4);                           \
            cp16(dp, sp);                                                     \
        }                                                                     \
        cp_commit();                                                          \
    }
    FILL_CHUNK(0, 0);

    // ---- Q fragments (single fp16, 16 rows per warp), scale folded ----
    const float qs = 0.125f * LOG2E;
    unsigned qf[4][4];
    {
        int rA = w * 16 + lg;
        const float* qa = qkv + (size_t)(b * S_LEN + ssq[rA])     * 3072 + h * 64;
        const float* qb = qkv + (size_t)(b * S_LEN + ssq[rA + 8]) * 3072 + h * 64;
#pragma unroll
        for (int ks = 0; ks < 4; ks++) {
            int c0 = ks * 16 + lq * 2;
            float2 xa0 = *(const float2*)(qa + c0);
            float2 xb0 = *(const float2*)(qb + c0);
            float2 xa1 = *(const float2*)(qa + c0 + 8);
            float2 xb1 = *(const float2*)(qb + c0 + 8);
            qf[ks][0] = pack_h2(xa0.x * qs, xa0.y * qs);
            qf[ks][1] = pack_h2(xb0.x * qs, xb0.y * qs);
            qf[ks][2] = pack_h2(xa1.x * qs, xa1.y * qs);
            qf[ks][3] = pack_h2(xb1.x * qs, xb1.y * qs);
        }
    }

    float o[8][4];
#pragma unroll
    for (int nt = 0; nt < 8; nt++)
#pragma unroll
        for (int q4 = 0; q4 < 4; q4++) o[nt][q4] = 0.f;
    float mrow[2] = {-1e30f, -1e30f};
    float lrow[2] = {0.f, 0.f};

#pragma unroll
    for (int c = 0; c < 4; c++) {
        if (c < 3) { FILL_CHUNK(c + 1, (c + 1) & 1); cp_wait<1>(); }
        else       { cp_wait<0>(); }
        __syncthreads();

        unsigned tb = sbase + (c & 1) * BUFB;
        unsigned kb = tb, vb = tb + 8192;

        // ---- S = q*K + bias ----
        float s[8][4];
#pragma unroll
        for (int nt = 0; nt < 8; nt++) {
            float2 bv = *(const float2*)(sbias_all + c * 64 + nt * 8 + lq * 2);
            s[nt][0] = bv.x; s[nt][1] = bv.y;
            s[nt][2] = bv.x; s[nt][3] = bv.y;
        }
#pragma unroll
        for (int ks = 0; ks < 4; ks++) {
#pragma unroll
            for (int ntp = 0; ntp < 4; ntp++) {
                int key  = (2 * ntp + (m8 >> 1)) * 8 + r8;
                int gidx = ks * 2 + (m8 & 1);
                unsigned off = (unsigned)(key * 128 + ((gidx ^ (key & 7)) << 4));
                unsigned kh0, kh1, kh2, kh3;
                ldsm_x4(kh0, kh1, kh2, kh3, kb + off);
                MMAH(s[2*ntp],   qf[ks][0],qf[ks][1],qf[ks][2],qf[ks][3], kh0,kh1);
                MMAH(s[2*ntp+1], qf[ks][0],qf[ks][1],qf[ks][2],qf[ks][3], kh2,kh3);
            }
        }

        // ---- online softmax (base-2), s becomes P ----
#pragma unroll
        for (int hh = 0; hh < 2; hh++) {
            float cm = -1e30f;
#pragma unroll
            for (int nt = 0; nt < 8; nt++)
                cm = fmaxf(cm, fmaxf(s[nt][2*hh], s[nt][2*hh+1]));
            cm = fmaxf(cm, __shfl_xor_sync(0xFFFFFFFFu, cm, 1));
            cm = fmaxf(cm, __shfl_xor_sync(0xFFFFFFFFu, cm, 2));
            float nm  = fmaxf(mrow[hh], cm);
            float fsc = fast_exp2(mrow[hh] - nm);
            mrow[hh]  = nm;
            float ls = 0.f;
#pragma unroll
            for (int nt = 0; nt < 8; nt++) {
                float p0 = fast_exp2(s[nt][2*hh]     - nm);
                float p1 = fast_exp2(s[nt][2*hh + 1] - nm);
                s[nt][2*hh] = p0; s[nt][2*hh+1] = p1;
                ls += p0 + p1;
            }
            ls += __shfl_xor_sync(0xFFFFFFFFu, ls, 1);
            ls += __shfl_xor_sync(0xFFFFFFFFu, ls, 2);
            lrow[hh] = lrow[hh] * fsc + ls;
#pragma unroll
            for (int nt = 0; nt < 8; nt++) {
                o[nt][2*hh]     *= fsc;
                o[nt][2*hh + 1] *= fsc;
            }
        }

        // ---- O += p*V ----
#pragma unroll
        for (int kap = 0; kap < 4; kap++) {
            unsigned ph[4];
            ph[0] = pack_h2(s[2*kap][0],   s[2*kap][1]);
            ph[1] = pack_h2(s[2*kap][2],   s[2*kap][3]);
            ph[2] = pack_h2(s[2*kap+1][0], s[2*kap+1][1]);
            ph[3] = pack_h2(s[2*kap+1][2], s[2*kap+1][3]);
#pragma unroll
            for (int ntdp = 0; ntdp < 4; ntdp++) {
                int key  = kap * 16 + (m8 & 1) * 8 + r8;
                int gidx = ntdp * 2 + (m8 >> 1);
                unsigned off = (unsigned)(key * 128 + ((gidx ^ (key & 7)) << 4));
                unsigned vh0, vh1, vh2, vh3;
                ldsm_x4_t(vh0, vh1, vh2, vh3, vb + off);
                MMAH(o[2*ntdp],   ph[0],ph[1],ph[2],ph[3], vh0,vh1);
                MMAH(o[2*ntdp+1], ph[0],ph[1],ph[2],ph[3], vh2,vh3);
            }
        }
        __syncthreads();   // buffer (c&1) reused by fill at next iteration
    }

    // ---- normalize + scatter back to original query order ----
#pragma unroll
    for (int hh = 0; hh < 2; hh++) {
        float inv = 1.0f / lrow[hh];
        int row = w * 16 + hh * 8 + lg;
        float* op = out + ((size_t)(b * S_LEN + ssq[row]) * NHEAD + h) * 64;
#pragma unroll
        for (int nt = 0; nt < 8; nt++) {
            float2 v;
            v.x = o[nt][2*hh]     * inv;
            v.y = o[nt][2*hh + 1] * inv;
            *(float2*)(op + nt * 8 + lq * 2) = v;
        }
    }
}

// ---------------------------------------------------------------------------
extern "C" void kernel_launch(void* const* d_in, const int* in_sizes, int n_in,
                              void* d_out, int out_size)
{
    const float* qkv     = (const float*)d_in[0];   // [2,4096,3,16,64] f32
    const float* proj    = (const float*)d_in[1];   // [64,8] f32
    const int*   sampled = (const int*)d_in[2];     // [2,16,128] i32
    float*       out     = (float*)d_out;           // [2,4096,16,64] f32

    cudaFuncSetAttribute(hyper_attn_kernel,
                         cudaFuncAttributeMaxDynamicSharedMemorySize, 32768);

    hyper_hash_pack_kernel<<<NBATCH * S_LEN, 256>>>(qkv, proj);
    hyper_sort_kernel<<<dim3(NBH, 2), 256>>>();
    hyper_attn_kernel<<<dim3(NBLK, NHEAD, NBATCH), 256, 32768>>>(qkv, sampled, out);
}

// round 14
// speedup vs baseline: 3.1458x; 1.0173x over previous
#include <cuda_runtime.h>
#include <cuda_fp16.h>

// Problem constants (fixed shapes)
#define S_LEN  4096
#define NHEAD  16
#define NBATCH 2
#define NBH    (NBATCH*NHEAD)
#define BLK    128
#define NBLK   32
#define NSAMP  128
#define LOG2E  1.4426950408889634f
#define COMP_BYTES ((size_t)NBH * S_LEN * 128)   // one packed component
#define BUFB   32768                             // smem bytes per chunk buffer

// ---------------- scratch (no cudaMalloc allowed) ----------------
__device__ __align__(16) unsigned char g_qh[NBH*S_LEN];
__device__ __align__(16) unsigned char g_kh[NBH*S_LEN];
__device__ int g_qidx[NBH*S_LEN];
__device__ int g_kidx[NBH*S_LEN];
// packed K/V rows (fp16): [comp(k, v)][bh][token][128B]
__device__ __align__(128) unsigned char g_pack[2 * NBH * S_LEN * 128];

__device__ __forceinline__ float fast_exp2(float x)
{
    float r;
    asm("ex2.approx.f32 %0, %1;" : "=f"(r) : "f"(x));
    return r;
}

// fp32 pair -> packed fp16x2
__device__ __forceinline__ unsigned pack_h2(float x, float y)
{
    __half2 h = __floats2half2_rn(x, y);
    return *reinterpret_cast<unsigned*>(&h);
}

#define MMAH(c, a0,a1,a2,a3, b0,b1) \
  asm volatile("mma.sync.aligned.m16n8k16.row.col.f32.f16.f16.f32 " \
    "{%0,%1,%2,%3}, {%4,%5,%6,%7}, {%8,%9}, {%0,%1,%2,%3};" \
    : "+f"((c)[0]), "+f"((c)[1]), "+f"((c)[2]), "+f"((c)[3]) \
    : "r"(a0), "r"(a1), "r"(a2), "r"(a3), "r"(b0), "r"(b1))

__device__ __forceinline__ void ldsm_x4(unsigned& r0, unsigned& r1,
                                        unsigned& r2, unsigned& r3,
                                        unsigned addr)
{
    asm volatile("ldmatrix.sync.aligned.m8n8.x4.shared.b16 {%0,%1,%2,%3}, [%4];"
                 : "=r"(r0), "=r"(r1), "=r"(r2), "=r"(r3) : "r"(addr));
}
__device__ __forceinline__ void ldsm_x4_t(unsigned& r0, unsigned& r1,
                                          unsigned& r2, unsigned& r3,
                                          unsigned addr)
{
    asm volatile("ldmatrix.sync.aligned.m8n8.x4.trans.shared.b16 {%0,%1,%2,%3}, [%4];"
                 : "=r"(r0), "=r"(r1), "=r"(r2), "=r"(r3) : "r"(addr));
}

__device__ __forceinline__ void cp16(unsigned dst, const void* src)
{
    asm volatile("cp.async.cg.shared.global [%0], [%1], 16;"
                 :: "r"(dst), "l"(src) : "memory");
}
__device__ __forceinline__ void cp_commit()
{ asm volatile("cp.async.commit_group;" ::: "memory"); }
template<int N> __device__ __forceinline__ void cp_wait()
{ asm volatile("cp.async.wait_group %0;" :: "n"(N) : "memory"); }

// ---------------------------------------------------------------------------
// Kernel 1: LSH hash + K/V fp16 pre-pack. One CTA per (b,s), 256 threads.
// Pack path reads K directly from gmem (L2 hit on the smem-staged lines) so
// the 33MB store stream issues BEFORE the hash's smem sync, not behind it.
// ---------------------------------------------------------------------------
__global__ void __launch_bounds__(256)
hyper_hash_pack_kernel(const float* __restrict__ qkv,
                       const float* __restrict__ proj)
{
    __shared__ float spT[8 * 68];
    __shared__ float row[32 * 68];       // 16 q rows then 16 k rows, padded
    __shared__ unsigned int sbits[128];

    int t  = threadIdx.x;                // 0..255
    int bs = blockIdx.x;                 // b*4096 + s
    int b  = bs >> 12;
    int s  = bs & (S_LEN - 1);
    int hh = t >> 4, dg = t & 15;        // pack assignment: head, 4-float group

    // direct gmem loads for the pack path (independent of smem/sync)
    float4 kvec = *(const float4*)(qkv + (size_t)bs * 3072 + 1024
                                   + hh * 64 + dg * 4);
    float4 vvec = *(const float4*)(qkv + (size_t)bs * 3072 + 2048
                                   + hh * 64 + dg * 4);

    if (t < 64) {
        const float* pr = proj + t * 8;
#pragma unroll
        for (int r = 0; r < 8; r++) spT[r * 68 + t] = pr[r];
    }
    const float4* src = (const float4*)(qkv + (size_t)bs * 3072); // q+k = 512 f4
    float4* dst = (float4*)row;
#pragma unroll
    for (int i = 0; i < 2; i++) {
        int f = t + i * 256;
        dst[(f >> 4) * 17 + (f & 15)] = src[f];
    }

    // ---- pack K and V (single fp16 each) into g_pack, pre-sync ----
    {
        int bhp = b * NHEAD + hh;
        size_t rb = (((size_t)bhp) * S_LEN + s) * 128 + dg * 8;
        unsigned k0 = pack_h2(kvec.x, kvec.y);
        unsigned k1 = pack_h2(kvec.z, kvec.w);
        *(uint2*)(g_pack + 0 * COMP_BYTES + rb) = make_uint2(k0, k1);
        unsigned v0 = pack_h2(vvec.x, vvec.y);
        unsigned v1 = pack_h2(vvec.z, vvec.w);
        *(uint2*)(g_pack + 1 * COMP_BYTES + rb) = make_uint2(v0, v1);
    }
    __syncthreads();

    // ---- hash: threads 0..127 = (head, projection) ----
    if (t < 128) {
        int h = t >> 3, r = t & 7;
        const float4* xq = (const float4*)(row + h * 68);
        const float4* xk = (const float4*)(row + (16 + h) * 68);
        const float4* pp = (const float4*)(spT + r * 68);
        float dq = 0.f, dk = 0.f;
#pragma unroll
        for (int i = 0; i < 16; i++) {
            float4 p4 = pp[i];
            float4 a  = xq[i];
            float4 c  = xk[i];
            dq += a.x*p4.x + a.y*p4.y + a.z*p4.z + a.w*p4.w;
            dk += c.x*p4.x + c.y*p4.y + c.z*p4.z + c.w*p4.w;
        }
        unsigned bq = (dq > 0.f) ? (1u << r) : 0u;
        unsigned bk = (dk > 0.f) ? (1u << r) : 0u;
        sbits[t] = bq | (bk << 8);
    }
    __syncthreads();
    if (t < 128 && (t & 7) == 0) {
        unsigned c = 0;
#pragma unroll
        for (int i = 0; i < 8; i++) c |= sbits[t + i];
        unsigned cq = c & 0xFFu, ck = (c >> 8) & 0xFFu;
        cq ^= cq >> 1;                   // Gray permutation
        ck ^= ck >> 1;
        size_t o = (size_t)(b * NHEAD + (t >> 3)) * S_LEN + s;
        g_qh[o] = (unsigned char)cq;
        g_kh[o] = (unsigned char)ck;
    }
}

// ---------------------------------------------------------------------------
// Kernel 2: stable counting sort of 4096 8-bit keys per (b,h). Unchanged.
// ---------------------------------------------------------------------------
__global__ void hyper_sort_kernel()
{
    int bh    = blockIdx.x;
    int which = blockIdx.y;
    const unsigned int* hw =
        (const unsigned int*)((which ? g_kh : g_qh) + (size_t)bh * S_LEN);
    int* idx = (which ? g_kidx : g_qidx) + (size_t)bh * S_LEN;

    __shared__ unsigned int w[1024];
    __shared__ int scan[256];
    int t = threadIdx.x;
#pragma unroll
    for (int i = 0; i < 4; i++) w[t + i * 256] = hw[t + i * 256];
    __syncthreads();

    unsigned k4 = t * 0x01010101u;
    int cnt = 0;
#pragma unroll 4
    for (int i = 0; i < 1024; i++) cnt += __popc(__vcmpeq4(w[i], k4));
    cnt >>= 3;

    scan[t] = cnt;
    __syncthreads();
    for (int off = 1; off < 256; off <<= 1) {
        int v = (t >= off) ? scan[t - off] : 0;
        __syncthreads();
        scan[t] += v;
        __syncthreads();
    }
    int pos = scan[t] - cnt;

    for (int i = 0; i < 1024; i++) {
        unsigned m = __vcmpeq4(w[i], k4);
        if (m) {
            int base = i * 4;
            if (m & 0x000000FFu) idx[pos++] = base;
            if (m & 0x0000FF00u) idx[pos++] = base + 1;
            if (m & 0x00FF0000u) idx[pos++] = base + 2;
            if (m & 0xFF000000u) idx[pos++] = base + 3;
        }
    }
}

// ---------------------------------------------------------------------------
// Kernel 3: fused attention, 256 threads, TWO chunks of 128 keys
// (chunk 0 = sorted block, chunk 1 = sampled), double-buffered so no buffer
// is ever reused -> only one sync per chunk.
// Dynamic smem: 2 buffers x 2 comps x 128 rows x 128 B = 64 KB.
// ---------------------------------------------------------------------------
extern __shared__ __align__(16) unsigned char dyn_smem[];

__global__ void __launch_bounds__(256, 2)
hyper_attn_kernel(const float* __restrict__ qkv,
                  const int*   __restrict__ sampled,
                  float*       __restrict__ out)
{
    __shared__ int   ssq[128];
    __shared__ int   ssrc_all[256];
    __shared__ float sbias_all[256];

    unsigned sbase = (unsigned)__cvta_generic_to_shared(dyn_smem);

    int g = blockIdx.x, h = blockIdx.y, b = blockIdx.z;
    int bh = b * NHEAD + h;
    int t  = threadIdx.x;
    int w  = t >> 5, l = t & 31;
    int lg = l >> 2, lq = l & 3;
    int m8 = l >> 3, r8 = l & 7;

    if (t < 128) ssq[t] = g_qidx[(size_t)bh * S_LEN + g * BLK + t];
    {   // both chunks' key lists + biases in one pass (128 keys each)
        int c = t >> 7, j = t & 127;
        int pos; float bias;
        if (c == 0) { pos = g * BLK + j; bias = 0.f; }
        else {
            pos  = sampled[bh * NSAMP + j];
            bias = ((pos >> 7) == g) ? -1e30f : 5.0f;   // log2(n/m) = 5
        }
        ssrc_all[t]  = g_kidx[(size_t)bh * S_LEN + pos];
        sbias_all[t] = bias;
    }
    __syncthreads();

// 2 comps x 128 rows x 8 groups = 2048 cp16 per chunk = 8 per thread
#define FILL_CHUNK(cc, bb)                                                    \
    {                                                                         \
        _Pragma("unroll")                                                     \
        for (int i = 0; i < 8; i++) {                                         \
            int lin = t + i * 256;                                            \
            int comp = lin >> 10, rowg = lin & 1023;                          \
            int rr = rowg >> 3, gg = rowg & 7;                                \
            int srow = ssrc_all[(cc) * 128 + rr];                             \
            const void* sp = g_pack + (size_t)comp * COMP_BYTES               \
                             + (((size_t)bh) * S_LEN + srow) * 128 + gg * 16; \
            unsigned dp = sbase + (bb) * BUFB + comp * 16384 + rr * 128       \
                          + ((gg ^ (rr & 7)) << 4);                           \
            cp16(dp, sp);                                                     \
        }                                                                     \
        cp_commit();                                                          \
    }
    FILL_CHUNK(0, 0);
    FILL_CHUNK(1, 1);

    // ---- Q fragments (single fp16, 16 rows per warp), scale folded ----
    const float qs = 0.125f * LOG2E;
    unsigned qf[4][4];
    {
        int rA = w * 16 + lg;
        const float* qa = qkv + (size_t)(b * S_LEN + ssq[rA])     * 3072 + h * 64;
        const float* qb = qkv + (size_t)(b * S_LEN + ssq[rA + 8]) * 3072 + h * 64;
#pragma unroll
        for (int ks = 0; ks < 4; ks++) {
            int c0 = ks * 16 + lq * 2;
            float2 xa0 = *(const float2*)(qa + c0);
            float2 xb0 = *(const float2*)(qb + c0);
            float2 xa1 = *(const float2*)(qa + c0 + 8);
            float2 xb1 = *(const float2*)(qb + c0 + 8);
            qf[ks][0] = pack_h2(xa0.x * qs, xa0.y * qs);
            qf[ks][1] = pack_h2(xb0.x * qs, xb0.y * qs);
            qf[ks][2] = pack_h2(xa1.x * qs, xa1.y * qs);
            qf[ks][3] = pack_h2(xb1.x * qs, xb1.y * qs);
        }
    }

    float o[8][4];
#pragma unroll
    for (int nt = 0; nt < 8; nt++)
#pragma unroll
        for (int q4 = 0; q4 < 4; q4++) o[nt][q4] = 0.f;
    float mrow[2] = {-1e30f, -1e30f};
    float lrow[2] = {0.f, 0.f};

#pragma unroll
    for (int c = 0; c < 2; c++) {
        if (c == 0) cp_wait<1>();
        else        cp_wait<0>();
        __syncthreads();

        unsigned tb = sbase + c * BUFB;
        unsigned kb = tb, vb = tb + 16384;

        // ---- S = q*K + bias (16 n-tiles of 8 keys) ----
        float s[16][4];
#pragma unroll
        for (int nt = 0; nt < 16; nt++) {
            float2 bv = *(const float2*)(sbias_all + c * 128 + nt * 8 + lq * 2);
            s[nt][0] = bv.x; s[nt][1] = bv.y;
            s[nt][2] = bv.x; s[nt][3] = bv.y;
        }
#pragma unroll
        for (int ks = 0; ks < 4; ks++) {
#pragma unroll
            for (int ntp = 0; ntp < 8; ntp++) {
                int key  = (2 * ntp + (m8 >> 1)) * 8 + r8;
                int gidx = ks * 2 + (m8 & 1);
                unsigned off = (unsigned)(key * 128 + ((gidx ^ (key & 7)) << 4));
                unsigned kh0, kh1, kh2, kh3;
                ldsm_x4(kh0, kh1, kh2, kh3, kb + off);
                MMAH(s[2*ntp],   qf[ks][0],qf[ks][1],qf[ks][2],qf[ks][3], kh0,kh1);
                MMAH(s[2*ntp+1], qf[ks][0],qf[ks][1],qf[ks][2],qf[ks][3], kh2,kh3);
            }
        }

        // ---- online softmax (base-2), s becomes P ----
#pragma unroll
        for (int hh = 0; hh < 2; hh++) {
            float cm = -1e30f;
#pragma unroll
            for (int nt = 0; nt < 16; nt++)
                cm = fmaxf(cm, fmaxf(s[nt][2*hh], s[nt][2*hh+1]));
            cm = fmaxf(cm, __shfl_xor_sync(0xFFFFFFFFu, cm, 1));
            cm = fmaxf(cm, __shfl_xor_sync(0xFFFFFFFFu, cm, 2));
            float nm  = fmaxf(mrow[hh], cm);
            float fsc = fast_exp2(mrow[hh] - nm);
            mrow[hh]  = nm;
            float ls = 0.f;
#pragma unroll
            for (int nt = 0; nt < 16; nt++) {
                float p0 = fast_exp2(s[nt][2*hh]     - nm);
                float p1 = fast_exp2(s[nt][2*hh + 1] - nm);
                s[nt][2*hh] = p0; s[nt][2*hh+1] = p1;
                ls += p0 + p1;
            }
            ls += __shfl_xor_sync(0xFFFFFFFFu, ls, 1);
            ls += __shfl_xor_sync(0xFFFFFFFFu, ls, 2);
            lrow[hh] = lrow[hh] * fsc + ls;
#pragma unroll
            for (int nt = 0; nt < 8; nt++) {
                o[nt][2*hh]     *= fsc;
                o[nt][2*hh + 1] *= fsc;
            }
        }

        // ---- O += p*V (8 k-steps of 16 keys) ----
#pragma unroll
        for (int kap = 0; kap < 8; kap++) {
            unsigned ph[4];
            ph[0] = pack_h2(s[2*kap][0],   s[2*kap][1]);
            ph[1] = pack_h2(s[2*kap][2],   s[2*kap][3]);
            ph[2] = pack_h2(s[2*kap+1][0], s[2*kap+1][1]);
            ph[3] = pack_h2(s[2*kap+1][2], s[2*kap+1][3]);
#pragma unroll
            for (int ntdp = 0; ntdp < 4; ntdp++) {
                int key  = kap * 16 + (m8 & 1) * 8 + r8;
                int gidx = ntdp * 2 + (m8 >> 1);
                unsigned off = (unsigned)(key * 128 + ((gidx ^ (key & 7)) << 4));
                unsigned vh0, vh1, vh2, vh3;
                ldsm_x4_t(vh0, vh1, vh2, vh3, vb + off);
                MMAH(o[2*ntdp],   ph[0],ph[1],ph[2],ph[3], vh0,vh1);
                MMAH(o[2*ntdp+1], ph[0],ph[1],ph[2],ph[3], vh2,vh3);
            }
        }
        // no end-of-chunk sync: each buffer is filled once and never reused
    }

    // ---- normalize + scatter back to original query order ----
#pragma unroll
    for (int hh = 0; hh < 2; hh++) {
        float inv = 1.0f / lrow[hh];
        int row = w * 16 + hh * 8 + lg;
        float* op = out + ((size_t)(b * S_LEN + ssq[row]) * NHEAD + h) * 64;
#pragma unroll
        for (int nt = 0; nt < 8; nt++) {
            float2 v;
            v.x = o[nt][2*hh]     * inv;
            v.y = o[nt][2*hh + 1] * inv;
            *(float2*)(op + nt * 8 + lq * 2) = v;
        }
    }
}

// ---------------------------------------------------------------------------
extern "C" void kernel_launch(void* const* d_in, const int* in_sizes, int n_in,
                              void* d_out, int out_size)
{
    const float* qkv     = (const float*)d_in[0];   // [2,4096,3,16,64] f32
    const float* proj    = (const float*)d_in[1];   // [64,8] f32
    const int*   sampled = (const int*)d_in[2];     // [2,16,128] i32
    float*       out     = (float*)d_out;           // [2,4096,16,64] f32

    cudaFuncSetAttribute(hyper_attn_kernel,
                         cudaFuncAttributeMaxDynamicSharedMemorySize, 65536);

    hyper_hash_pack_kernel<<<NBATCH * S_LEN, 256>>>(qkv, proj);
    hyper_sort_kernel<<<dim3(NBH, 2), 256>>>();
    hyper_attn_kernel<<<dim3(NBLK, NHEAD, NBATCH), 256, 65536>>>(qkv, sampled, out);
}

// round 15
// speedup vs baseline: 3.9716x; 1.2625x over previous
#include <cuda_runtime.h>
#include <cuda_fp16.h>

// Problem constants (fixed shapes)
#define S_LEN  4096
#define NHEAD  16
#define NBATCH 2
#define NBH    (NBATCH*NHEAD)
#define BLK    128
#define NBLK   32
#define NSAMP  128
#define LOG2E  1.4426950408889634f
#define COMP_BYTES ((size_t)NBH * S_LEN * 128)   // one packed component
#define BUFB   32768                             // smem bytes per chunk buffer

// ---------------- scratch (no cudaMalloc allowed) ----------------
__device__ __align__(16) unsigned char g_qh[NBH*S_LEN];
__device__ __align__(16) unsigned char g_kh[NBH*S_LEN];
__device__ int g_qidx[NBH*S_LEN];
__device__ int g_kidx[NBH*S_LEN];
// packed K/V rows (fp16): [comp(k, v)][bh][token][128B]
__device__ __align__(128) unsigned char g_pack[2 * NBH * S_LEN * 128];

__device__ __forceinline__ float fast_exp2(float x)
{
    float r;
    asm("ex2.approx.f32 %0, %1;" : "=f"(r) : "f"(x));
    return r;
}

// fp32 pair -> packed fp16x2
__device__ __forceinline__ unsigned pack_h2(float x, float y)
{
    __half2 h = __floats2half2_rn(x, y);
    return *reinterpret_cast<unsigned*>(&h);
}

#define MMAH(c, a0,a1,a2,a3, b0,b1) \
  asm volatile("mma.sync.aligned.m16n8k16.row.col.f32.f16.f16.f32 " \
    "{%0,%1,%2,%3}, {%4,%5,%6,%7}, {%8,%9}, {%0,%1,%2,%3};" \
    : "+f"((c)[0]), "+f"((c)[1]), "+f"((c)[2]), "+f"((c)[3]) \
    : "r"(a0), "r"(a1), "r"(a2), "r"(a3), "r"(b0), "r"(b1))

__device__ __forceinline__ void ldsm_x4(unsigned& r0, unsigned& r1,
                                        unsigned& r2, unsigned& r3,
                                        unsigned addr)
{
    asm volatile("ldmatrix.sync.aligned.m8n8.x4.shared.b16 {%0,%1,%2,%3}, [%4];"
                 : "=r"(r0), "=r"(r1), "=r"(r2), "=r"(r3) : "r"(addr));
}
__device__ __forceinline__ void ldsm_x4_t(unsigned& r0, unsigned& r1,
                                          unsigned& r2, unsigned& r3,
                                          unsigned addr)
{
    asm volatile("ldmatrix.sync.aligned.m8n8.x4.trans.shared.b16 {%0,%1,%2,%3}, [%4];"
                 : "=r"(r0), "=r"(r1), "=r"(r2), "=r"(r3) : "r"(addr));
}

__device__ __forceinline__ void cp16(unsigned dst, const void* src)
{
    asm volatile("cp.async.cg.shared.global [%0], [%1], 16;"
                 :: "r"(dst), "l"(src) : "memory");
}
__device__ __forceinline__ void cp_commit()
{ asm volatile("cp.async.commit_group;" ::: "memory"); }
template<int N> __device__ __forceinline__ void cp_wait()
{ asm volatile("cp.async.wait_group %0;" :: "n"(N) : "memory"); }

// ---------------------------------------------------------------------------
// Kernel 1: LSH hash + K/V fp16 pre-pack (identical to R14).
// ---------------------------------------------------------------------------
__global__ void __launch_bounds__(256)
hyper_hash_pack_kernel(const float* __restrict__ qkv,
                       const float* __restrict__ proj)
{
    __shared__ float spT[8 * 68];
    __shared__ float row[32 * 68];       // 16 q rows then 16 k rows, padded
    __shared__ unsigned int sbits[128];

    int t  = threadIdx.x;                // 0..255
    int bs = blockIdx.x;                 // b*4096 + s
    int b  = bs >> 12;
    int s  = bs & (S_LEN - 1);
    int hh = t >> 4, dg = t & 15;        // pack assignment: head, 4-float group

    // direct gmem loads for the pack path (independent of smem/sync)
    float4 kvec = *(const float4*)(qkv + (size_t)bs * 3072 + 1024
                                   + hh * 64 + dg * 4);
    float4 vvec = *(const float4*)(qkv + (size_t)bs * 3072 + 2048
                                   + hh * 64 + dg * 4);

    if (t < 64) {
        const float* pr = proj + t * 8;
#pragma unroll
        for (int r = 0; r < 8; r++) spT[r * 68 + t] = pr[r];
    }
    const float4* src = (const float4*)(qkv + (size_t)bs * 3072); // q+k = 512 f4
    float4* dst = (float4*)row;
#pragma unroll
    for (int i = 0; i < 2; i++) {
        int f = t + i * 256;
        dst[(f >> 4) * 17 + (f & 15)] = src[f];
    }

    // ---- pack K and V (single fp16 each) into g_pack, pre-sync ----
    {
        int bhp = b * NHEAD + hh;
        size_t rb = (((size_t)bhp) * S_LEN + s) * 128 + dg * 8;
        unsigned k0 = pack_h2(kvec.x, kvec.y);
        unsigned k1 = pack_h2(kvec.z, kvec.w);
        *(uint2*)(g_pack + 0 * COMP_BYTES + rb) = make_uint2(k0, k1);
        unsigned v0 = pack_h2(vvec.x, vvec.y);
        unsigned v1 = pack_h2(vvec.z, vvec.w);
        *(uint2*)(g_pack + 1 * COMP_BYTES + rb) = make_uint2(v0, v1);
    }
    __syncthreads();

    // ---- hash: threads 0..127 = (head, projection) ----
    if (t < 128) {
        int h = t >> 3, r = t & 7;
        const float4* xq = (const float4*)(row + h * 68);
        const float4* xk = (const float4*)(row + (16 + h) * 68);
        const float4* pp = (const float4*)(spT + r * 68);
        float dq = 0.f, dk = 0.f;
#pragma unroll
        for (int i = 0; i < 16; i++) {
            float4 p4 = pp[i];
            float4 a  = xq[i];
            float4 c  = xk[i];
            dq += a.x*p4.x + a.y*p4.y + a.z*p4.z + a.w*p4.w;
            dk += c.x*p4.x + c.y*p4.y + c.z*p4.z + c.w*p4.w;
        }
        unsigned bq = (dq > 0.f) ? (1u << r) : 0u;
        unsigned bk = (dk > 0.f) ? (1u << r) : 0u;
        sbits[t] = bq | (bk << 8);
    }
    __syncthreads();
    if (t < 128 && (t & 7) == 0) {
        unsigned c = 0;
#pragma unroll
        for (int i = 0; i < 8; i++) c |= sbits[t + i];
        unsigned cq = c & 0xFFu, ck = (c >> 8) & 0xFFu;
        cq ^= cq >> 1;                   // Gray permutation
        ck ^= ck >> 1;
        size_t o = (size_t)(b * NHEAD + (t >> 3)) * S_LEN + s;
        g_qh[o] = (unsigned char)cq;
        g_kh[o] = (unsigned char)ck;
    }
}

// ---------------------------------------------------------------------------
// Kernel 2: stable counting sort, 1024 threads = (quarter, bucket).
// Each thread counts/places only its quarter (256 words) -> 4x less serial
// latency than the 256-thread version. Output permutation is bit-identical
// (quarters concatenated in ascending index order => stable).
// ---------------------------------------------------------------------------
__global__ void __launch_bounds__(1024)
hyper_sort_kernel()
{
    int bh    = blockIdx.x;
    int which = blockIdx.y;
    const unsigned int* hw =
        (const unsigned int*)((which ? g_kh : g_qh) + (size_t)bh * S_LEN);
    int* idx = (which ? g_kidx : g_qidx) + (size_t)bh * S_LEN;

    __shared__ unsigned int w[1024];
    __shared__ int scnt[4][256];
    __shared__ int scan[256];

    int t = threadIdx.x;                 // 0..1023
    int q = t >> 8;                      // quarter 0..3
    int k = t & 255;                     // bucket

    w[t] = hw[t];
    __syncthreads();

    unsigned k4 = k * 0x01010101u;
    int base = q * 256;
    int cnt = 0;
#pragma unroll 4
    for (int i = 0; i < 256; i++) cnt += __popc(__vcmpeq4(w[base + i], k4));
    cnt >>= 3;                           // 8 bits set per matching byte
    scnt[q][k] = cnt;
    __syncthreads();

    if (t < 256)
        scan[t] = scnt[0][t] + scnt[1][t] + scnt[2][t] + scnt[3][t];
    __syncthreads();
    for (int off = 1; off < 256; off <<= 1) {
        int v = (t < 256 && t >= off) ? scan[t - off] : 0;
        __syncthreads();
        if (t < 256) scan[t] += v;
        __syncthreads();
    }

    // start of (quarter q, bucket k) = inclusive_scan[k] - sum_{q'>=q} cnt[q'][k]
    int pos = scan[k];
#pragma unroll
    for (int qq = 3; qq >= 0; qq--)
        if (qq >= q) pos -= scnt[qq][k];

    for (int i = base; i < base + 256; i++) {
        unsigned m = __vcmpeq4(w[i], k4);
        if (m) {
            int e = i * 4;
            if (m & 0x000000FFu) idx[pos++] = e;
            if (m & 0x0000FF00u) idx[pos++] = e + 1;
            if (m & 0x00FF0000u) idx[pos++] = e + 2;
            if (m & 0xFF000000u) idx[pos++] = e + 3;
        }
    }
}

// ---------------------------------------------------------------------------
// Kernel 3: fused attention (identical to R14): 256 threads, two 128-key
// chunks, double-buffered cp.async, plain fp16 MMAs, fp32 softmax/accum.
// Dynamic smem: 2 buffers x 2 comps x 128 rows x 128 B = 64 KB.
// ---------------------------------------------------------------------------
extern __shared__ __align__(16) unsigned char dyn_smem[];

__global__ void __launch_bounds__(256, 2)
hyper_attn_kernel(const float* __restrict__ qkv,
                  const int*   __restrict__ sampled,
                  float*       __restrict__ out)
{
    __shared__ int   ssq[128];
    __shared__ int   ssrc_all[256];
    __shared__ float sbias_all[256];

    unsigned sbase = (unsigned)__cvta_generic_to_shared(dyn_smem);

    int g = blockIdx.x, h = blockIdx.y, b = blockIdx.z;
    int bh = b * NHEAD + h;
    int t  = threadIdx.x;
    int w  = t >> 5, l = t & 31;
    int lg = l >> 2, lq = l & 3;
    int m8 = l >> 3, r8 = l & 7;

    if (t < 128) ssq[t] = g_qidx[(size_t)bh * S_LEN + g * BLK + t];
    {   // both chunks' key lists + biases in one pass (128 keys each)
        int c = t >> 7, j = t & 127;
        int pos; float bias;
        if (c == 0) { pos = g * BLK + j; bias = 0.f; }
        else {
            pos  = sampled[bh * NSAMP + j];
            bias = ((pos >> 7) == g) ? -1e30f : 5.0f;   // log2(n/m) = 5
        }
        ssrc_all[t]  = g_kidx[(size_t)bh * S_LEN + pos];
        sbias_all[t] = bias;
    }
    __syncthreads();

// 2 comps x 128 rows x 8 groups = 2048 cp16 per chunk = 8 per thread
#define FILL_CHUNK(cc, bb)                                                    \
    {                                                                         \
        _Pragma("unroll")                                                     \
        for (int i = 0; i < 8; i++) {                                         \
            int lin = t + i * 256;                                            \
            int comp = lin >> 10, rowg = lin & 1023;                          \
            int rr = rowg >> 3, gg = rowg & 7;                                \
            int srow = ssrc_all[(cc) * 128 + rr];                             \
            const void* sp = g_pack + (size_t)comp * COMP_BYTES               \
                             + (((size_t)bh) * S_LEN + srow) * 128 + gg * 16; \
            unsigned dp = sbase + (bb) * BUFB + comp * 16384 + rr * 128       \
                          + ((gg ^ (rr & 7)) << 4);                           \
            cp16(dp, sp);                                                     \
        }                                                                     \
        cp_commit();                                                          \
    }
    FILL_CHUNK(0, 0);
    FILL_CHUNK(1, 1);

    // ---- Q fragments (single fp16, 16 rows per warp), scale folded ----
    const float qs = 0.125f * LOG2E;
    unsigned qf[4][4];
    {
        int rA = w * 16 + lg;
        const float* qa = qkv + (size_t)(b * S_LEN + ssq[rA])     * 3072 + h * 64;
        const float* qb = qkv + (size_t)(b * S_LEN + ssq[rA + 8]) * 3072 + h * 64;
#pragma unroll
        for (int ks = 0; ks < 4; ks++) {
            int c0 = ks * 16 + lq * 2;
            float2 xa0 = *(const float2*)(qa + c0);
            float2 xb0 = *(const float2*)(qb + c0);
            float2 xa1 = *(const float2*)(qa + c0 + 8);
            float2 xb1 = *(const float2*)(qb + c0 + 8);
            qf[ks][0] = pack_h2(xa0.x * qs, xa0.y * qs);
            qf[ks][1] = pack_h2(xb0.x * qs, xb0.y * qs);
            qf[ks][2] = pack_h2(xa1.x * qs, xa1.y * qs);
            qf[ks][3] = pack_h2(xb1.x * qs, xb1.y * qs);
        }
    }

    float o[8][4];
#pragma unroll
    for (int nt = 0; nt < 8; nt++)
#pragma unroll
        for (int q4 = 0; q4 < 4; q4++) o[nt][q4] = 0.f;
    float mrow[2] = {-1e30f, -1e30f};
    float lrow[2] = {0.f, 0.f};

#pragma unroll
    for (int c = 0; c < 2; c++) {
        if (c == 0) cp_wait<1>();
        else        cp_wait<0>();
        __syncthreads();

        unsigned tb = sbase + c * BUFB;
        unsigned kb = tb, vb = tb + 16384;

        // ---- S = q*K + bias (16 n-tiles of 8 keys) ----
        float s[16][4];
#pragma unroll
        for (int nt = 0; nt < 16; nt++) {
            float2 bv = *(const float2*)(sbias_all + c * 128 + nt * 8 + lq * 2);
            s[nt][0] = bv.x; s[nt][1] = bv.y;
            s[nt][2] = bv.x; s[nt][3] = bv.y;
        }
#pragma unroll
        for (int ks = 0; ks < 4; ks++) {
#pragma unroll
            for (int ntp = 0; ntp < 8; ntp++) {
                int key  = (2 * ntp + (m8 >> 1)) * 8 + r8;
                int gidx = ks * 2 + (m8 & 1);
                unsigned off = (unsigned)(key * 128 + ((gidx ^ (key & 7)) << 4));
                unsigned kh0, kh1, kh2, kh3;
                ldsm_x4(kh0, kh1, kh2, kh3, kb + off);
                MMAH(s[2*ntp],   qf[ks][0],qf[ks][1],qf[ks][2],qf[ks][3], kh0,kh1);
                MMAH(s[2*ntp+1], qf[ks][0],qf[ks][1],qf[ks][2],qf[ks][3], kh2,kh3);
            }
        }

        // ---- online softmax (base-2), s becomes P ----
#pragma unroll
        for (int hh = 0; hh < 2; hh++) {
            float cm = -1e30f;
#pragma unroll
            for (int nt = 0; nt < 16; nt++)
                cm = fmaxf(cm, fmaxf(s[nt][2*hh], s[nt][2*hh+1]));
            cm = fmaxf(cm, __shfl_xor_sync(0xFFFFFFFFu, cm, 1));
            cm = fmaxf(cm, __shfl_xor_sync(0xFFFFFFFFu, cm, 2));
            float nm  = fmaxf(mrow[hh], cm);
            float fsc = fast_exp2(mrow[hh] - nm);
            mrow[hh]  = nm;
            float ls = 0.f;
#pragma unroll
            for (int nt = 0; nt < 16; nt++) {
                float p0 = fast_exp2(s[nt][2*hh]     - nm);
                float p1 = fast_exp2(s[nt][2*hh + 1] - nm);
                s[nt][2*hh] = p0; s[nt][2*hh+1] = p1;
                ls += p0 + p1;
            }
            ls += __shfl_xor_sync(0xFFFFFFFFu, ls, 1);
            ls += __shfl_xor_sync(0xFFFFFFFFu, ls, 2);
            lrow[hh] = lrow[hh] * fsc + ls;
#pragma unroll
            for (int nt = 0; nt < 8; nt++) {
                o[nt][2*hh]     *= fsc;
                o[nt][2*hh + 1] *= fsc;
            }
        }

        // ---- O += p*V (8 k-steps of 16 keys) ----
#pragma unroll
        for (int kap = 0; kap < 8; kap++) {
            unsigned ph[4];
            ph[0] = pack_h2(s[2*kap][0],   s[2*kap][1]);
            ph[1] = pack_h2(s[2*kap][2],   s[2*kap][3]);
            ph[2] = pack_h2(s[2*kap+1][0], s[2*kap+1][1]);
            ph[3] = pack_h2(s[2*kap+1][2], s[2*kap+1][3]);
#pragma unroll
            for (int ntdp = 0; ntdp < 4; ntdp++) {
                int key  = kap * 16 + (m8 & 1) * 8 + r8;
                int gidx = ntdp * 2 + (m8 >> 1);
                unsigned off = (unsigned)(key * 128 + ((gidx ^ (key & 7)) << 4));
                unsigned vh0, vh1, vh2, vh3;
                ldsm_x4_t(vh0, vh1, vh2, vh3, vb + off);
                MMAH(o[2*ntdp],   ph[0],ph[1],ph[2],ph[3], vh0,vh1);
                MMAH(o[2*ntdp+1], ph[0],ph[1],ph[2],ph[3], vh2,vh3);
            }
        }
        // no end-of-chunk sync: each buffer is filled once and never reused
    }

    // ---- normalize + scatter back to original query order ----
#pragma unroll
    for (int hh = 0; hh < 2; hh++) {
        float inv = 1.0f / lrow[hh];
        int row = w * 16 + hh * 8 + lg;
        float* op = out + ((size_t)(b * S_LEN + ssq[row]) * NHEAD + h) * 64;
#pragma unroll
        for (int nt = 0; nt < 8; nt++) {
            float2 v;
            v.x = o[nt][2*hh]     * inv;
            v.y = o[nt][2*hh + 1] * inv;
            *(float2*)(op + nt * 8 + lq * 2) = v;
        }
    }
}

// ---------------------------------------------------------------------------
extern "C" void kernel_launch(void* const* d_in, const int* in_sizes, int n_in,
                              void* d_out, int out_size)
{
    const float* qkv     = (const float*)d_in[0];   // [2,4096,3,16,64] f32
    const float* proj    = (const float*)d_in[1];   // [64,8] f32
    const int*   sampled = (const int*)d_in[2];     // [2,16,128] i32
    float*       out     = (float*)d_out;           // [2,4096,16,64] f32

    cudaFuncSetAttribute(hyper_attn_kernel,
                         cudaFuncAttributeMaxDynamicSharedMemorySize, 65536);

    hyper_hash_pack_kernel<<<NBATCH * S_LEN, 256>>>(qkv, proj);
    hyper_sort_kernel<<<dim3(NBH, 2), 1024>>>();
    hyper_attn_kernel<<<dim3(NBLK, NHEAD, NBATCH), 256, 65536>>>(qkv, sampled, out);
}

// round 16
// speedup vs baseline: 3.9737x; 1.0005x over previous
#include <cuda_runtime.h>
#include <cuda_fp16.h>

// Problem constants (fixed shapes)
#define S_LEN  4096
#define NHEAD  16
#define NBATCH 2
#define NBH    (NBATCH*NHEAD)
#define BLK    128
#define NBLK   32
#define NSAMP  128
#define LOG2E  1.4426950408889634f
#define COMP_BYTES ((size_t)NBH * S_LEN * 128)   // one packed component
#define BUFB   32768                             // smem bytes per chunk buffer

// ---------------- scratch (no cudaMalloc allowed) ----------------
__device__ __align__(16) unsigned char g_qh[NBH*S_LEN];
__device__ __align__(16) unsigned char g_kh[NBH*S_LEN];
__device__ int g_qidx[NBH*S_LEN];
__device__ int g_kidx[NBH*S_LEN];
// packed K/V rows (fp16): [comp(k, v)][bh][token][128B]
__device__ __align__(128) unsigned char g_pack[2 * NBH * S_LEN * 128];

__device__ __forceinline__ float fast_exp2(float x)
{
    float r;
    asm("ex2.approx.f32 %0, %1;" : "=f"(r) : "f"(x));
    return r;
}

// fp32 pair -> packed fp16x2
__device__ __forceinline__ unsigned pack_h2(float x, float y)
{
    __half2 h = __floats2half2_rn(x, y);
    return *reinterpret_cast<unsigned*>(&h);
}

#define MMAH(c, a0,a1,a2,a3, b0,b1) \
  asm volatile("mma.sync.aligned.m16n8k16.row.col.f32.f16.f16.f32 " \
    "{%0,%1,%2,%3}, {%4,%5,%6,%7}, {%8,%9}, {%0,%1,%2,%3};" \
    : "+f"((c)[0]), "+f"((c)[1]), "+f"((c)[2]), "+f"((c)[3]) \
    : "r"(a0), "r"(a1), "r"(a2), "r"(a3), "r"(b0), "r"(b1))

__device__ __forceinline__ void ldsm_x4(unsigned& r0, unsigned& r1,
                                        unsigned& r2, unsigned& r3,
                                        unsigned addr)
{
    asm volatile("ldmatrix.sync.aligned.m8n8.x4.shared.b16 {%0,%1,%2,%3}, [%4];"
                 : "=r"(r0), "=r"(r1), "=r"(r2), "=r"(r3) : "r"(addr));
}
__device__ __forceinline__ void ldsm_x4_t(unsigned& r0, unsigned& r1,
                                          unsigned& r2, unsigned& r3,
                                          unsigned addr)
{
    asm volatile("ldmatrix.sync.aligned.m8n8.x4.trans.shared.b16 {%0,%1,%2,%3}, [%4];"
                 : "=r"(r0), "=r"(r1), "=r"(r2), "=r"(r3) : "r"(addr));
}

__device__ __forceinline__ void cp16(unsigned dst, const void* src)
{
    asm volatile("cp.async.cg.shared.global [%0], [%1], 16;"
                 :: "r"(dst), "l"(src) : "memory");
}
__device__ __forceinline__ void cp_commit()
{ asm volatile("cp.async.commit_group;" ::: "memory"); }
template<int N> __device__ __forceinline__ void cp_wait()
{ asm volatile("cp.async.wait_group %0;" :: "n"(N) : "memory"); }

// ---------------------------------------------------------------------------
// Kernel 1: LSH hash + K/V fp16 pre-pack. TWO tokens per CTA (grid 4096):
// doubled per-thread MLP on the load side, full 256-thread hash phase.
// ---------------------------------------------------------------------------
__global__ void __launch_bounds__(256)
hyper_hash_pack_kernel(const float* __restrict__ qkv,
                       const float* __restrict__ proj)
{
    __shared__ float spT[8 * 68];
    __shared__ float row[2 * 32 * 68];   // per token: 16 q rows + 16 k rows
    __shared__ unsigned int sbits[256];

    int t   = threadIdx.x;               // 0..255
    int bs2 = blockIdx.x * 2;            // first token of the pair
    int hh  = t >> 4, dg = t & 15;       // pack assignment: head, 4-float grp

    // direct gmem loads for the pack path (4 independent loads, front-batched)
    float4 kvec0 = *(const float4*)(qkv + (size_t)bs2 * 3072 + 1024
                                    + hh * 64 + dg * 4);
    float4 vvec0 = *(const float4*)(qkv + (size_t)bs2 * 3072 + 2048
                                    + hh * 64 + dg * 4);
    float4 kvec1 = *(const float4*)(qkv + (size_t)(bs2 + 1) * 3072 + 1024
                                    + hh * 64 + dg * 4);
    float4 vvec1 = *(const float4*)(qkv + (size_t)(bs2 + 1) * 3072 + 2048
                                    + hh * 64 + dg * 4);

    if (t < 64) {
        const float* pr = proj + t * 8;
#pragma unroll
        for (int r = 0; r < 8; r++) spT[r * 68 + t] = pr[r];
    }
    // stage q+k of both tokens (4 independent f4 loads per thread)
    const float4* src = (const float4*)(qkv + (size_t)bs2 * 3072);
    float4* dst = (float4*)row;
#pragma unroll
    for (int i = 0; i < 4; i++) {
        int f = t + i * 256;             // 0..1023
        int tok = f >> 9, wi = f & 511;
        dst[tok * 544 + (wi >> 4) * 17 + (wi & 15)] = src[tok * 768 + wi];
    }

    // ---- pack K and V (single fp16 each) for both tokens, pre-sync ----
    {
        int bhp = ((bs2 >> 12) * NHEAD) + hh;     // pair never crosses batch
        size_t rb = (((size_t)bhp) * S_LEN + (bs2 & (S_LEN - 1))) * 128 + dg * 8;
        *(uint2*)(g_pack + 0 * COMP_BYTES + rb) =
            make_uint2(pack_h2(kvec0.x, kvec0.y), pack_h2(kvec0.z, kvec0.w));
        *(uint2*)(g_pack + 1 * COMP_BYTES + rb) =
            make_uint2(pack_h2(vvec0.x, vvec0.y), pack_h2(vvec0.z, vvec0.w));
        *(uint2*)(g_pack + 0 * COMP_BYTES + rb + 128) =
            make_uint2(pack_h2(kvec1.x, kvec1.y), pack_h2(kvec1.z, kvec1.w));
        *(uint2*)(g_pack + 1 * COMP_BYTES + rb + 128) =
            make_uint2(pack_h2(vvec1.x, vvec1.y), pack_h2(vvec1.z, vvec1.w));
    }
    __syncthreads();

    // ---- hash: all 256 threads = (token, head, projection) ----
    {
        int tok = t >> 7, tt = t & 127;
        int h = tt >> 3, r = tt & 7;
        const float4* xq = (const float4*)(row + tok * 2176 + h * 68);
        const float4* xk = (const float4*)(row + tok * 2176 + (16 + h) * 68);
        const float4* pp = (const float4*)(spT + r * 68);
        float dq = 0.f, dk = 0.f;
#pragma unroll
        for (int i = 0; i < 16; i++) {
            float4 p4 = pp[i];
            float4 a  = xq[i];
            float4 c  = xk[i];
            dq += a.x*p4.x + a.y*p4.y + a.z*p4.z + a.w*p4.w;
            dk += c.x*p4.x + c.y*p4.y + c.z*p4.z + c.w*p4.w;
        }
        unsigned bq = (dq > 0.f) ? (1u << r) : 0u;
        unsigned bk = (dk > 0.f) ? (1u << r) : 0u;
        sbits[t] = bq | (bk << 8);
    }
    __syncthreads();
    if ((t & 7) == 0) {
        unsigned c = 0;
#pragma unroll
        for (int i = 0; i < 8; i++) c |= sbits[t + i];
        unsigned cq = c & 0xFFu, ck = (c >> 8) & 0xFFu;
        cq ^= cq >> 1;                   // Gray permutation
        ck ^= ck >> 1;
        int tok = t >> 7, h = (t & 127) >> 3;
        int bs  = bs2 + tok;
        size_t o = (size_t)((bs >> 12) * NHEAD + h) * S_LEN + (bs & (S_LEN - 1));
        g_qh[o] = (unsigned char)cq;
        g_kh[o] = (unsigned char)ck;
    }
}

// ---------------------------------------------------------------------------
// Kernel 2: stable counting sort, 1024 threads = (quarter, bucket).
// Bit-identical stable output (quarters concatenated in index order).
// ---------------------------------------------------------------------------
__global__ void __launch_bounds__(1024)
hyper_sort_kernel()
{
    int bh    = blockIdx.x;
    int which = blockIdx.y;
    const unsigned int* hw =
        (const unsigned int*)((which ? g_kh : g_qh) + (size_t)bh * S_LEN);
    int* idx = (which ? g_kidx : g_qidx) + (size_t)bh * S_LEN;

    __shared__ unsigned int w[1024];
    __shared__ int scnt[4][256];
    __shared__ int scan[256];

    int t = threadIdx.x;                 // 0..1023
    int q = t >> 8;                      // quarter 0..3
    int k = t & 255;                     // bucket

    w[t] = hw[t];
    __syncthreads();

    unsigned k4 = k * 0x01010101u;
    int base = q * 256;
    int cnt = 0;
#pragma unroll 4
    for (int i = 0; i < 256; i++) cnt += __popc(__vcmpeq4(w[base + i], k4));
    cnt >>= 3;                           // 8 bits set per matching byte
    scnt[q][k] = cnt;
    __syncthreads();

    if (t < 256)
        scan[t] = scnt[0][t] + scnt[1][t] + scnt[2][t] + scnt[3][t];
    __syncthreads();
    for (int off = 1; off < 256; off <<= 1) {
        int v = (t < 256 && t >= off) ? scan[t - off] : 0;
        __syncthreads();
        if (t < 256) scan[t] += v;
        __syncthreads();
    }

    // start of (quarter q, bucket k) = inclusive_scan[k] - sum_{q'>=q} cnt[q'][k]
    int pos = scan[k];
#pragma unroll
    for (int qq = 3; qq >= 0; qq--)
        if (qq >= q) pos -= scnt[qq][k];

    for (int i = base; i < base + 256; i++) {
        unsigned m = __vcmpeq4(w[i], k4);
        if (m) {
            int e = i * 4;
            if (m & 0x000000FFu) idx[pos++] = e;
            if (m & 0x0000FF00u) idx[pos++] = e + 1;
            if (m & 0x00FF0000u) idx[pos++] = e + 2;
            if (m & 0xFF000000u) idx[pos++] = e + 3;
        }
    }
}

// ---------------------------------------------------------------------------
// Kernel 3: fused attention: 256 threads, two 128-key chunks, double-buffered
// cp.async, plain fp16 MMAs, fp32 softmax/accum. Chunk-0 o-rescale skipped
// (bit-identical: o is zero there).
// Dynamic smem: 2 buffers x 2 comps x 128 rows x 128 B = 64 KB.
// ---------------------------------------------------------------------------
extern __shared__ __align__(16) unsigned char dyn_smem[];

__global__ void __launch_bounds__(256, 2)
hyper_attn_kernel(const float* __restrict__ qkv,
                  const int*   __restrict__ sampled,
                  float*       __restrict__ out)
{
    __shared__ int   ssq[128];
    __shared__ int   ssrc_all[256];
    __shared__ float sbias_all[256];

    unsigned sbase = (unsigned)__cvta_generic_to_shared(dyn_smem);

    int g = blockIdx.x, h = blockIdx.y, b = blockIdx.z;
    int bh = b * NHEAD + h;
    int t  = threadIdx.x;
    int w  = t >> 5, l = t & 31;
    int lg = l >> 2, lq = l & 3;
    int m8 = l >> 3, r8 = l & 7;

    if (t < 128) ssq[t] = g_qidx[(size_t)bh * S_LEN + g * BLK + t];
    {   // both chunks' key lists + biases in one pass (128 keys each)
        int c = t >> 7, j = t & 127;
        int pos; float bias;
        if (c == 0) { pos = g * BLK + j; bias = 0.f; }
        else {
            pos  = sampled[bh * NSAMP + j];
            bias = ((pos >> 7) == g) ? -1e30f : 5.0f;   // log2(n/m) = 5
        }
        ssrc_all[t]  = g_kidx[(size_t)bh * S_LEN + pos];
        sbias_all[t] = bias;
    }
    __syncthreads();

// 2 comps x 128 rows x 8 groups = 2048 cp16 per chunk = 8 per thread
#define FILL_CHUNK(cc, bb)                                                    \
    {                                                                         \
        _Pragma("unroll")                                                     \
        for (int i = 0; i < 8; i++) {                                         \
            int lin = t + i * 256;                                            \
            int comp = lin >> 10, rowg = lin & 1023;                          \
            int rr = rowg >> 3, gg = rowg & 7;                                \
            int srow = ssrc_all[(cc) * 128 + rr];                             \
            const void* sp = g_pack + (size_t)comp * COMP_BYTES               \
                             + (((size_t)bh) * S_LEN + srow) * 128 + gg * 16; \
            unsigned dp = sbase + (bb) * BUFB + comp * 16384 + rr * 128       \
                          + ((gg ^ (rr & 7)) << 4);                           \
            cp16(dp, sp);                                                     \
        }                                                                     \
        cp_commit();                                                          \
    }
    FILL_CHUNK(0, 0);
    FILL_CHUNK(1, 1);

    // ---- Q fragments (single fp16, 16 rows per warp), scale folded ----
    const float qs = 0.125f * LOG2E;
    unsigned qf[4][4];
    {
        int rA = w * 16 + lg;
        const float* qa = qkv + (size_t)(b * S_LEN + ssq[rA])     * 3072 + h * 64;
        const float* qb = qkv + (size_t)(b * S_LEN + ssq[rA + 8]) * 3072 + h * 64;
#pragma unroll
        for (int ks = 0; ks < 4; ks++) {
            int c0 = ks * 16 + lq * 2;
            float2 xa0 = *(const float2*)(qa + c0);
            float2 xb0 = *(const float2*)(qb + c0);
            float2 xa1 = *(const float2*)(qa + c0 + 8);
            float2 xb1 = *(const float2*)(qb + c0 + 8);
            qf[ks][0] = pack_h2(xa0.x * qs, xa0.y * qs);
            qf[ks][1] = pack_h2(xb0.x * qs, xb0.y * qs);
            qf[ks][2] = pack_h2(xa1.x * qs, xa1.y * qs);
            qf[ks][3] = pack_h2(xb1.x * qs, xb1.y * qs);
        }
    }

    float o[8][4];
#pragma unroll
    for (int nt = 0; nt < 8; nt++)
#pragma unroll
        for (int q4 = 0; q4 < 4; q4++) o[nt][q4] = 0.f;
    float mrow[2] = {-1e30f, -1e30f};
    float lrow[2] = {0.f, 0.f};

#pragma unroll
    for (int c = 0; c < 2; c++) {
        if (c == 0) cp_wait<1>();
        else        cp_wait<0>();
        __syncthreads();

        unsigned tb = sbase + c * BUFB;
        unsigned kb = tb, vb = tb + 16384;

        // ---- S = q*K + bias (16 n-tiles of 8 keys) ----
        float s[16][4];
#pragma unroll
        for (int nt = 0; nt < 16; nt++) {
            float2 bv = *(const float2*)(sbias_all + c * 128 + nt * 8 + lq * 2);
            s[nt][0] = bv.x; s[nt][1] = bv.y;
            s[nt][2] = bv.x; s[nt][3] = bv.y;
        }
#pragma unroll
        for (int ks = 0; ks < 4; ks++) {
#pragma unroll
            for (int ntp = 0; ntp < 8; ntp++) {
                int key  = (2 * ntp + (m8 >> 1)) * 8 + r8;
                int gidx = ks * 2 + (m8 & 1);
                unsigned off = (unsigned)(key * 128 + ((gidx ^ (key & 7)) << 4));
                unsigned kh0, kh1, kh2, kh3;
                ldsm_x4(kh0, kh1, kh2, kh3, kb + off);
                MMAH(s[2*ntp],   qf[ks][0],qf[ks][1],qf[ks][2],qf[ks][3], kh0,kh1);
                MMAH(s[2*ntp+1], qf[ks][0],qf[ks][1],qf[ks][2],qf[ks][3], kh2,kh3);
            }
        }

        // ---- online softmax (base-2), s becomes P ----
#pragma unroll
        for (int hh = 0; hh < 2; hh++) {
            float cm = -1e30f;
#pragma unroll
            for (int nt = 0; nt < 16; nt++)
                cm = fmaxf(cm, fmaxf(s[nt][2*hh], s[nt][2*hh+1]));
            cm = fmaxf(cm, __shfl_xor_sync(0xFFFFFFFFu, cm, 1));
            cm = fmaxf(cm, __shfl_xor_sync(0xFFFFFFFFu, cm, 2));
            float nm  = fmaxf(mrow[hh], cm);
            float fsc = fast_exp2(mrow[hh] - nm);
            mrow[hh]  = nm;
            float ls = 0.f;
#pragma unroll
            for (int nt = 0; nt < 16; nt++) {
                float p0 = fast_exp2(s[nt][2*hh]     - nm);
                float p1 = fast_exp2(s[nt][2*hh + 1] - nm);
                s[nt][2*hh] = p0; s[nt][2*hh+1] = p1;
                ls += p0 + p1;
            }
            ls += __shfl_xor_sync(0xFFFFFFFFu, ls, 1);
            ls += __shfl_xor_sync(0xFFFFFFFFu, ls, 2);
            lrow[hh] = lrow[hh] * fsc + ls;
            if (c) {                     // chunk 0: o is all zeros, skip
#pragma unroll
                for (int nt = 0; nt < 8; nt++) {
                    o[nt][2*hh]     *= fsc;
                    o[nt][2*hh + 1] *= fsc;
                }
            }
        }

        // ---- O += p*V (8 k-steps of 16 keys) ----
#pragma unroll
        for (int kap = 0; kap < 8; kap++) {
            unsigned ph[4];
            ph[0] = pack_h2(s[2*kap][0],   s[2*kap][1]);
            ph[1] = pack_h2(s[2*kap][2],   s[2*kap][3]);
            ph[2] = pack_h2(s[2*kap+1][0], s[2*kap+1][1]);
            ph[3] = pack_h2(s[2*kap+1][2], s[2*kap+1][3]);
#pragma unroll
            for (int ntdp = 0; ntdp < 4; ntdp++) {
                int key  = kap * 16 + (m8 & 1) * 8 + r8;
                int gidx = ntdp * 2 + (m8 >> 1);
                unsigned off = (unsigned)(key * 128 + ((gidx ^ (key & 7)) << 4));
                unsigned vh0, vh1, vh2, vh3;
                ldsm_x4_t(vh0, vh1, vh2, vh3, vb + off);
                MMAH(o[2*ntdp],   ph[0],ph[1],ph[2],ph[3], vh0,vh1);
                MMAH(o[2*ntdp+1], ph[0],ph[1],ph[2],ph[3], vh2,vh3);
            }
        }
        // no end-of-chunk sync: each buffer is filled once and never reused
    }

    // ---- normalize + scatter back to original query order ----
#pragma unroll
    for (int hh = 0; hh < 2; hh++) {
        float inv = 1.0f / lrow[hh];
        int row = w * 16 + hh * 8 + lg;
        float* op = out + ((size_t)(b * S_LEN + ssq[row]) * NHEAD + h) * 64;
#pragma unroll
        for (int nt = 0; nt < 8; nt++) {
            float2 v;
            v.x = o[nt][2*hh]     * inv;
            v.y = o[nt][2*hh + 1] * inv;
            *(float2*)(op + nt * 8 + lq * 2) = v;
        }
    }
}

// ---------------------------------------------------------------------------
extern "C" void kernel_launch(void* const* d_in, const int* in_sizes, int n_in,
                              void* d_out, int out_size)
{
    const float* qkv     = (const float*)d_in[0];   // [2,4096,3,16,64] f32
    const float* proj    = (const float*)d_in[1];   // [64,8] f32
    const int*   sampled = (const int*)d_in[2];     // [2,16,128] i32
    float*       out     = (float*)d_out;           // [2,4096,16,64] f32

    cudaFuncSetAttribute(hyper_attn_kernel,
                         cudaFuncAttributeMaxDynamicSharedMemorySize, 65536);

    hyper_hash_pack_kernel<<<NBATCH * S_LEN / 2, 256>>>(qkv, proj);
    hyper_sort_kernel<<<dim3(NBH, 2), 1024>>>();
    hyper_attn_kernel<<<dim3(NBLK, NHEAD, NBATCH), 256, 65536>>>(qkv, sampled, out);
}

// round 17
// speedup vs baseline: 4.0400x; 1.0167x over previous
#include <cuda_runtime.h>
#include <cuda_fp16.h>

// Problem constants (fixed shapes)
#define S_LEN  4096
#define NHEAD  16
#define NBATCH 2
#define NBH    (NBATCH*NHEAD)
#define BLK    128
#define NBLK   32
#define NSAMP  128
#define LOG2E  1.4426950408889634f
#define COMP_BYTES ((size_t)NBH * S_LEN * 128)   // one packed component
#define BUFB   32768                             // smem bytes per chunk buffer

// ---------------- scratch (no cudaMalloc allowed) ----------------
__device__ __align__(16) unsigned char g_qh[NBH*S_LEN];
__device__ __align__(16) unsigned char g_kh[NBH*S_LEN];
__device__ int g_qidx[NBH*S_LEN];
__device__ int g_kidx[NBH*S_LEN];
// packed K/V rows (fp16): [comp(k, v)][bh][token][128B]
__device__ __align__(128) unsigned char g_pack[2 * NBH * S_LEN * 128];

__device__ __forceinline__ float fast_exp2(float x)
{
    float r;
    asm("ex2.approx.f32 %0, %1;" : "=f"(r) : "f"(x));
    return r;
}

// fp32 pair -> packed fp16x2
__device__ __forceinline__ unsigned pack_h2(float x, float y)
{
    __half2 h = __floats2half2_rn(x, y);
    return *reinterpret_cast<unsigned*>(&h);
}

#define MMAH(c, a0,a1,a2,a3, b0,b1) \
  asm volatile("mma.sync.aligned.m16n8k16.row.col.f32.f16.f16.f32 " \
    "{%0,%1,%2,%3}, {%4,%5,%6,%7}, {%8,%9}, {%0,%1,%2,%3};" \
    : "+f"((c)[0]), "+f"((c)[1]), "+f"((c)[2]), "+f"((c)[3]) \
    : "r"(a0), "r"(a1), "r"(a2), "r"(a3), "r"(b0), "r"(b1))

__device__ __forceinline__ void ldsm_x4(unsigned& r0, unsigned& r1,
                                        unsigned& r2, unsigned& r3,
                                        unsigned addr)
{
    asm volatile("ldmatrix.sync.aligned.m8n8.x4.shared.b16 {%0,%1,%2,%3}, [%4];"
                 : "=r"(r0), "=r"(r1), "=r"(r2), "=r"(r3) : "r"(addr));
}
__device__ __forceinline__ void ldsm_x4_t(unsigned& r0, unsigned& r1,
                                          unsigned& r2, unsigned& r3,
                                          unsigned addr)
{
    asm volatile("ldmatrix.sync.aligned.m8n8.x4.trans.shared.b16 {%0,%1,%2,%3}, [%4];"
                 : "=r"(r0), "=r"(r1), "=r"(r2), "=r"(r3) : "r"(addr));
}

__device__ __forceinline__ void cp16(unsigned dst, const void* src)
{
    asm volatile("cp.async.cg.shared.global [%0], [%1], 16;"
                 :: "r"(dst), "l"(src) : "memory");
}
__device__ __forceinline__ void cp_commit()
{ asm volatile("cp.async.commit_group;" ::: "memory"); }
template<int N> __device__ __forceinline__ void cp_wait()
{ asm volatile("cp.async.wait_group %0;" :: "n"(N) : "memory"); }

// ---------------------------------------------------------------------------
// Kernel 1: LSH hash + K/V fp16 pre-pack. Two tokens per CTA (identical R16).
// ---------------------------------------------------------------------------
__global__ void __launch_bounds__(256)
hyper_hash_pack_kernel(const float* __restrict__ qkv,
                       const float* __restrict__ proj)
{
    __shared__ float spT[8 * 68];
    __shared__ float row[2 * 32 * 68];   // per token: 16 q rows + 16 k rows
    __shared__ unsigned int sbits[256];

    int t   = threadIdx.x;               // 0..255
    int bs2 = blockIdx.x * 2;            // first token of the pair
    int hh  = t >> 4, dg = t & 15;       // pack assignment: head, 4-float grp

    float4 kvec0 = *(const float4*)(qkv + (size_t)bs2 * 3072 + 1024
                                    + hh * 64 + dg * 4);
    float4 vvec0 = *(const float4*)(qkv + (size_t)bs2 * 3072 + 2048
                                    + hh * 64 + dg * 4);
    float4 kvec1 = *(const float4*)(qkv + (size_t)(bs2 + 1) * 3072 + 1024
                                    + hh * 64 + dg * 4);
    float4 vvec1 = *(const float4*)(qkv + (size_t)(bs2 + 1) * 3072 + 2048
                                    + hh * 64 + dg * 4);

    if (t < 64) {
        const float* pr = proj + t * 8;
#pragma unroll
        for (int r = 0; r < 8; r++) spT[r * 68 + t] = pr[r];
    }
    const float4* src = (const float4*)(qkv + (size_t)bs2 * 3072);
    float4* dst = (float4*)row;
#pragma unroll
    for (int i = 0; i < 4; i++) {
        int f = t + i * 256;             // 0..1023
        int tok = f >> 9, wi = f & 511;
        dst[tok * 544 + (wi >> 4) * 17 + (wi & 15)] = src[tok * 768 + wi];
    }

    {
        int bhp = ((bs2 >> 12) * NHEAD) + hh;     // pair never crosses batch
        size_t rb = (((size_t)bhp) * S_LEN + (bs2 & (S_LEN - 1))) * 128 + dg * 8;
        *(uint2*)(g_pack + 0 * COMP_BYTES + rb) =
            make_uint2(pack_h2(kvec0.x, kvec0.y), pack_h2(kvec0.z, kvec0.w));
        *(uint2*)(g_pack + 1 * COMP_BYTES + rb) =
            make_uint2(pack_h2(vvec0.x, vvec0.y), pack_h2(vvec0.z, vvec0.w));
        *(uint2*)(g_pack + 0 * COMP_BYTES + rb + 128) =
            make_uint2(pack_h2(kvec1.x, kvec1.y), pack_h2(kvec1.z, kvec1.w));
        *(uint2*)(g_pack + 1 * COMP_BYTES + rb + 128) =
            make_uint2(pack_h2(vvec1.x, vvec1.y), pack_h2(vvec1.z, vvec1.w));
    }
    __syncthreads();

    {
        int tok = t >> 7, tt = t & 127;
        int h = tt >> 3, r = tt & 7;
        const float4* xq = (const float4*)(row + tok * 2176 + h * 68);
        const float4* xk = (const float4*)(row + tok * 2176 + (16 + h) * 68);
        const float4* pp = (const float4*)(spT + r * 68);
        float dq = 0.f, dk = 0.f;
#pragma unroll
        for (int i = 0; i < 16; i++) {
            float4 p4 = pp[i];
            float4 a  = xq[i];
            float4 c  = xk[i];
            dq += a.x*p4.x + a.y*p4.y + a.z*p4.z + a.w*p4.w;
            dk += c.x*p4.x + c.y*p4.y + c.z*p4.z + c.w*p4.w;
        }
        unsigned bq = (dq > 0.f) ? (1u << r) : 0u;
        unsigned bk = (dk > 0.f) ? (1u << r) : 0u;
        sbits[t] = bq | (bk << 8);
    }
    __syncthreads();
    if ((t & 7) == 0) {
        unsigned c = 0;
#pragma unroll
        for (int i = 0; i < 8; i++) c |= sbits[t + i];
        unsigned cq = c & 0xFFu, ck = (c >> 8) & 0xFFu;
        cq ^= cq >> 1;                   // Gray permutation
        ck ^= ck >> 1;
        int tok = t >> 7, h = (t & 127) >> 3;
        int bs  = bs2 + tok;
        size_t o = (size_t)((bs >> 12) * NHEAD + h) * S_LEN + (bs & (S_LEN - 1));
        g_qh[o] = (unsigned char)cq;
        g_kh[o] = (unsigned char)ck;
    }
}

// ---------------------------------------------------------------------------
// Kernel 2: stable counting sort, 1024 threads = (quarter, bucket). Unchanged.
// ---------------------------------------------------------------------------
__global__ void __launch_bounds__(1024)
hyper_sort_kernel()
{
    int bh    = blockIdx.x;
    int which = blockIdx.y;
    const unsigned int* hw =
        (const unsigned int*)((which ? g_kh : g_qh) + (size_t)bh * S_LEN);
    int* idx = (which ? g_kidx : g_qidx) + (size_t)bh * S_LEN;

    __shared__ unsigned int w[1024];
    __shared__ int scnt[4][256];
    __shared__ int scan[256];

    int t = threadIdx.x;                 // 0..1023
    int q = t >> 8;                      // quarter 0..3
    int k = t & 255;                     // bucket

    w[t] = hw[t];
    __syncthreads();

    unsigned k4 = k * 0x01010101u;
    int base = q * 256;
    int cnt = 0;
#pragma unroll 4
    for (int i = 0; i < 256; i++) cnt += __popc(__vcmpeq4(w[base + i], k4));
    cnt >>= 3;                           // 8 bits set per matching byte
    scnt[q][k] = cnt;
    __syncthreads();

    if (t < 256)
        scan[t] = scnt[0][t] + scnt[1][t] + scnt[2][t] + scnt[3][t];
    __syncthreads();
    for (int off = 1; off < 256; off <<= 1) {
        int v = (t < 256 && t >= off) ? scan[t - off] : 0;
        __syncthreads();
        if (t < 256) scan[t] += v;
        __syncthreads();
    }

    int pos = scan[k];
#pragma unroll
    for (int qq = 3; qq >= 0; qq--)
        if (qq >= q) pos -= scnt[qq][k];

    for (int i = base; i < base + 256; i++) {
        unsigned m = __vcmpeq4(w[i], k4);
        if (m) {
            int e = i * 4;
            if (m & 0x000000FFu) idx[pos++] = e;
            if (m & 0x0000FF00u) idx[pos++] = e + 1;
            if (m & 0x00FF0000u) idx[pos++] = e + 2;
            if (m & 0xFF000000u) idx[pos++] = e + 3;
        }
    }
}

// ---------------------------------------------------------------------------
// Kernel 3: fused attention. No-max softmax (|s|+bias bounded, fp32 safe):
// the two 128-key chunks fully decouple -> no online merge, no rescale.
// Q/output indices loaded straight to registers (no ssq smem dependency).
// Dynamic smem: 2 buffers x 2 comps x 128 rows x 128 B = 64 KB.
// ---------------------------------------------------------------------------
extern __shared__ __align__(16) unsigned char dyn_smem[];

__global__ void __launch_bounds__(256, 2)
hyper_attn_kernel(const float* __restrict__ qkv,
                  const int*   __restrict__ sampled,
                  float*       __restrict__ out)
{
    __shared__ int   ssrc_all[256];
    __shared__ float sbias_all[256];

    unsigned sbase = (unsigned)__cvta_generic_to_shared(dyn_smem);

    int g = blockIdx.x, h = blockIdx.y, b = blockIdx.z;
    int bh = b * NHEAD + h;
    int t  = threadIdx.x;
    int w  = t >> 5, l = t & 31;
    int lg = l >> 2, lq = l & 3;
    int m8 = l >> 3, r8 = l & 7;

    // per-thread Q/output row indices, straight to registers (no smem, no sync)
    int rA  = w * 16 + lg;
    int qiA = g_qidx[(size_t)bh * S_LEN + g * BLK + rA];
    int qiB = g_qidx[(size_t)bh * S_LEN + g * BLK + rA + 8];

    {   // both chunks' key lists + biases in one pass (128 keys each)
        int c = t >> 7, j = t & 127;
        int pos; float bias;
        if (c == 0) { pos = g * BLK + j; bias = 0.f; }
        else {
            pos  = sampled[bh * NSAMP + j];
            bias = ((pos >> 7) == g) ? -1e30f : 5.0f;   // log2(n/m) = 5
        }
        ssrc_all[t]  = g_kidx[(size_t)bh * S_LEN + pos];
        sbias_all[t] = bias;
    }
    __syncthreads();

// 2 comps x 128 rows x 8 groups = 2048 cp16 per chunk = 8 per thread
#define FILL_CHUNK(cc, bb)                                                    \
    {                                                                         \
        _Pragma("unroll")                                                     \
        for (int i = 0; i < 8; i++) {                                         \
            int lin = t + i * 256;                                            \
            int comp = lin >> 10, rowg = lin & 1023;                          \
            int rr = rowg >> 3, gg = rowg & 7;                                \
            int srow = ssrc_all[(cc) * 128 + rr];                             \
            const void* sp = g_pack + (size_t)comp * COMP_BYTES               \
                             + (((size_t)bh) * S_LEN + srow) * 128 + gg * 16; \
            unsigned dp = sbase + (bb) * BUFB + comp * 16384 + rr * 128       \
                          + ((gg ^ (rr & 7)) << 4);                           \
            cp16(dp, sp);                                                     \
        }                                                                     \
        cp_commit();                                                          \
    }
    FILL_CHUNK(0, 0);
    FILL_CHUNK(1, 1);

    // ---- Q fragments (single fp16, 16 rows per warp), scale folded ----
    const float qs = 0.125f * LOG2E;
    unsigned qf[4][4];
    {
        const float* qa = qkv + (size_t)(b * S_LEN + qiA) * 3072 + h * 64;
        const float* qb = qkv + (size_t)(b * S_LEN + qiB) * 3072 + h * 64;
#pragma unroll
        for (int ks = 0; ks < 4; ks++) {
            int c0 = ks * 16 + lq * 2;
            float2 xa0 = *(const float2*)(qa + c0);
            float2 xb0 = *(const float2*)(qb + c0);
            float2 xa1 = *(const float2*)(qa + c0 + 8);
            float2 xb1 = *(const float2*)(qb + c0 + 8);
            qf[ks][0] = pack_h2(xa0.x * qs, xa0.y * qs);
            qf[ks][1] = pack_h2(xb0.x * qs, xb0.y * qs);
            qf[ks][2] = pack_h2(xa1.x * qs, xa1.y * qs);
            qf[ks][3] = pack_h2(xb1.x * qs, xb1.y * qs);
        }
    }

    float o[8][4];
#pragma unroll
    for (int nt = 0; nt < 8; nt++)
#pragma unroll
        for (int q4 = 0; q4 < 4; q4++) o[nt][q4] = 0.f;
    float lrow[2] = {0.f, 0.f};

#pragma unroll
    for (int c = 0; c < 2; c++) {
        if (c == 0) cp_wait<1>();
        else        cp_wait<0>();
        __syncthreads();

        unsigned tb = sbase + c * BUFB;
        unsigned kb = tb, vb = tb + 16384;

        // ---- S = q*K + bias (16 n-tiles of 8 keys) ----
        float s[16][4];
#pragma unroll
        for (int nt = 0; nt < 16; nt++) {
            float2 bv = *(const float2*)(sbias_all + c * 128 + nt * 8 + lq * 2);
            s[nt][0] = bv.x; s[nt][1] = bv.y;
            s[nt][2] = bv.x; s[nt][3] = bv.y;
        }
#pragma unroll
        for (int ks = 0; ks < 4; ks++) {
#pragma unroll
            for (int ntp = 0; ntp < 8; ntp++) {
                int key  = (2 * ntp + (m8 >> 1)) * 8 + r8;
                int gidx = ks * 2 + (m8 & 1);
                unsigned off = (unsigned)(key * 128 + ((gidx ^ (key & 7)) << 4));
                unsigned kh0, kh1, kh2, kh3;
                ldsm_x4(kh0, kh1, kh2, kh3, kb + off);
                MMAH(s[2*ntp],   qf[ks][0],qf[ks][1],qf[ks][2],qf[ks][3], kh0,kh1);
                MMAH(s[2*ntp+1], qf[ks][0],qf[ks][1],qf[ks][2],qf[ks][3], kh2,kh3);
            }
        }

        // ---- no-max softmax (base-2): p = exp2(s), bounded so fp32-safe ----
#pragma unroll
        for (int hh = 0; hh < 2; hh++) {
            float ls = 0.f;
#pragma unroll
            for (int nt = 0; nt < 16; nt++) {
                float p0 = fast_exp2(s[nt][2*hh]);
                float p1 = fast_exp2(s[nt][2*hh + 1]);
                s[nt][2*hh] = p0; s[nt][2*hh+1] = p1;
                ls += p0 + p1;
            }
            ls += __shfl_xor_sync(0xFFFFFFFFu, ls, 1);
            ls += __shfl_xor_sync(0xFFFFFFFFu, ls, 2);
            lrow[hh] += ls;
        }

        // ---- O += p*V (8 k-steps of 16 keys) ----
#pragma unroll
        for (int kap = 0; kap < 8; kap++) {
            unsigned ph[4];
            ph[0] = pack_h2(s[2*kap][0],   s[2*kap][1]);
            ph[1] = pack_h2(s[2*kap][2],   s[2*kap][3]);
            ph[2] = pack_h2(s[2*kap+1][0], s[2*kap+1][1]);
            ph[3] = pack_h2(s[2*kap+1][2], s[2*kap+1][3]);
#pragma unroll
            for (int ntdp = 0; ntdp < 4; ntdp++) {
                int key  = kap * 16 + (m8 & 1) * 8 + r8;
                int gidx = ntdp * 2 + (m8 >> 1);
                unsigned off = (unsigned)(key * 128 + ((gidx ^ (key & 7)) << 4));
                unsigned vh0, vh1, vh2, vh3;
                ldsm_x4_t(vh0, vh1, vh2, vh3, vb + off);
                MMAH(o[2*ntdp],   ph[0],ph[1],ph[2],ph[3], vh0,vh1);
                MMAH(o[2*ntdp+1], ph[0],ph[1],ph[2],ph[3], vh2,vh3);
            }
        }
        // no end-of-chunk sync: each buffer is filled once and never reused
    }

    // ---- normalize + scatter back to original query order ----
#pragma unroll
    for (int hh = 0; hh < 2; hh++) {
        float inv = 1.0f / lrow[hh];
        int qsrc = hh ? qiB : qiA;
        float* op = out + ((size_t)(b * S_LEN + qsrc) * NHEAD + h) * 64;
#pragma unroll
        for (int nt = 0; nt < 8; nt++) {
            float2 v;
            v.x = o[nt][2*hh]     * inv;
            v.y = o[nt][2*hh + 1] * inv;
            *(float2*)(op + nt * 8 + lq * 2) = v;
        }
    }
}

// ---------------------------------------------------------------------------
extern "C" void kernel_launch(void* const* d_in, const int* in_sizes, int n_in,
                              void* d_out, int out_size)
{
    const float* qkv     = (const float*)d_in[0];   // [2,4096,3,16,64] f32
    const float* proj    = (const float*)d_in[1];   // [64,8] f32
    const int*   sampled = (const int*)d_in[2];     // [2,16,128] i32
    float*       out     = (float*)d_out;           // [2,4096,16,64] f32

    cudaFuncSetAttribute(hyper_attn_kernel,
                         cudaFuncAttributeMaxDynamicSharedMemorySize, 65536);

    hyper_hash_pack_kernel<<<NBATCH * S_LEN / 2, 256>>>(qkv, proj);
    hyper_sort_kernel<<<dim3(NBH, 2), 1024>>>();
    hyper_attn_kernel<<<dim3(NBLK, NHEAD, NBATCH), 256, 65536>>>(qkv, sampled, out);
}